// round 1
// baseline (speedup 1.0000x reference)
#include <cuda_runtime.h>

#define EPSN 1e-12f

constexpr int BATCH = 8;
constexpr int CDIM  = 192;
constexpr int HWSZ  = 16384;   // 128*128
constexpr int NHEAD = 4;
constexpr int CHD   = 48;
constexpr int SPLIT = 8;

// ---------------- scratch (device globals; no runtime allocation) -------------
__device__ float g_w3f[CDIM * CDIM * 9];                    // folded 3x3 weights
__device__ float g_cnf[(size_t)BATCH * CDIM * HWSZ];        // cn feature branch
__device__ float g_qkv1[(size_t)BATCH * 3 * CDIM * HWSZ];   // after 1x1
__device__ float g_qkv[(size_t)BATCH * 3 * CDIM * HWSZ];    // after depthwise
__device__ float g_coef[BATCH * CDIM * 3];                  // alpha,beta,gamma per row
__device__ float g_gpart[BATCH * NHEAD * SPLIT * CHD * CHD];
__device__ float g_attn[BATCH * NHEAD * CHD * CHD];
__device__ float g_av[(size_t)BATCH * CDIM * HWSZ];         // attn @ v

// ---------------- fold W3' [co][cj][t] = sum_ci W3[co][ci][t] * W1[ci][cj] ----
__global__ void foldw_kernel(const float* __restrict__ w3,
                             const float* __restrict__ w1,
                             float* __restrict__ wf) {
    int idx = blockIdx.x * 256 + threadIdx.x;
    if (idx >= CDIM * CDIM * 9) return;
    int t  = idx % 9;
    int cj = (idx / 9) % CDIM;
    int co = idx / (9 * CDIM);
    float s = 0.f;
    for (int ci = 0; ci < CDIM; ci++)
        s = fmaf(w3[(co * CDIM + ci) * 9 + t], w1[ci * CDIM + cj], s);
    wf[idx] = s;
}

// ---------------- GEMM conv: out[b][m][p] = sum_k w[m][k] * im2col(in)[k][p] --
// Tile: M=64, N=128, K=16.  256 threads, 4x8 micro-tile per thread.
template <int KTOT, bool IM2COL>
__global__ __launch_bounds__(256) void conv_gemm_kernel(
    const float* __restrict__ in, const float* __restrict__ w,
    float* __restrict__ out, int Cout) {
    constexpr int CIN = IM2COL ? KTOT / 9 : KTOT;
    __shared__ float As[64][20];    // [m][k], padded (bank-conflict free)
    __shared__ float Bs[16][128];   // [k][n]

    const int b  = blockIdx.z;
    const int m0 = blockIdx.y * 64;
    const int n0 = blockIdx.x * 128;
    const int tid = threadIdx.x;
    const int tx = tid & 15, ty = tid >> 4;
    const float* inB = in + (size_t)b * CIN * HWSZ;

    float acc[4][8];
#pragma unroll
    for (int i = 0; i < 4; i++)
#pragma unroll
        for (int j = 0; j < 8; j++) acc[i][j] = 0.f;

    const int lm  = tid >> 2;          // A-tile row (m)
    const int lk4 = (tid & 3) << 2;    // A-tile col (k), float4

    for (int k0 = 0; k0 < KTOT; k0 += 16) {
        // ---- load A tile (weights), coalesced along k
        *(float4*)&As[lm][lk4] =
            *(const float4*)(w + (size_t)(m0 + lm) * KTOT + (k0 + lk4));
        // ---- load B tile
        if (!IM2COL) {
            const int bk  = tid >> 4;
            const int bn8 = (tid & 15) << 3;
            const float* src = inB + (size_t)(k0 + bk) * HWSZ + n0 + bn8;
            *(float4*)&Bs[bk][bn8]     = *(const float4*)src;
            *(float4*)&Bs[bk][bn8 + 4] = *(const float4*)(src + 4);
        } else {
#pragma unroll
            for (int i = 0; i < 8; i++) {
                int e = tid + (i << 8);
                int k = e >> 7, n = e & 127;
                int kk = k0 + k;
                int ci = kk / 9;
                int t  = kk - ci * 9;
                int p  = n0 + n;
                int yy = (p >> 7) + t / 3 - 1;
                int xx = (p & 127) + (t % 3) - 1;
                float v = 0.f;
                if ((unsigned)yy < 128u && (unsigned)xx < 128u)
                    v = inB[ci * HWSZ + (yy << 7) + xx];
                Bs[k][n] = v;
            }
        }
        __syncthreads();
#pragma unroll
        for (int k = 0; k < 16; k++) {
            float ra[4];
#pragma unroll
            for (int i = 0; i < 4; i++) ra[i] = As[(ty << 2) + i][k];
            float4 b0 = *(const float4*)&Bs[k][tx << 3];
            float4 b1 = *(const float4*)&Bs[k][(tx << 3) + 4];
            float rb[8] = {b0.x, b0.y, b0.z, b0.w, b1.x, b1.y, b1.z, b1.w};
#pragma unroll
            for (int i = 0; i < 4; i++)
#pragma unroll
                for (int j = 0; j < 8; j++)
                    acc[i][j] = fmaf(ra[i], rb[j], acc[i][j]);
        }
        __syncthreads();
    }

#pragma unroll
    for (int i = 0; i < 4; i++) {
        float* dst = out + (size_t)b * Cout * HWSZ +
                     (size_t)(m0 + (ty << 2) + i) * HWSZ + n0 + (tx << 3);
        *(float4*)dst       = make_float4(acc[i][0], acc[i][1], acc[i][2], acc[i][3]);
        *(float4*)(dst + 4) = make_float4(acc[i][4], acc[i][5], acc[i][6], acc[i][7]);
    }
}

// ---------------- depthwise 3x3 (groups = 3C) --------------------------------
__global__ __launch_bounds__(256) void dwconv3_kernel(
    const float* __restrict__ in, const float* __restrict__ wdw,
    float* __restrict__ out) {
    int p = blockIdx.x * 256 + threadIdx.x;
    int c = blockIdx.y;
    int b = blockIdx.z;
    const float* src = in + ((size_t)b * (3 * CDIM) + c) * HWSZ;
    int y = p >> 7, x = p & 127;
    float acc = 0.f;
#pragma unroll
    for (int t = 0; t < 9; t++) {
        int yy = y + t / 3 - 1, xx = x + t % 3 - 1;
        if ((unsigned)yy < 128u && (unsigned)xx < 128u)
            acc = fmaf(wdw[c * 9 + t], src[(yy << 7) + xx], acc);
    }
    out[((size_t)b * (3 * CDIM) + c) * HWSZ + p] = acc;
}

// ---------------- per-row norms -> normalization coefficients ----------------
// l2n(l2n(q)+l2n(cn)) only needs: a=||q||, bb=||cn||, <q,cn>, ||k||.
__global__ __launch_bounds__(256) void stats_kernel(
    const float* __restrict__ qkv, const float* __restrict__ cnf,
    float* __restrict__ coef) {
    int row = blockIdx.x;                 // b*192 + c
    int b = row / CDIM, c = row % CDIM;
    const float* q  = qkv + ((size_t)b * (3 * CDIM) + c) * HWSZ;
    const float* kk = qkv + ((size_t)b * (3 * CDIM) + CDIM + c) * HWSZ;
    const float* cn = cnf + (size_t)row * HWSZ;
    float sq = 0.f, sk = 0.f, sc = 0.f, sqc = 0.f;
    for (int i = threadIdx.x; i < HWSZ; i += 256) {
        float qv = q[i], kv = kk[i], cv = cn[i];
        sq  = fmaf(qv, qv, sq);
        sk  = fmaf(kv, kv, sk);
        sc  = fmaf(cv, cv, sc);
        sqc = fmaf(qv, cv, sqc);
    }
#pragma unroll
    for (int o = 16; o; o >>= 1) {
        sq  += __shfl_xor_sync(~0u, sq, o);
        sk  += __shfl_xor_sync(~0u, sk, o);
        sc  += __shfl_xor_sync(~0u, sc, o);
        sqc += __shfl_xor_sync(~0u, sqc, o);
    }
    __shared__ float r4[4][8];
    int wid = threadIdx.x >> 5, lane = threadIdx.x & 31;
    if (lane == 0) { r4[0][wid] = sq; r4[1][wid] = sk; r4[2][wid] = sc; r4[3][wid] = sqc; }
    __syncthreads();
    if (threadIdx.x == 0) {
        float SQ = 0, SK = 0, SC = 0, SQC = 0;
        for (int i = 0; i < 8; i++) { SQ += r4[0][i]; SK += r4[1][i]; SC += r4[2][i]; SQC += r4[3][i]; }
        float a  = fmaxf(sqrtf(SQ), EPSN);
        float bb = fmaxf(sqrtf(SC), EPSN);
        float s2 = SQ / (a * a) + 2.f * SQC / (a * bb) + SC / (bb * bb);
        float s  = fmaxf(sqrtf(s2), EPSN);
        float kn = fmaxf(sqrtf(SK), EPSN);
        coef[row * 3 + 0] = 1.f / (a * s);    // alpha (scales q)
        coef[row * 3 + 1] = 1.f / (bb * s);   // beta  (scales cn)
        coef[row * 3 + 2] = 1.f / kn;         // gamma (scales k)
    }
}

// ---------------- gram G[c][d] = <alpha_c q_c + beta_c cn_c, gamma_d k_d> ----
__global__ __launch_bounds__(256) void gram_kernel(
    const float* __restrict__ qkv, const float* __restrict__ cnf,
    const float* __restrict__ coef, float* __restrict__ gpart) {
    __shared__ float SQ[48][33];
    __shared__ float SK[48][33];
    __shared__ float al[48], be[48], ga[48];
    int bh = blockIdx.x, sp = blockIdx.y;
    int b = bh >> 2, h = bh & 3;
    int tid = threadIdx.x, tx = tid & 15, ty = tid >> 4;
    if (tid < 48) {
        int row = b * CDIM + h * CHD + tid;
        al[tid] = coef[row * 3 + 0];
        be[tid] = coef[row * 3 + 1];
        ga[tid] = coef[row * 3 + 2];
    }
    __syncthreads();
    const float* qb = qkv + ((size_t)b * (3 * CDIM) + h * CHD) * HWSZ;
    const float* kb = qkv + ((size_t)b * (3 * CDIM) + CDIM + h * CHD) * HWSZ;
    const float* cb = cnf + ((size_t)b * CDIM + h * CHD) * HWSZ;
    float acc[3][3] = {};
    int send = sp * 2048 + 2048;
    for (int s0 = sp * 2048; s0 < send; s0 += 32) {
        for (int e = tid; e < 1536; e += 256) {
            int r = e >> 5, s = e & 31;
            int off = r * HWSZ + s0 + s;
            SQ[r][s] = al[r] * qb[off] + be[r] * cb[off];
            SK[r][s] = ga[r] * kb[off];
        }
        __syncthreads();
#pragma unroll 4
        for (int s = 0; s < 32; s++) {
            float qa[3], kv[3];
#pragma unroll
            for (int i = 0; i < 3; i++) qa[i] = SQ[tx + 16 * i][s];
#pragma unroll
            for (int j = 0; j < 3; j++) kv[j] = SK[ty + 16 * j][s];
#pragma unroll
            for (int i = 0; i < 3; i++)
#pragma unroll
                for (int j = 0; j < 3; j++)
                    acc[i][j] = fmaf(qa[i], kv[j], acc[i][j]);
        }
        __syncthreads();
    }
#pragma unroll
    for (int i = 0; i < 3; i++)
#pragma unroll
        for (int j = 0; j < 3; j++)
            gpart[((bh * SPLIT + sp) * CHD + tx + 16 * i) * CHD + ty + 16 * j] = acc[i][j];
}

// ---------------- reduce partials, * temperature, softmax over d -------------
__global__ __launch_bounds__(256) void softmax_kernel(
    const float* __restrict__ gpart, const float* __restrict__ temp,
    float* __restrict__ attn) {
    __shared__ float S[48][49];
    int bh = blockIdx.x;
    float T = temp[bh & 3];
    int tid = threadIdx.x;
    for (int e = tid; e < CHD * CHD; e += 256) {
        int c = e / CHD, d = e - c * CHD;
        float g = 0.f;
#pragma unroll
        for (int sp = 0; sp < SPLIT; sp++)
            g += gpart[((bh * SPLIT + sp) * CHD + c) * CHD + d];
        S[c][d] = g * T;
    }
    __syncthreads();
    int wid = tid >> 5, lane = tid & 31;
    for (int r = wid; r < 48; r += 8) {
        float v1 = S[r][lane];
        float v2 = (lane < 16) ? S[r][32 + lane] : -1e30f;
        float m = fmaxf(v1, v2);
#pragma unroll
        for (int o = 16; o; o >>= 1) m = fmaxf(m, __shfl_xor_sync(~0u, m, o));
        float e1 = expf(v1 - m);
        float e2 = (lane < 16) ? expf(v2 - m) : 0.f;
        float s = e1 + e2;
#pragma unroll
        for (int o = 16; o; o >>= 1) s += __shfl_xor_sync(~0u, s, o);
        float inv = 1.f / s;
        attn[bh * (CHD * CHD) + r * CHD + lane] = e1 * inv;
        if (lane < 16) attn[bh * (CHD * CHD) + r * CHD + 32 + lane] = e2 * inv;
    }
}

// ---------------- out[c][p] = sum_d attn[c][d] * v[d][p] ---------------------
__global__ __launch_bounds__(256) void apply_kernel(
    const float* __restrict__ qkv, const float* __restrict__ attn,
    float* __restrict__ out) {
    __shared__ float A[48][48];
    int b = blockIdx.z, h = blockIdx.y;
    int tid = threadIdx.x;
    for (int e = tid; e < CHD * CHD; e += 256)
        A[e / CHD][e % CHD] = attn[(b * NHEAD + h) * (CHD * CHD) + e];
    __syncthreads();
    int p = blockIdx.x * 512 + tid;
    const float* vb = qkv + ((size_t)b * (3 * CDIM) + 2 * CDIM + h * CHD) * HWSZ;
    float a0[48], a1[48];
#pragma unroll
    for (int c = 0; c < 48; c++) { a0[c] = 0.f; a1[c] = 0.f; }
#pragma unroll 2
    for (int d = 0; d < 48; d++) {
        float v0 = vb[d * HWSZ + p];
        float v1 = vb[d * HWSZ + p + 256];
#pragma unroll
        for (int c = 0; c < 48; c++) {
            float a = A[c][d];
            a0[c] = fmaf(a, v0, a0[c]);
            a1[c] = fmaf(a, v1, a1[c]);
        }
    }
    float* ob = out + ((size_t)b * CDIM + h * CHD) * HWSZ;
#pragma unroll
    for (int c = 0; c < 48; c++) {
        ob[c * HWSZ + p]       = a0[c];
        ob[c * HWSZ + p + 256] = a1[c];
    }
}

// ---------------- launch -----------------------------------------------------
extern "C" void kernel_launch(void* const* d_in, const int* in_sizes, int n_in,
                              void* d_out, int out_size) {
    const float* x     = (const float*)d_in[0];
    const float* cn    = (const float*)d_in[1];
    const float* w1    = (const float*)d_in[2];
    const float* w3    = (const float*)d_in[3];
    const float* qkvw  = (const float*)d_in[4];
    const float* dww   = (const float*)d_in[5];
    const float* projw = (const float*)d_in[6];
    const float* temp  = (const float*)d_in[7];

    float *w3f, *cnf, *qkv1, *qkv2, *coef, *gpart, *attn, *av;
    cudaGetSymbolAddress((void**)&w3f,   g_w3f);
    cudaGetSymbolAddress((void**)&cnf,   g_cnf);
    cudaGetSymbolAddress((void**)&qkv1,  g_qkv1);
    cudaGetSymbolAddress((void**)&qkv2,  g_qkv);
    cudaGetSymbolAddress((void**)&coef,  g_coef);
    cudaGetSymbolAddress((void**)&gpart, g_gpart);
    cudaGetSymbolAddress((void**)&attn,  g_attn);
    cudaGetSymbolAddress((void**)&av,    g_av);

    // 1. fold cn 1x1 into the 3x3 weights (saves a 9.7 GF conv + 200MB traffic)
    foldw_kernel<<<(CDIM * CDIM * 9 + 255) / 256, 256>>>(w3, w1, w3f);
    // 2. cn feature branch: single 3x3 conv with folded weights (implicit im2col GEMM)
    conv_gemm_kernel<CDIM * 9, true><<<dim3(128, 3, BATCH), 256>>>(cn, w3f, cnf, CDIM);
    // 3. qkv 1x1 (192 -> 576)
    conv_gemm_kernel<CDIM, false><<<dim3(128, 9, BATCH), 256>>>(x, qkvw, qkv1, 3 * CDIM);
    // 4. depthwise 3x3
    dwconv3_kernel<<<dim3(64, 3 * CDIM, BATCH), 256>>>(qkv1, dww, qkv2);
    // 5. per-row normalization coefficients
    stats_kernel<<<BATCH * CDIM, 256>>>(qkv2, cnf, coef);
    // 6. channel gram matrices (split over spatial dim for occupancy)
    gram_kernel<<<dim3(BATCH * NHEAD, SPLIT), 256>>>(qkv2, cnf, coef, gpart);
    // 7. reduce + temperature + softmax
    softmax_kernel<<<BATCH * NHEAD, 256>>>(gpart, temp, attn);
    // 8. attn @ v
    apply_kernel<<<dim3(32, NHEAD, BATCH), 256>>>(qkv2, attn, av);
    // 9. projection 1x1 -> output
    conv_gemm_kernel<CDIM, false><<<dim3(128, 3, BATCH), 256>>>(av, projw, (float*)d_out, CDIM);
}

// round 3
// speedup vs baseline: 2.8638x; 2.8638x over previous
#include <cuda_runtime.h>
#include <cuda_bf16.h>
#include <cstdint>

#define EPSN 1e-12f

constexpr int BATCH = 8;
constexpr int CDIM  = 192;
constexpr int HWSZ  = 16384;   // 128*128
constexpr int NHEAD = 4;
constexpr int CHD   = 48;
constexpr int SPLIT = 8;

// ---------------------------------------------------------------------------
// helpers
// ---------------------------------------------------------------------------
__device__ __forceinline__ uint32_t s2u(const void* p) {
    uint32_t a;
    asm("{ .reg .u64 t; cvta.to.shared.u64 t, %1; cvt.u32.u64 %0, t; }" : "=r"(a) : "l"(p));
    return a;
}
#define SWZ(x) ((x) ^ (((x) >> 3) & 0x70))

__device__ __forceinline__ void ldsm4(uint32_t* r, uint32_t addr) {
    asm volatile("ldmatrix.sync.aligned.m8n8.x4.shared.b16 {%0,%1,%2,%3}, [%4];"
        : "=r"(r[0]), "=r"(r[1]), "=r"(r[2]), "=r"(r[3]) : "r"(addr));
}
__device__ __forceinline__ void ldsm4t(uint32_t* r, uint32_t addr) {
    asm volatile("ldmatrix.sync.aligned.m8n8.x4.trans.shared.b16 {%0,%1,%2,%3}, [%4];"
        : "=r"(r[0]), "=r"(r[1]), "=r"(r[2]), "=r"(r[3]) : "r"(addr));
}
__device__ __forceinline__ void mma16816(float* d, const uint32_t* a, const uint32_t* b) {
    asm volatile("mma.sync.aligned.m16n8k16.row.col.f32.bf16.bf16.f32 "
        "{%0,%1,%2,%3}, {%4,%5,%6,%7}, {%8,%9}, {%0,%1,%2,%3};"
        : "+f"(d[0]), "+f"(d[1]), "+f"(d[2]), "+f"(d[3])
        : "r"(a[0]), "r"(a[1]), "r"(a[2]), "r"(a[3]), "r"(b[0]), "r"(b[1]));
}

__device__ __forceinline__ void splitbf(float v, __nv_bfloat16& h, __nv_bfloat16& l) {
    h = __float2bfloat16(v);
    l = __float2bfloat16(v - __bfloat162float(h));
}
__device__ __forceinline__ uint32_t pack2(__nv_bfloat16 a, __nv_bfloat16 b) {
    return (uint32_t)__bfloat16_as_ushort(a) | ((uint32_t)__bfloat16_as_ushort(b) << 16);
}

// ---------------------------------------------------------------------------
// scratch buffers
// ---------------------------------------------------------------------------
__device__ __nv_bfloat16 g_wc_h[256 * 1728], g_wc_l[256 * 1728];   // folded 3x3 (t-major)
__device__ __nv_bfloat16 g_wq_h[640 * 192],  g_wq_l[640 * 192];    // qkv 1x1 (padded)
__device__ __nv_bfloat16 g_wp_h[256 * 192],  g_wp_l[256 * 192];    // proj 1x1 (padded)
__device__ __nv_bfloat16 g_xh[(size_t)BATCH * CDIM * HWSZ];        // act split hi
__device__ __nv_bfloat16 g_xl[(size_t)BATCH * CDIM * HWSZ];        // act split lo
__device__ float g_cnf[(size_t)BATCH * CDIM * HWSZ];
__device__ float g_qkv1[(size_t)BATCH * 3 * CDIM * HWSZ];
__device__ float g_qkv[(size_t)BATCH * 3 * CDIM * HWSZ];
__device__ float g_coef[BATCH * CDIM * 3];
__device__ float g_gpart[BATCH * NHEAD * SPLIT * CHD * CHD];
__device__ float g_attn[BATCH * NHEAD * CHD * CHD];
__device__ float g_av[(size_t)BATCH * CDIM * HWSZ];

// ---------------------------------------------------------------------------
// weight prep: fold 1x1 into 3x3 (k reordered to t*192+cj), bf16 hi/lo split
// ---------------------------------------------------------------------------
__global__ void foldw_kernel(const float* __restrict__ w3, const float* __restrict__ w1,
                             __nv_bfloat16* __restrict__ wh, __nv_bfloat16* __restrict__ wl) {
    int idx = blockIdx.x * 256 + threadIdx.x;          // 256*1728
    int co = idx / 1728, r = idx % 1728;
    int t = r / 192, cj = r % 192;
    float s = 0.f;
    if (co < CDIM)
        for (int ci = 0; ci < CDIM; ci++)
            s = fmaf(w3[(co * CDIM + ci) * 9 + t], w1[ci * CDIM + cj], s);
    __nv_bfloat16 h, l; splitbf(s, h, l);
    wh[idx] = h; wl[idx] = l;
}

__global__ void splitw_kernel(const float* __restrict__ w, __nv_bfloat16* __restrict__ wh,
                              __nv_bfloat16* __restrict__ wl, int validRows) {
    int idx = blockIdx.x * 256 + threadIdx.x;
    int row = idx / CDIM;
    float v = (row < validRows) ? w[(size_t)row * CDIM + (idx % CDIM)] : 0.f;
    __nv_bfloat16 h, l; splitbf(v, h, l);
    wh[idx] = h; wl[idx] = l;
}

// elementwise fp32 -> bf16 hi/lo (same [C][HW] layout, no transpose)
__global__ __launch_bounds__(256) void asplit_kernel(
    const float* __restrict__ in, __nv_bfloat16* __restrict__ oh,
    __nv_bfloat16* __restrict__ ol, int n4) {
    int i = blockIdx.x * 256 + threadIdx.x;
    if (i >= n4) return;
    float4 v = ((const float4*)in)[i];
    __nv_bfloat16 h0, l0, h1, l1, h2, l2, h3, l3;
    splitbf(v.x, h0, l0); splitbf(v.y, h1, l1);
    splitbf(v.z, h2, l2); splitbf(v.w, h3, l3);
    ((uint2*)oh)[i] = make_uint2(pack2(h0, h1), pack2(h2, h3));
    ((uint2*)ol)[i] = make_uint2(pack2(l0, l1), pack2(l2, l3));
}

// ---------------------------------------------------------------------------
// HMMA GEMM:  out[b][m][p] = sum_k W[m][k] * B[k][p]
//   CTA tile 128m x 128n, K-chunk 64, 3-term bf16 split, fp32 acc.
//   TAPS=9: implicit im2col (k = t*192+ci), chunk never crosses a tap.
//   smem: A hi/lo [128][64] (0,16K), B hi/lo [64][128] as 2x64-col halves (32K,48K)
// ---------------------------------------------------------------------------
template <int KTOT, int TAPS>
__global__ __launch_bounds__(256) void mm_kernel(
    const __nv_bfloat16* __restrict__ xh, const __nv_bfloat16* __restrict__ xl,
    const __nv_bfloat16* __restrict__ wh, const __nv_bfloat16* __restrict__ wl,
    float* __restrict__ out, int Cout) {
    extern __shared__ char sraw[];
    char* sal = (char*)((((uintptr_t)sraw) + 127) & ~(uintptr_t)127);
    const uint32_t sb = s2u(sal);
    const int tid = threadIdx.x, lane = tid & 31, wid = tid >> 5;
    const int n0 = blockIdx.x * 128, m0 = blockIdx.y * 128, b = blockIdx.z;
    const int wm = wid >> 1, wn = wid & 1;
    const int y = n0 >> 7;
    const int lr = lane & 15, lc = lane >> 4;

    float acc[2][8][4];
#pragma unroll
    for (int i = 0; i < 2; i++)
#pragma unroll
        for (int j = 0; j < 8; j++)
#pragma unroll
            for (int q = 0; q < 4; q++) acc[i][j][q] = 0.f;

    constexpr int NCH = KTOT / 64;
    for (int cc = 0; cc < NCH; cc++) {
        const int k0 = cc * 64;
        const int t = (TAPS == 9) ? (k0 / 192) : 0;
        const int ci0 = k0 - t * 192;
        const int dy = t / 3 - 1, dx = t % 3 - 1;
        const int yy = y + dy;
        const bool rowok = (TAPS == 1) || ((unsigned)yy < 128u);
        const int rowstart = (TAPS == 1) ? 0 : (yy << 7);

        // ---- A tiles (weights; rows padded, always valid)
#pragma unroll
        for (int i = 0; i < 8; i++) {
            int e = tid + (i << 8);
            int ck = e & 7, r = (e >> 3) & 127, dt = e >> 10;
            const __nv_bfloat16* src = (dt ? wl : wh) + (size_t)(m0 + r) * KTOT + k0 + ck * 8;
            *(uint4*)(sal + dt * 16384 + SWZ(r * 128 + ck * 16)) = *(const uint4*)src;
        }
        // ---- B tiles (activations; implicit im2col with in-register x-shift)
#pragma unroll
        for (int i = 0; i < 8; i++) {
            int e = tid + (i << 8);
            int nc = e & 15, k = (e >> 4) & 63, dt = e >> 10;
            int n = nc * 8;
            uint4 v = make_uint4(0, 0, 0, 0);
            if (rowok) {
                const __nv_bfloat16* base =
                    (dt ? xl : xh) + ((size_t)b * CDIM + ci0 + k) * HWSZ;
                if (TAPS == 1) {
                    v = *(const uint4*)(base + n0 + n);
                } else {
                    const __nv_bfloat16* p = base + rowstart + n;
                    if (dx == 0) {
                        v = *(const uint4*)p;
                    } else {
                        uint4 a = *(const uint4*)p;
                        uint32_t* s = (uint32_t*)&a;
                        uint32_t ex = 0;
                        if (dx > 0) {
                            if (n + 8 < 128) ex = *(const unsigned short*)(p + 8);
                            v.x = __funnelshift_r(s[0], s[1], 16);
                            v.y = __funnelshift_r(s[1], s[2], 16);
                            v.z = __funnelshift_r(s[2], s[3], 16);
                            v.w = (s[3] >> 16) | (ex << 16);
                        } else {
                            if (n > 0) ex = *(const unsigned short*)(p - 1);
                            v.x = (s[0] << 16) | ex;
                            v.y = (s[1] << 16) | (s[0] >> 16);
                            v.z = (s[2] << 16) | (s[1] >> 16);
                            v.w = (s[3] << 16) | (s[2] >> 16);
                        }
                    }
                }
            }
            int half = nc >> 3;
            *(uint4*)(sal + 32768 + dt * 16384 + half * 8192 + SWZ(k * 128 + (n & 63) * 2)) = v;
        }
        __syncthreads();

        // ---- 4 k16-steps of HMMA
#pragma unroll
        for (int ks = 0; ks < 4; ks++) {
            uint32_t ah[2][4], alo[2][4];
#pragma unroll
            for (int mf = 0; mf < 2; mf++) {
                uint32_t ao = SWZ((wm * 32 + mf * 16 + lr) * 128 + ks * 32 + lc * 16);
                ldsm4(ah[mf],  sb + ao);
                ldsm4(alo[mf], sb + 16384 + ao);
            }
#pragma unroll
            for (int g = 0; g < 4; g++) {
                uint32_t bh[4], bl[4];
                uint32_t bo = 32768 + wn * 8192 + SWZ((ks * 16 + lr) * 128 + g * 32 + lc * 16);
                ldsm4t(bh, sb + bo);
                ldsm4t(bl, sb + 16384 + bo);
#pragma unroll
                for (int mf = 0; mf < 2; mf++) {
                    mma16816(acc[mf][2 * g],     ah[mf],  bh);
                    mma16816(acc[mf][2 * g],     ah[mf],  bl);
                    mma16816(acc[mf][2 * g],     alo[mf], bh);
                    mma16816(acc[mf][2 * g + 1], ah[mf],  bh + 2);
                    mma16816(acc[mf][2 * g + 1], ah[mf],  bl + 2);
                    mma16816(acc[mf][2 * g + 1], alo[mf], bh + 2);
                }
            }
        }
        __syncthreads();
    }

    // ---- epilogue: direct fp32 stores (float2 per fragment row)
#pragma unroll
    for (int mf = 0; mf < 2; mf++) {
        int mb = m0 + wm * 32 + mf * 16 + (lane >> 2);
#pragma unroll
        for (int nb = 0; nb < 8; nb++) {
            int nn = n0 + wn * 64 + nb * 8 + (lane & 3) * 2;
            if (mb < Cout)
                *(float2*)(out + ((size_t)b * Cout + mb) * HWSZ + nn) =
                    make_float2(acc[mf][nb][0], acc[mf][nb][1]);
            if (mb + 8 < Cout)
                *(float2*)(out + ((size_t)b * Cout + mb + 8) * HWSZ + nn) =
                    make_float2(acc[mf][nb][2], acc[mf][nb][3]);
        }
    }
}

// ---------------------------------------------------------------------------
// depthwise 3x3, float4 vectorized
// ---------------------------------------------------------------------------
__global__ __launch_bounds__(256) void dwconv3_kernel(
    const float* __restrict__ in, const float* __restrict__ wdw,
    float* __restrict__ out) {
    int c = blockIdx.y, b = blockIdx.z;
    int p4 = (blockIdx.x * 256 + threadIdx.x) * 4;
    int y = p4 >> 7, x = p4 & 127;
    const float* src = in + ((size_t)b * (3 * CDIM) + c) * HWSZ;
    float w[9];
#pragma unroll
    for (int i = 0; i < 9; i++) w[i] = wdw[c * 9 + i];
    float4 a = make_float4(0.f, 0.f, 0.f, 0.f);
#pragma unroll
    for (int r = -1; r <= 1; r++) {
        int yy = y + r;
        if ((unsigned)yy >= 128u) continue;
        const float* rp = src + (yy << 7);
        float4 m = *(const float4*)(rp + x);
        float L = (x > 0) ? rp[x - 1] : 0.f;
        float R = (x + 4 < 128) ? rp[x + 4] : 0.f;
        int wb = (r + 1) * 3;
        a.x = fmaf(w[wb], L,   fmaf(w[wb + 1], m.x, fmaf(w[wb + 2], m.y, a.x)));
        a.y = fmaf(w[wb], m.x, fmaf(w[wb + 1], m.y, fmaf(w[wb + 2], m.z, a.y)));
        a.z = fmaf(w[wb], m.y, fmaf(w[wb + 1], m.z, fmaf(w[wb + 2], m.w, a.z)));
        a.w = fmaf(w[wb], m.z, fmaf(w[wb + 1], m.w, fmaf(w[wb + 2], R,   a.w)));
    }
    *(float4*)(out + ((size_t)b * (3 * CDIM) + c) * HWSZ + p4) = a;
}

// ---------------------------------------------------------------------------
// per-row norms -> normalization coefficients
// ---------------------------------------------------------------------------
__global__ __launch_bounds__(256) void stats_kernel(
    const float* __restrict__ qkv, const float* __restrict__ cnf,
    float* __restrict__ coef) {
    int rowi = blockIdx.x;
    int b = rowi / CDIM, c = rowi % CDIM;
    const float* q  = qkv + ((size_t)b * (3 * CDIM) + c) * HWSZ;
    const float* kk = qkv + ((size_t)b * (3 * CDIM) + CDIM + c) * HWSZ;
    const float* cn = cnf + (size_t)rowi * HWSZ;
    float sq = 0.f, sk = 0.f, sc = 0.f, sqc = 0.f;
    for (int i = threadIdx.x; i < HWSZ; i += 256) {
        float qv = q[i], kv = kk[i], cv = cn[i];
        sq = fmaf(qv, qv, sq); sk = fmaf(kv, kv, sk);
        sc = fmaf(cv, cv, sc); sqc = fmaf(qv, cv, sqc);
    }
#pragma unroll
    for (int o = 16; o; o >>= 1) {
        sq += __shfl_xor_sync(~0u, sq, o); sk += __shfl_xor_sync(~0u, sk, o);
        sc += __shfl_xor_sync(~0u, sc, o); sqc += __shfl_xor_sync(~0u, sqc, o);
    }
    __shared__ float r4[4][8];
    int wid = threadIdx.x >> 5, lane = threadIdx.x & 31;
    if (lane == 0) { r4[0][wid] = sq; r4[1][wid] = sk; r4[2][wid] = sc; r4[3][wid] = sqc; }
    __syncthreads();
    if (threadIdx.x == 0) {
        float SQ = 0, SK = 0, SC = 0, SQC = 0;
        for (int i = 0; i < 8; i++) { SQ += r4[0][i]; SK += r4[1][i]; SC += r4[2][i]; SQC += r4[3][i]; }
        float a  = fmaxf(sqrtf(SQ), EPSN);
        float bb = fmaxf(sqrtf(SC), EPSN);
        float s2 = SQ / (a * a) + 2.f * SQC / (a * bb) + SC / (bb * bb);
        float s  = fmaxf(sqrtf(s2), EPSN);
        float kn = fmaxf(sqrtf(SK), EPSN);
        coef[rowi * 3 + 0] = 1.f / (a * s);
        coef[rowi * 3 + 1] = 1.f / (bb * s);
        coef[rowi * 3 + 2] = 1.f / kn;
    }
}

// ---------------------------------------------------------------------------
// gram / softmax / apply
// ---------------------------------------------------------------------------
__global__ __launch_bounds__(256) void gram_kernel(
    const float* __restrict__ qkv, const float* __restrict__ cnf,
    const float* __restrict__ coef, float* __restrict__ gpart) {
    __shared__ float SQ[48][33];
    __shared__ float SK[48][33];
    __shared__ float al[48], be[48], ga[48];
    int bh = blockIdx.x, sp = blockIdx.y;
    int b = bh >> 2, h = bh & 3;
    int tid = threadIdx.x, tx = tid & 15, ty = tid >> 4;
    if (tid < 48) {
        int rw = b * CDIM + h * CHD + tid;
        al[tid] = coef[rw * 3 + 0]; be[tid] = coef[rw * 3 + 1]; ga[tid] = coef[rw * 3 + 2];
    }
    __syncthreads();
    const float* qb = qkv + ((size_t)b * (3 * CDIM) + h * CHD) * HWSZ;
    const float* kb = qkv + ((size_t)b * (3 * CDIM) + CDIM + h * CHD) * HWSZ;
    const float* cb = cnf + ((size_t)b * CDIM + h * CHD) * HWSZ;
    float acc[3][3] = {};
    int send = sp * 2048 + 2048;
    for (int s0 = sp * 2048; s0 < send; s0 += 32) {
        for (int e = tid; e < 1536; e += 256) {
            int r = e >> 5, s = e & 31;
            int off = r * HWSZ + s0 + s;
            SQ[r][s] = al[r] * qb[off] + be[r] * cb[off];
            SK[r][s] = ga[r] * kb[off];
        }
        __syncthreads();
#pragma unroll 4
        for (int s = 0; s < 32; s++) {
            float qa[3], kv[3];
#pragma unroll
            for (int i = 0; i < 3; i++) qa[i] = SQ[tx + 16 * i][s];
#pragma unroll
            for (int j = 0; j < 3; j++) kv[j] = SK[ty + 16 * j][s];
#pragma unroll
            for (int i = 0; i < 3; i++)
#pragma unroll
                for (int j = 0; j < 3; j++)
                    acc[i][j] = fmaf(qa[i], kv[j], acc[i][j]);
        }
        __syncthreads();
    }
#pragma unroll
    for (int i = 0; i < 3; i++)
#pragma unroll
        for (int j = 0; j < 3; j++)
            gpart[((bh * SPLIT + sp) * CHD + tx + 16 * i) * CHD + ty + 16 * j] = acc[i][j];
}

__global__ __launch_bounds__(256) void softmax_kernel(
    const float* __restrict__ gpart, const float* __restrict__ temp,
    float* __restrict__ attn) {
    __shared__ float S[48][49];
    int bh = blockIdx.x;
    float T = temp[bh & 3];
    int tid = threadIdx.x;
    for (int e = tid; e < CHD * CHD; e += 256) {
        int c = e / CHD, d = e - c * CHD;
        float g = 0.f;
#pragma unroll
        for (int sp = 0; sp < SPLIT; sp++)
            g += gpart[((bh * SPLIT + sp) * CHD + c) * CHD + d];
        S[c][d] = g * T;
    }
    __syncthreads();
    int wid = tid >> 5, lane = tid & 31;
    for (int r = wid; r < 48; r += 8) {
        float v1 = S[r][lane];
        float v2 = (lane < 16) ? S[r][32 + lane] : -1e30f;
        float m = fmaxf(v1, v2);
#pragma unroll
        for (int o = 16; o; o >>= 1) m = fmaxf(m, __shfl_xor_sync(~0u, m, o));
        float e1 = expf(v1 - m);
        float e2 = (lane < 16) ? expf(v2 - m) : 0.f;
        float s = e1 + e2;
#pragma unroll
        for (int o = 16; o; o >>= 1) s += __shfl_xor_sync(~0u, s, o);
        float inv = 1.f / s;
        attn[bh * (CHD * CHD) + r * CHD + lane] = e1 * inv;
        if (lane < 16) attn[bh * (CHD * CHD) + r * CHD + 32 + lane] = e2 * inv;
    }
}

__global__ __launch_bounds__(256) void apply_kernel(
    const float* __restrict__ qkv, const float* __restrict__ attn,
    float* __restrict__ out) {
    __shared__ float A[48][48];
    int b = blockIdx.z, h = blockIdx.y;
    int tid = threadIdx.x;
    for (int e = tid; e < CHD * CHD; e += 256)
        A[e / CHD][e % CHD] = attn[(b * NHEAD + h) * (CHD * CHD) + e];
    __syncthreads();
    int p = blockIdx.x * 512 + tid;
    const float* vb = qkv + ((size_t)b * (3 * CDIM) + 2 * CDIM + h * CHD) * HWSZ;
    float a0[48], a1[48];
#pragma unroll
    for (int c = 0; c < 48; c++) { a0[c] = 0.f; a1[c] = 0.f; }
#pragma unroll 2
    for (int d = 0; d < 48; d++) {
        float v0 = vb[d * HWSZ + p];
        float v1 = vb[d * HWSZ + p + 256];
#pragma unroll
        for (int c = 0; c < 48; c++) {
            float a = A[c][d];
            a0[c] = fmaf(a, v0, a0[c]);
            a1[c] = fmaf(a, v1, a1[c]);
        }
    }
    float* ob = out + ((size_t)b * CDIM + h * CHD) * HWSZ;
#pragma unroll
    for (int c = 0; c < 48; c++) {
        ob[c * HWSZ + p]       = a0[c];
        ob[c * HWSZ + p + 256] = a1[c];
    }
}

// ---------------------------------------------------------------------------
// launch
// ---------------------------------------------------------------------------
constexpr int MM_SMEM = 65536 + 128;

extern "C" void kernel_launch(void* const* d_in, const int* in_sizes, int n_in,
                              void* d_out, int out_size) {
    const float* x     = (const float*)d_in[0];
    const float* cn    = (const float*)d_in[1];
    const float* w1    = (const float*)d_in[2];
    const float* w3    = (const float*)d_in[3];
    const float* qkvw  = (const float*)d_in[4];
    const float* dww   = (const float*)d_in[5];
    const float* projw = (const float*)d_in[6];
    const float* temp  = (const float*)d_in[7];

    __nv_bfloat16 *wch, *wcl, *wqh, *wql, *wph, *wpl, *xh, *xl;
    float *cnf, *qkv1, *qkv2, *coef, *gpart, *attn, *av;
    cudaGetSymbolAddress((void**)&wch, g_wc_h);  cudaGetSymbolAddress((void**)&wcl, g_wc_l);
    cudaGetSymbolAddress((void**)&wqh, g_wq_h);  cudaGetSymbolAddress((void**)&wql, g_wq_l);
    cudaGetSymbolAddress((void**)&wph, g_wp_h);  cudaGetSymbolAddress((void**)&wpl, g_wp_l);
    cudaGetSymbolAddress((void**)&xh,  g_xh);    cudaGetSymbolAddress((void**)&xl,  g_xl);
    cudaGetSymbolAddress((void**)&cnf,  g_cnf);
    cudaGetSymbolAddress((void**)&qkv1, g_qkv1);
    cudaGetSymbolAddress((void**)&qkv2, g_qkv);
    cudaGetSymbolAddress((void**)&coef, g_coef);
    cudaGetSymbolAddress((void**)&gpart, g_gpart);
    cudaGetSymbolAddress((void**)&attn, g_attn);
    cudaGetSymbolAddress((void**)&av,   g_av);

    cudaFuncSetAttribute(mm_kernel<1728, 9>, cudaFuncAttributeMaxDynamicSharedMemorySize, MM_SMEM);
    cudaFuncSetAttribute(mm_kernel<192, 1>,  cudaFuncAttributeMaxDynamicSharedMemorySize, MM_SMEM);

    const int NACT4 = BATCH * CDIM * HWSZ / 4;

    // weight prep
    foldw_kernel<<<256 * 1728 / 256, 256>>>(w3, w1, wch, wcl);
    splitw_kernel<<<640 * 192 / 256, 256>>>(qkvw, wqh, wql, 3 * CDIM);
    splitw_kernel<<<256 * 192 / 256, 256>>>(projw, wph, wpl, CDIM);

    // cn branch: split, folded 3x3 conv (implicit im2col, HMMA)
    asplit_kernel<<<(NACT4 + 255) / 256, 256>>>(cn, xh, xl, NACT4);
    mm_kernel<1728, 9><<<dim3(128, 2, BATCH), 256, MM_SMEM>>>(xh, xl, wch, wcl, cnf, CDIM);

    // qkv 1x1 (HMMA)
    asplit_kernel<<<(NACT4 + 255) / 256, 256>>>(x, xh, xl, NACT4);
    mm_kernel<192, 1><<<dim3(128, 5, BATCH), 256, MM_SMEM>>>(xh, xl, wqh, wql, qkv1, 3 * CDIM);

    // depthwise 3x3
    dwconv3_kernel<<<dim3(HWSZ / 1024, 3 * CDIM, BATCH), 256>>>(qkv1, dww, qkv2);

    // attention chain
    stats_kernel<<<BATCH * CDIM, 256>>>(qkv2, cnf, coef);
    gram_kernel<<<dim3(BATCH * NHEAD, SPLIT), 256>>>(qkv2, cnf, coef, gpart);
    softmax_kernel<<<BATCH * NHEAD, 256>>>(gpart, temp, attn);
    apply_kernel<<<dim3(32, NHEAD, BATCH), 256>>>(qkv2, attn, av);

    // projection 1x1 (HMMA)
    asplit_kernel<<<(NACT4 + 255) / 256, 256>>>(av, xh, xl, NACT4);
    mm_kernel<192, 1><<<dim3(128, 2, BATCH), 256, MM_SMEM>>>(xh, xl, wph, wpl, (float*)d_out, CDIM);
}

// round 5
// speedup vs baseline: 4.1727x; 1.4570x over previous
#include <cuda_runtime.h>
#include <cuda_bf16.h>
#include <cstdint>

#define EPSN 1e-12f

constexpr int BATCH = 8;
constexpr int CDIM  = 192;
constexpr int HWSZ  = 16384;   // 128*128
constexpr int NHEAD = 4;
constexpr int CHD   = 48;
constexpr int SPLIT = 8;

// ---------------------------------------------------------------------------
// helpers
// ---------------------------------------------------------------------------
__device__ __forceinline__ uint32_t s2u(const void* p) {
    uint32_t a;
    asm("{ .reg .u64 t; cvta.to.shared.u64 t, %1; cvt.u32.u64 %0, t; }" : "=r"(a) : "l"(p));
    return a;
}
#define SWZ(x) ((x) ^ (((x) >> 3) & 0x70))

__device__ __forceinline__ void cpa16(uint32_t dst, const void* src, int srcsize) {
    asm volatile("cp.async.cg.shared.global [%0], [%1], 16, %2;"
                 :: "r"(dst), "l"(src), "r"(srcsize));
}
#define CPA_COMMIT() asm volatile("cp.async.commit_group;" ::: "memory")
#define CPA_WAIT(n)  asm volatile("cp.async.wait_group %0;" :: "n"(n) : "memory")

__device__ __forceinline__ void ldsm4(uint32_t* r, uint32_t addr) {
    asm volatile("ldmatrix.sync.aligned.m8n8.x4.shared.b16 {%0,%1,%2,%3}, [%4];"
        : "=r"(r[0]), "=r"(r[1]), "=r"(r[2]), "=r"(r[3]) : "r"(addr));
}
__device__ __forceinline__ void ldsm4t(uint32_t* r, uint32_t addr) {
    asm volatile("ldmatrix.sync.aligned.m8n8.x4.trans.shared.b16 {%0,%1,%2,%3}, [%4];"
        : "=r"(r[0]), "=r"(r[1]), "=r"(r[2]), "=r"(r[3]) : "r"(addr));
}
__device__ __forceinline__ void mma16816(float* d, const uint32_t* a, const uint32_t* b) {
    asm volatile("mma.sync.aligned.m16n8k16.row.col.f32.bf16.bf16.f32 "
        "{%0,%1,%2,%3}, {%4,%5,%6,%7}, {%8,%9}, {%0,%1,%2,%3};"
        : "+f"(d[0]), "+f"(d[1]), "+f"(d[2]), "+f"(d[3])
        : "r"(a[0]), "r"(a[1]), "r"(a[2]), "r"(a[3]), "r"(b[0]), "r"(b[1]));
}

__device__ __forceinline__ void splitbf(float v, __nv_bfloat16& h, __nv_bfloat16& l) {
    h = __float2bfloat16(v);
    l = __float2bfloat16(v - __bfloat162float(h));
}
__device__ __forceinline__ uint32_t pack2(__nv_bfloat16 a, __nv_bfloat16 b) {
    return (uint32_t)__bfloat16_as_ushort(a) | ((uint32_t)__bfloat16_as_ushort(b) << 16);
}

// ---------------------------------------------------------------------------
// scratch buffers
// ---------------------------------------------------------------------------
__device__ __nv_bfloat16 g_wc_h[256 * 1728], g_wc_l[256 * 1728];   // folded 3x3 (t-major)
__device__ __nv_bfloat16 g_wq_h[640 * 192],  g_wq_l[640 * 192];    // qkv 1x1 (padded)
__device__ __nv_bfloat16 g_wp_h[256 * 192],  g_wp_l[256 * 192];    // proj 1x1 (padded)
__device__ __nv_bfloat16 g_xh[(size_t)BATCH * CDIM * HWSZ];        // act split hi (center)
__device__ __nv_bfloat16 g_xl[(size_t)BATCH * CDIM * HWSZ];        // act split lo
__device__ __nv_bfloat16 g_xhL[(size_t)BATCH * CDIM * HWSZ];       // shifted: [p] = x[p+1]
__device__ __nv_bfloat16 g_xlL[(size_t)BATCH * CDIM * HWSZ];
__device__ __nv_bfloat16 g_xhR[(size_t)BATCH * CDIM * HWSZ];       // shifted: [p] = x[p-1]
__device__ __nv_bfloat16 g_xlR[(size_t)BATCH * CDIM * HWSZ];
__device__ float g_cnf[(size_t)BATCH * CDIM * HWSZ];
__device__ float g_qkv1[(size_t)BATCH * 3 * CDIM * HWSZ];
__device__ float g_qkv[(size_t)BATCH * 3 * CDIM * HWSZ];
__device__ float g_coef[BATCH * CDIM * 3];
__device__ float g_gpart[BATCH * NHEAD * SPLIT * CHD * CHD];
__device__ float g_attn[BATCH * NHEAD * CHD * CHD];

// ---------------------------------------------------------------------------
// weight prep
// ---------------------------------------------------------------------------
__global__ void foldw_kernel(const float* __restrict__ w3, const float* __restrict__ w1,
                             __nv_bfloat16* __restrict__ wh, __nv_bfloat16* __restrict__ wl) {
    int idx = blockIdx.x * 256 + threadIdx.x;          // 256*1728
    int co = idx / 1728, r = idx % 1728;
    int t = r / 192, cj = r % 192;
    float s = 0.f;
    if (co < CDIM)
        for (int ci = 0; ci < CDIM; ci++)
            s = fmaf(w3[(co * CDIM + ci) * 9 + t], w1[ci * CDIM + cj], s);
    __nv_bfloat16 h, l; splitbf(s, h, l);
    wh[idx] = h; wl[idx] = l;
}

__global__ void splitw_kernel(const float* __restrict__ w, __nv_bfloat16* __restrict__ wh,
                              __nv_bfloat16* __restrict__ wl, int validRows) {
    int idx = blockIdx.x * 256 + threadIdx.x;
    int row = idx / CDIM;
    float v = (row < validRows) ? w[(size_t)row * CDIM + (idx % CDIM)] : 0.f;
    __nv_bfloat16 h, l; splitbf(v, h, l);
    wh[idx] = h; wl[idx] = l;
}

// elementwise fp32 -> bf16 hi/lo (center only)
__global__ __launch_bounds__(256) void asplit_kernel(
    const float* __restrict__ in, __nv_bfloat16* __restrict__ oh,
    __nv_bfloat16* __restrict__ ol, int n4) {
    int i = blockIdx.x * 256 + threadIdx.x;
    if (i >= n4) return;
    float4 v = ((const float4*)in)[i];
    __nv_bfloat16 h0, l0, h1, l1, h2, l2, h3, l3;
    splitbf(v.x, h0, l0); splitbf(v.y, h1, l1);
    splitbf(v.z, h2, l2); splitbf(v.w, h3, l3);
    ((uint2*)oh)[i] = make_uint2(pack2(h0, h1), pack2(h2, h3));
    ((uint2*)ol)[i] = make_uint2(pack2(l0, l1), pack2(l2, l3));
}

// fp32 -> bf16 hi/lo, center + left-shift + right-shift copies (row-edge zeroed)
__global__ __launch_bounds__(256) void asplit_shift_kernel(
    const float* __restrict__ in,
    __nv_bfloat16* __restrict__ oh,  __nv_bfloat16* __restrict__ ol,
    __nv_bfloat16* __restrict__ ohL, __nv_bfloat16* __restrict__ olL,
    __nv_bfloat16* __restrict__ ohR, __nv_bfloat16* __restrict__ olR, int n4) {
    int i = blockIdx.x * 256 + threadIdx.x;
    if (i >= n4) return;
    int p = i * 4;
    int col = p & 127;
    float4 v = ((const float4*)in)[i];
    float vnext = (col == 124) ? 0.f : in[p + 4];
    float vprev = (col == 0)   ? 0.f : in[p - 1];
    __nv_bfloat16 h[4], l[4];
    splitbf(v.x, h[0], l[0]); splitbf(v.y, h[1], l[1]);
    splitbf(v.z, h[2], l[2]); splitbf(v.w, h[3], l[3]);
    __nv_bfloat16 hn, ln, hp, lp;
    splitbf(vnext, hn, ln); splitbf(vprev, hp, lp);
    ((uint2*)oh)[i]  = make_uint2(pack2(h[0], h[1]), pack2(h[2], h[3]));
    ((uint2*)ol)[i]  = make_uint2(pack2(l[0], l[1]), pack2(l[2], l[3]));
    ((uint2*)ohL)[i] = make_uint2(pack2(h[1], h[2]), pack2(h[3], hn));
    ((uint2*)olL)[i] = make_uint2(pack2(l[1], l[2]), pack2(l[3], ln));
    ((uint2*)ohR)[i] = make_uint2(pack2(hp, h[0]), pack2(h[1], h[2]));
    ((uint2*)olR)[i] = make_uint2(pack2(lp, l[0]), pack2(l[1], l[2]));
}

// ---------------------------------------------------------------------------
// HMMA GEMM with 3-stage cp.async pipeline.
//   CTA tile 128m x 128n, K-chunk 64, 3-term bf16 split, fp32 acc.
//   stage layout (64KB): A_hi 0 | A_lo 16K | B_hi 32K | B_lo 48K
//   TAPS=9: implicit im2col (k = t*192+ci); x-shift via pre-shifted arrays.
// ---------------------------------------------------------------------------
template <int KTOT, int TAPS>
__global__ __launch_bounds__(256) void mm_kernel(
    const __nv_bfloat16* __restrict__ xh,  const __nv_bfloat16* __restrict__ xl,
    const __nv_bfloat16* __restrict__ xhL, const __nv_bfloat16* __restrict__ xlL,
    const __nv_bfloat16* __restrict__ xhR, const __nv_bfloat16* __restrict__ xlR,
    const __nv_bfloat16* __restrict__ wh,  const __nv_bfloat16* __restrict__ wl,
    float* __restrict__ out, int Cout) {
    extern __shared__ char sraw[];
    char* sal = (char*)((((uintptr_t)sraw) + 127) & ~(uintptr_t)127);
    const uint32_t sb = s2u(sal);
    const int tid = threadIdx.x, lane = tid & 31, wid = tid >> 5;
    const int n0 = blockIdx.x * 128, m0 = blockIdx.y * 128, b = blockIdx.z;
    const int wm = wid >> 1, wn = wid & 1;
    const int y = n0 >> 7;
    const int lr = lane & 15, lc = lane >> 4;
    constexpr int NCH = KTOT / 64;

    // ---- async load of chunk cc into stage cc%3
    auto load_chunk = [&](int cc) {
        const int k0 = cc * 64;
        const int t = (TAPS == 9) ? (k0 / 192) : 0;
        const int ci0 = k0 - t * 192;
        // FIX(R4): tap offsets exist only for the conv; TAPS==1 must use dy=dx=0.
        const int dy = (TAPS == 9) ? (t / 3 - 1) : 0;
        const int dx = (TAPS == 9) ? (t % 3 - 1) : 0;
        const int yy = y + dy;
        const bool rowok = (TAPS == 1) || ((unsigned)yy < 128u);
        const int ys = rowok ? yy : y;
        const uint32_t stg = sb + (uint32_t)(cc % 3) * 65536u;
        // A (weights; rows padded, always valid)
#pragma unroll
        for (int i = 0; i < 8; i++) {
            int e = tid + (i << 8);
            int ck = e & 7, r = (e >> 3) & 127, dt = e >> 10;
            const __nv_bfloat16* src = (dt ? wl : wh) + (size_t)(m0 + r) * KTOT + k0 + ck * 8;
            cpa16(stg + dt * 16384 + SWZ(r * 128 + ck * 16), src, 16);
        }
        // B (activations; pre-shifted arrays select dx)
        const __nv_bfloat16 *bhp, *blp;
        if (dx == 0)      { bhp = xh;  blp = xl;  }
        else if (dx > 0)  { bhp = xhL; blp = xlL; }
        else              { bhp = xhR; blp = xlR; }
        const int sz = rowok ? 16 : 0;
#pragma unroll
        for (int i = 0; i < 8; i++) {
            int e = tid + (i << 8);
            int nc = e & 15, k = (e >> 4) & 63, dt = e >> 10;
            int n = nc * 8;
            const __nv_bfloat16* src =
                (dt ? blp : bhp) + ((size_t)b * CDIM + ci0 + k) * HWSZ + ys * 128 + n;
            cpa16(stg + 32768 + dt * 16384 + (nc >> 3) * 8192 + SWZ(k * 128 + (n & 63) * 2),
                  src, sz);
        }
        CPA_COMMIT();
    };

    float acc[2][8][4];
#pragma unroll
    for (int i = 0; i < 2; i++)
#pragma unroll
        for (int j = 0; j < 8; j++)
#pragma unroll
            for (int q = 0; q < 4; q++) acc[i][j][q] = 0.f;

    load_chunk(0);
    if (NCH > 1) load_chunk(1);

    for (int cc = 0; cc < NCH; cc++) {
        if (cc + 2 < NCH) load_chunk(cc + 2);
        if (cc + 2 < NCH)      CPA_WAIT(2);
        else if (cc + 1 < NCH) CPA_WAIT(1);
        else                   CPA_WAIT(0);
        __syncthreads();
        const uint32_t stg = sb + (uint32_t)(cc % 3) * 65536u;

#pragma unroll
        for (int ks = 0; ks < 4; ks++) {
            uint32_t ah[2][4], alo[2][4];
#pragma unroll
            for (int mf = 0; mf < 2; mf++) {
                uint32_t ao = SWZ((wm * 32 + mf * 16 + lr) * 128 + ks * 32 + lc * 16);
                ldsm4(ah[mf],  stg + ao);
                ldsm4(alo[mf], stg + 16384 + ao);
            }
#pragma unroll
            for (int g = 0; g < 4; g++) {
                uint32_t bh[4], bl[4];
                uint32_t bo = 32768 + wn * 8192 + SWZ((ks * 16 + lr) * 128 + g * 32 + lc * 16);
                ldsm4t(bh, stg + bo);
                ldsm4t(bl, stg + 16384 + bo);
#pragma unroll
                for (int mf = 0; mf < 2; mf++) {
                    mma16816(acc[mf][2 * g],     ah[mf],  bh);
                    mma16816(acc[mf][2 * g],     ah[mf],  bl);
                    mma16816(acc[mf][2 * g],     alo[mf], bh);
                    mma16816(acc[mf][2 * g + 1], ah[mf],  bh + 2);
                    mma16816(acc[mf][2 * g + 1], ah[mf],  bl + 2);
                    mma16816(acc[mf][2 * g + 1], alo[mf], bh + 2);
                }
            }
        }
        __syncthreads();
    }

    // ---- epilogue: direct fp32 stores
#pragma unroll
    for (int mf = 0; mf < 2; mf++) {
        int mb = m0 + wm * 32 + mf * 16 + (lane >> 2);
#pragma unroll
        for (int nb = 0; nb < 8; nb++) {
            int nn = n0 + wn * 64 + nb * 8 + (lane & 3) * 2;
            if (mb < Cout)
                *(float2*)(out + ((size_t)b * Cout + mb) * HWSZ + nn) =
                    make_float2(acc[mf][nb][0], acc[mf][nb][1]);
            if (mb + 8 < Cout)
                *(float2*)(out + ((size_t)b * Cout + mb + 8) * HWSZ + nn) =
                    make_float2(acc[mf][nb][2], acc[mf][nb][3]);
        }
    }
}

// ---------------------------------------------------------------------------
// depthwise 3x3, float4 vectorized
// ---------------------------------------------------------------------------
__global__ __launch_bounds__(256) void dwconv3_kernel(
    const float* __restrict__ in, const float* __restrict__ wdw,
    float* __restrict__ out) {
    int c = blockIdx.y, b = blockIdx.z;
    int p4 = (blockIdx.x * 256 + threadIdx.x) * 4;
    int y = p4 >> 7, x = p4 & 127;
    const float* src = in + ((size_t)b * (3 * CDIM) + c) * HWSZ;
    float w[9];
#pragma unroll
    for (int i = 0; i < 9; i++) w[i] = wdw[c * 9 + i];
    float4 a = make_float4(0.f, 0.f, 0.f, 0.f);
#pragma unroll
    for (int r = -1; r <= 1; r++) {
        int yy = y + r;
        if ((unsigned)yy >= 128u) continue;
        const float* rp = src + (yy << 7);
        float4 m = *(const float4*)(rp + x);
        float L = (x > 0) ? rp[x - 1] : 0.f;
        float R = (x + 4 < 128) ? rp[x + 4] : 0.f;
        int wb = (r + 1) * 3;
        a.x = fmaf(w[wb], L,   fmaf(w[wb + 1], m.x, fmaf(w[wb + 2], m.y, a.x)));
        a.y = fmaf(w[wb], m.x, fmaf(w[wb + 1], m.y, fmaf(w[wb + 2], m.z, a.y)));
        a.z = fmaf(w[wb], m.y, fmaf(w[wb + 1], m.z, fmaf(w[wb + 2], m.w, a.z)));
        a.w = fmaf(w[wb], m.z, fmaf(w[wb + 1], m.w, fmaf(w[wb + 2], R,   a.w)));
    }
    *(float4*)(out + ((size_t)b * (3 * CDIM) + c) * HWSZ + p4) = a;
}

// ---------------------------------------------------------------------------
// per-row norms -> normalization coefficients
// ---------------------------------------------------------------------------
__global__ __launch_bounds__(256) void stats_kernel(
    const float* __restrict__ qkv, const float* __restrict__ cnf,
    float* __restrict__ coef) {
    int rowi = blockIdx.x;
    int b = rowi / CDIM, c = rowi % CDIM;
    const float* q  = qkv + ((size_t)b * (3 * CDIM) + c) * HWSZ;
    const float* kk = qkv + ((size_t)b * (3 * CDIM) + CDIM + c) * HWSZ;
    const float* cn = cnf + (size_t)rowi * HWSZ;
    float sq = 0.f, sk = 0.f, sc = 0.f, sqc = 0.f;
    for (int i = threadIdx.x; i < HWSZ; i += 256) {
        float qv = q[i], kv = kk[i], cv = cn[i];
        sq = fmaf(qv, qv, sq); sk = fmaf(kv, kv, sk);
        sc = fmaf(cv, cv, sc); sqc = fmaf(qv, cv, sqc);
    }
#pragma unroll
    for (int o = 16; o; o >>= 1) {
        sq += __shfl_xor_sync(~0u, sq, o); sk += __shfl_xor_sync(~0u, sk, o);
        sc += __shfl_xor_sync(~0u, sc, o); sqc += __shfl_xor_sync(~0u, sqc, o);
    }
    __shared__ float r4[4][8];
    int wid = threadIdx.x >> 5, lane = threadIdx.x & 31;
    if (lane == 0) { r4[0][wid] = sq; r4[1][wid] = sk; r4[2][wid] = sc; r4[3][wid] = sqc; }
    __syncthreads();
    if (threadIdx.x == 0) {
        float SQ = 0, SK = 0, SC = 0, SQC = 0;
        for (int i = 0; i < 8; i++) { SQ += r4[0][i]; SK += r4[1][i]; SC += r4[2][i]; SQC += r4[3][i]; }
        float a  = fmaxf(sqrtf(SQ), EPSN);
        float bb = fmaxf(sqrtf(SC), EPSN);
        float s2 = SQ / (a * a) + 2.f * SQC / (a * bb) + SC / (bb * bb);
        float s  = fmaxf(sqrtf(s2), EPSN);
        float kn = fmaxf(sqrtf(SK), EPSN);
        coef[rowi * 3 + 0] = 1.f / (a * s);
        coef[rowi * 3 + 1] = 1.f / (bb * s);
        coef[rowi * 3 + 2] = 1.f / kn;
    }
}

// ---------------------------------------------------------------------------
// gram / softmax / apply
// ---------------------------------------------------------------------------
__global__ __launch_bounds__(256) void gram_kernel(
    const float* __restrict__ qkv, const float* __restrict__ cnf,
    const float* __restrict__ coef, float* __restrict__ gpart) {
    __shared__ float SQ[48][33];
    __shared__ float SK[48][33];
    __shared__ float al[48], be[48], ga[48];
    int bh = blockIdx.x, sp = blockIdx.y;
    int b = bh >> 2, h = bh & 3;
    int tid = threadIdx.x, tx = tid & 15, ty = tid >> 4;
    if (tid < 48) {
        int rw = b * CDIM + h * CHD + tid;
        al[tid] = coef[rw * 3 + 0]; be[tid] = coef[rw * 3 + 1]; ga[tid] = coef[rw * 3 + 2];
    }
    __syncthreads();
    const float* qb = qkv + ((size_t)b * (3 * CDIM) + h * CHD) * HWSZ;
    const float* kb = qkv + ((size_t)b * (3 * CDIM) + CDIM + h * CHD) * HWSZ;
    const float* cb = cnf + ((size_t)b * CDIM + h * CHD) * HWSZ;
    float acc[3][3] = {};
    int send = sp * 2048 + 2048;
    for (int s0 = sp * 2048; s0 < send; s0 += 32) {
        for (int e = tid; e < 1536; e += 256) {
            int r = e >> 5, s = e & 31;
            int off = r * HWSZ + s0 + s;
            SQ[r][s] = al[r] * qb[off] + be[r] * cb[off];
            SK[r][s] = ga[r] * kb[off];
        }
        __syncthreads();
#pragma unroll 4
        for (int s = 0; s < 32; s++) {
            float qa[3], kv[3];
#pragma unroll
            for (int i = 0; i < 3; i++) qa[i] = SQ[tx + 16 * i][s];
#pragma unroll
            for (int j = 0; j < 3; j++) kv[j] = SK[ty + 16 * j][s];
#pragma unroll
            for (int i = 0; i < 3; i++)
#pragma unroll
                for (int j = 0; j < 3; j++)
                    acc[i][j] = fmaf(qa[i], kv[j], acc[i][j]);
        }
        __syncthreads();
    }
#pragma unroll
    for (int i = 0; i < 3; i++)
#pragma unroll
        for (int j = 0; j < 3; j++)
            gpart[((bh * SPLIT + sp) * CHD + tx + 16 * i) * CHD + ty + 16 * j] = acc[i][j];
}

__global__ __launch_bounds__(256) void softmax_kernel(
    const float* __restrict__ gpart, const float* __restrict__ temp,
    float* __restrict__ attn) {
    __shared__ float S[48][49];
    int bh = blockIdx.x;
    float T = temp[bh & 3];
    int tid = threadIdx.x;
    for (int e = tid; e < CHD * CHD; e += 256) {
        int c = e / CHD, d = e - c * CHD;
        float g = 0.f;
#pragma unroll
        for (int sp = 0; sp < SPLIT; sp++)
            g += gpart[((bh * SPLIT + sp) * CHD + c) * CHD + d];
        S[c][d] = g * T;
    }
    __syncthreads();
    int wid = tid >> 5, lane = tid & 31;
    for (int r = wid; r < 48; r += 8) {
        float v1 = S[r][lane];
        float v2 = (lane < 16) ? S[r][32 + lane] : -1e30f;
        float m = fmaxf(v1, v2);
#pragma unroll
        for (int o = 16; o; o >>= 1) m = fmaxf(m, __shfl_xor_sync(~0u, m, o));
        float e1 = expf(v1 - m);
        float e2 = (lane < 16) ? expf(v2 - m) : 0.f;
        float s = e1 + e2;
#pragma unroll
        for (int o = 16; o; o >>= 1) s += __shfl_xor_sync(~0u, s, o);
        float inv = 1.f / s;
        attn[bh * (CHD * CHD) + r * CHD + lane] = e1 * inv;
        if (lane < 16) attn[bh * (CHD * CHD) + r * CHD + 32 + lane] = e2 * inv;
    }
}

// attn @ v, fused with bf16 hi/lo split (feeds proj GEMM directly)
__global__ __launch_bounds__(256) void apply_kernel(
    const float* __restrict__ qkv, const float* __restrict__ attn,
    __nv_bfloat16* __restrict__ oh, __nv_bfloat16* __restrict__ ol) {
    __shared__ float A[48][48];
    int b = blockIdx.z, h = blockIdx.y;
    int tid = threadIdx.x;
    for (int e = tid; e < CHD * CHD; e += 256)
        A[e / CHD][e % CHD] = attn[(b * NHEAD + h) * (CHD * CHD) + e];
    __syncthreads();
    int p = blockIdx.x * 512 + tid;
    const float* vb = qkv + ((size_t)b * (3 * CDIM) + 2 * CDIM + h * CHD) * HWSZ;
    float a0[48], a1[48];
#pragma unroll
    for (int c = 0; c < 48; c++) { a0[c] = 0.f; a1[c] = 0.f; }
#pragma unroll 2
    for (int d = 0; d < 48; d++) {
        float v0 = vb[d * HWSZ + p];
        float v1 = vb[d * HWSZ + p + 256];
#pragma unroll
        for (int c = 0; c < 48; c++) {
            float a = A[c][d];
            a0[c] = fmaf(a, v0, a0[c]);
            a1[c] = fmaf(a, v1, a1[c]);
        }
    }
    size_t ob = ((size_t)b * CDIM + h * CHD) * HWSZ;
#pragma unroll
    for (int c = 0; c < 48; c++) {
        __nv_bfloat16 hh, ll;
        splitbf(a0[c], hh, ll);
        oh[ob + c * HWSZ + p] = hh; ol[ob + c * HWSZ + p] = ll;
        splitbf(a1[c], hh, ll);
        oh[ob + c * HWSZ + p + 256] = hh; ol[ob + c * HWSZ + p + 256] = ll;
    }
}

// ---------------------------------------------------------------------------
// launch
// ---------------------------------------------------------------------------
constexpr int MM_SMEM = 3 * 65536 + 128;

extern "C" void kernel_launch(void* const* d_in, const int* in_sizes, int n_in,
                              void* d_out, int out_size) {
    const float* x     = (const float*)d_in[0];
    const float* cn    = (const float*)d_in[1];
    const float* w1    = (const float*)d_in[2];
    const float* w3    = (const float*)d_in[3];
    const float* qkvw  = (const float*)d_in[4];
    const float* dww   = (const float*)d_in[5];
    const float* projw = (const float*)d_in[6];
    const float* temp  = (const float*)d_in[7];

    __nv_bfloat16 *wch, *wcl, *wqh, *wql, *wph, *wpl;
    __nv_bfloat16 *xh, *xl, *xhL, *xlL, *xhR, *xlR;
    float *cnf, *qkv1, *qkv2, *coef, *gpart, *attn;
    cudaGetSymbolAddress((void**)&wch, g_wc_h);  cudaGetSymbolAddress((void**)&wcl, g_wc_l);
    cudaGetSymbolAddress((void**)&wqh, g_wq_h);  cudaGetSymbolAddress((void**)&wql, g_wq_l);
    cudaGetSymbolAddress((void**)&wph, g_wp_h);  cudaGetSymbolAddress((void**)&wpl, g_wp_l);
    cudaGetSymbolAddress((void**)&xh,  g_xh);    cudaGetSymbolAddress((void**)&xl,  g_xl);
    cudaGetSymbolAddress((void**)&xhL, g_xhL);   cudaGetSymbolAddress((void**)&xlL, g_xlL);
    cudaGetSymbolAddress((void**)&xhR, g_xhR);   cudaGetSymbolAddress((void**)&xlR, g_xlR);
    cudaGetSymbolAddress((void**)&cnf,  g_cnf);
    cudaGetSymbolAddress((void**)&qkv1, g_qkv1);
    cudaGetSymbolAddress((void**)&qkv2, g_qkv);
    cudaGetSymbolAddress((void**)&coef, g_coef);
    cudaGetSymbolAddress((void**)&gpart, g_gpart);
    cudaGetSymbolAddress((void**)&attn, g_attn);

    cudaFuncSetAttribute(mm_kernel<1728, 9>, cudaFuncAttributeMaxDynamicSharedMemorySize, MM_SMEM);
    cudaFuncSetAttribute(mm_kernel<192, 1>,  cudaFuncAttributeMaxDynamicSharedMemorySize, MM_SMEM);

    const int NACT4 = BATCH * CDIM * HWSZ / 4;

    // weight prep
    foldw_kernel<<<256 * 1728 / 256, 256>>>(w3, w1, wch, wcl);
    splitw_kernel<<<640 * 192 / 256, 256>>>(qkvw, wqh, wql, 3 * CDIM);
    splitw_kernel<<<256 * 192 / 256, 256>>>(projw, wph, wpl, CDIM);

    // cn branch: split + shifted copies, folded 3x3 conv (pipelined HMMA)
    asplit_shift_kernel<<<(NACT4 + 255) / 256, 256>>>(cn, xh, xl, xhL, xlL, xhR, xlR, NACT4);
    mm_kernel<1728, 9><<<dim3(128, 2, BATCH), 256, MM_SMEM>>>(
        xh, xl, xhL, xlL, xhR, xlR, wch, wcl, cnf, CDIM);

    // qkv 1x1 (pipelined HMMA)
    asplit_kernel<<<(NACT4 + 255) / 256, 256>>>(x, xh, xl, NACT4);
    mm_kernel<192, 1><<<dim3(128, 5, BATCH), 256, MM_SMEM>>>(
        xh, xl, xh, xl, xh, xl, wqh, wql, qkv1, 3 * CDIM);

    // depthwise 3x3
    dwconv3_kernel<<<dim3(HWSZ / 1024, 3 * CDIM, BATCH), 256>>>(qkv1, dww, qkv2);

    // attention chain
    stats_kernel<<<BATCH * CDIM, 256>>>(qkv2, cnf, coef);
    gram_kernel<<<dim3(BATCH * NHEAD, SPLIT), 256>>>(qkv2, cnf, coef, gpart);
    softmax_kernel<<<BATCH * NHEAD, 256>>>(gpart, temp, attn);
    apply_kernel<<<dim3(32, NHEAD, BATCH), 256>>>(qkv2, attn, xh, xl);

    // projection 1x1 (pipelined HMMA; reads bf16 hi/lo written by apply)
    mm_kernel<192, 1><<<dim3(128, 2, BATCH), 256, MM_SMEM>>>(
        xh, xl, xh, xl, xh, xl, wph, wpl, (float*)d_out, CDIM);
}

// round 6
// speedup vs baseline: 4.8563x; 1.1638x over previous
#include <cuda_runtime.h>
#include <cuda_bf16.h>
#include <cuda_fp16.h>
#include <cstdint>

#define EPSN 1e-12f

constexpr int BATCH = 8;
constexpr int CDIM  = 192;
constexpr int HWSZ  = 16384;   // 128*128
constexpr int NHEAD = 4;
constexpr int CHD   = 48;
constexpr int SPLIT = 8;
constexpr float WSC  = 64.f;        // conv weight pre-scale (keeps fp16 lo normal)
constexpr float IWSC = 1.f / 64.f;

// ---------------------------------------------------------------------------
// helpers
// ---------------------------------------------------------------------------
__device__ __forceinline__ uint32_t s2u(const void* p) {
    uint32_t a;
    asm("{ .reg .u64 t; cvta.to.shared.u64 t, %1; cvt.u32.u64 %0, t; }" : "=r"(a) : "l"(p));
    return a;
}
#define SWZ(x) ((x) ^ (((x) >> 3) & 0x70))

__device__ __forceinline__ void cpa16(uint32_t dst, const void* src, int srcsize) {
    asm volatile("cp.async.cg.shared.global [%0], [%1], 16, %2;"
                 :: "r"(dst), "l"(src), "r"(srcsize));
}
#define CPA_COMMIT() asm volatile("cp.async.commit_group;" ::: "memory")
#define CPA_WAIT(n)  asm volatile("cp.async.wait_group %0;" :: "n"(n) : "memory")

__device__ __forceinline__ void ldsm4(uint32_t* r, uint32_t addr) {
    asm volatile("ldmatrix.sync.aligned.m8n8.x4.shared.b16 {%0,%1,%2,%3}, [%4];"
        : "=r"(r[0]), "=r"(r[1]), "=r"(r[2]), "=r"(r[3]) : "r"(addr));
}
__device__ __forceinline__ void ldsm4t(uint32_t* r, uint32_t addr) {
    asm volatile("ldmatrix.sync.aligned.m8n8.x4.trans.shared.b16 {%0,%1,%2,%3}, [%4];"
        : "=r"(r[0]), "=r"(r[1]), "=r"(r[2]), "=r"(r[3]) : "r"(addr));
}
template <typename T>
__device__ __forceinline__ void mma16816(float* d, const uint32_t* a, const uint32_t* b);
template <>
__device__ __forceinline__ void mma16816<__nv_bfloat16>(float* d, const uint32_t* a, const uint32_t* b) {
    asm volatile("mma.sync.aligned.m16n8k16.row.col.f32.bf16.bf16.f32 "
        "{%0,%1,%2,%3}, {%4,%5,%6,%7}, {%8,%9}, {%0,%1,%2,%3};"
        : "+f"(d[0]), "+f"(d[1]), "+f"(d[2]), "+f"(d[3])
        : "r"(a[0]), "r"(a[1]), "r"(a[2]), "r"(a[3]), "r"(b[0]), "r"(b[1]));
}
template <>
__device__ __forceinline__ void mma16816<__half>(float* d, const uint32_t* a, const uint32_t* b) {
    asm volatile("mma.sync.aligned.m16n8k16.row.col.f32.f16.f16.f32 "
        "{%0,%1,%2,%3}, {%4,%5,%6,%7}, {%8,%9}, {%0,%1,%2,%3};"
        : "+f"(d[0]), "+f"(d[1]), "+f"(d[2]), "+f"(d[3])
        : "r"(a[0]), "r"(a[1]), "r"(a[2]), "r"(a[3]), "r"(b[0]), "r"(b[1]));
}

__device__ __forceinline__ void splitbf(float v, __nv_bfloat16& h, __nv_bfloat16& l) {
    h = __float2bfloat16(v);
    l = __float2bfloat16(v - __bfloat162float(h));
}
__device__ __forceinline__ uint32_t pack2(__nv_bfloat16 a, __nv_bfloat16 b) {
    return (uint32_t)__bfloat16_as_ushort(a) | ((uint32_t)__bfloat16_as_ushort(b) << 16);
}
__device__ __forceinline__ uint32_t pack2h(__half a, __half b) {
    return (uint32_t)__half_as_ushort(a) | ((uint32_t)__half_as_ushort(b) << 16);
}

// ---------------------------------------------------------------------------
// scratch buffers
// ---------------------------------------------------------------------------
__device__ __half        g_wc_h[256 * 1728], g_wc_l[256 * 1728];   // folded 3x3, fp16, x64
__device__ __nv_bfloat16 g_wq_h[640 * 192],  g_wq_l[640 * 192];    // qkv 1x1 (padded)
__device__ __nv_bfloat16 g_wp_h[256 * 192],  g_wp_l[256 * 192];    // proj 1x1 (padded)
__device__ __half g_ch [(size_t)BATCH * CDIM * HWSZ];              // cn fp16 (center)
__device__ __half g_chL[(size_t)BATCH * CDIM * HWSZ];              // cn fp16 [p]=x[p+1]
__device__ __half g_chR[(size_t)BATCH * CDIM * HWSZ];              // cn fp16 [p]=x[p-1]
__device__ __nv_bfloat16 g_xh[(size_t)BATCH * CDIM * HWSZ];        // bf16 hi (x / av)
__device__ __nv_bfloat16 g_xl[(size_t)BATCH * CDIM * HWSZ];        // bf16 lo
__device__ float g_cnf[(size_t)BATCH * CDIM * HWSZ];
__device__ float g_qkv1[(size_t)BATCH * 3 * CDIM * HWSZ];
__device__ float g_qkv[(size_t)BATCH * 3 * CDIM * HWSZ];
__device__ float g_coef[BATCH * CDIM * 3];
__device__ float g_gpart[BATCH * NHEAD * SPLIT * CHD * CHD];
__device__ float g_attn[BATCH * NHEAD * CHD * CHD];

// ---------------------------------------------------------------------------
// weight prep
// ---------------------------------------------------------------------------
// fold 1x1 into 3x3 (k = t*192+cj), scale x64, fp16 hi/lo split
__global__ void foldw_kernel(const float* __restrict__ w3, const float* __restrict__ w1,
                             __half* __restrict__ wh, __half* __restrict__ wl) {
    int idx = blockIdx.x * 256 + threadIdx.x;          // 256*1728
    int co = idx / 1728, r = idx % 1728;
    int t = r / 192, cj = r % 192;
    float s = 0.f;
    if (co < CDIM)
        for (int ci = 0; ci < CDIM; ci++)
            s = fmaf(w3[(co * CDIM + ci) * 9 + t], w1[ci * CDIM + cj], s);
    s *= WSC;
    __half h = __float2half(s);
    wh[idx] = h;
    wl[idx] = __float2half(s - __half2float(h));
}

__global__ void splitw_kernel(const float* __restrict__ w, __nv_bfloat16* __restrict__ wh,
                              __nv_bfloat16* __restrict__ wl, int validRows) {
    int idx = blockIdx.x * 256 + threadIdx.x;
    int row = idx / CDIM;
    float v = (row < validRows) ? w[(size_t)row * CDIM + (idx % CDIM)] : 0.f;
    __nv_bfloat16 h, l; splitbf(v, h, l);
    wh[idx] = h; wl[idx] = l;
}

// elementwise fp32 -> bf16 hi/lo
__global__ __launch_bounds__(256) void asplit_kernel(
    const float* __restrict__ in, __nv_bfloat16* __restrict__ oh,
    __nv_bfloat16* __restrict__ ol, int n4) {
    int i = blockIdx.x * 256 + threadIdx.x;
    if (i >= n4) return;
    float4 v = ((const float4*)in)[i];
    __nv_bfloat16 h0, l0, h1, l1, h2, l2, h3, l3;
    splitbf(v.x, h0, l0); splitbf(v.y, h1, l1);
    splitbf(v.z, h2, l2); splitbf(v.w, h3, l3);
    ((uint2*)oh)[i] = make_uint2(pack2(h0, h1), pack2(h2, h3));
    ((uint2*)ol)[i] = make_uint2(pack2(l0, l1), pack2(l2, l3));
}

// fp32 -> fp16, center + left/right shifted copies (row-edge zeroed)
__global__ __launch_bounds__(256) void asplit_shift_h_kernel(
    const float* __restrict__ in,
    __half* __restrict__ oh, __half* __restrict__ ohL, __half* __restrict__ ohR, int n4) {
    int i = blockIdx.x * 256 + threadIdx.x;
    if (i >= n4) return;
    int p = i * 4;
    int col = p & 127;
    float4 v = ((const float4*)in)[i];
    float vnext = (col == 124) ? 0.f : in[p + 4];
    float vprev = (col == 0)   ? 0.f : in[p - 1];
    __half h0 = __float2half(v.x), h1 = __float2half(v.y);
    __half h2 = __float2half(v.z), h3 = __float2half(v.w);
    __half hn = __float2half(vnext), hp = __float2half(vprev);
    ((uint2*)oh)[i]  = make_uint2(pack2h(h0, h1), pack2h(h2, h3));
    ((uint2*)ohL)[i] = make_uint2(pack2h(h1, h2), pack2h(h3, hn));
    ((uint2*)ohR)[i] = make_uint2(pack2h(hp, h0), pack2h(h1, h2));
}

// ---------------------------------------------------------------------------
// HMMA GEMM, multi-stage cp.async pipeline.
//   CTA tile 128m x 128n, K-chunk 64, fp32 acc.
//   TERMS==3 (bf16): C = AhBh + AhBl + AlBh ; stage 64KB, 3 stages, 1 CTA/SM
//   TERMS==2 (fp16): C = AhB + AlB (A=weights exact, B=act fp16) ;
//                    stage 48KB, 2 stages, 2 CTAs/SM ; epilogue x 1/WSC
//   stage layout: A_hi 0 | A_lo 16K | B_hi 32K | (B_lo 48K if TERMS==3)
//   TAPS=9: implicit im2col (k = t*192+ci); x-shift via pre-shifted arrays.
// ---------------------------------------------------------------------------
template <int KTOT, int TAPS, int TERMS, int MINB, typename T>
__global__ __launch_bounds__(256, MINB) void mm_kernel(
    const T* __restrict__ xh,  const T* __restrict__ xl,
    const T* __restrict__ xhL, const T* __restrict__ xlL,
    const T* __restrict__ xhR, const T* __restrict__ xlR,
    const T* __restrict__ wh,  const T* __restrict__ wl,
    float* __restrict__ out, int Cout) {
    constexpr int SSZ    = (TERMS == 3) ? 65536 : 49152;
    constexpr int STAGES = (TERMS == 3) ? 3 : 2;
    extern __shared__ char sraw[];
    char* sal = (char*)((((uintptr_t)sraw) + 127) & ~(uintptr_t)127);
    const uint32_t sb = s2u(sal);
    const int tid = threadIdx.x, lane = tid & 31, wid = tid >> 5;
    const int n0 = blockIdx.x * 128, m0 = blockIdx.y * 128, b = blockIdx.z;
    const int wm = wid >> 1, wn = wid & 1;
    const int y = n0 >> 7;
    const int lr = lane & 15, lc = lane >> 4;
    constexpr int NCH = KTOT / 64;

    auto load_chunk = [&](int cc) {
        const int k0 = cc * 64;
        const int t = (TAPS == 9) ? (k0 / 192) : 0;
        const int ci0 = k0 - t * 192;
        const int dy = (TAPS == 9) ? (t / 3 - 1) : 0;
        const int dx = (TAPS == 9) ? (t % 3 - 1) : 0;
        const int yy = y + dy;
        const bool rowok = (TAPS == 1) || ((unsigned)yy < 128u);
        const int ys = rowok ? yy : y;
        const uint32_t stg = sb + (uint32_t)(cc % STAGES) * SSZ;
        // A (weights, 2 terms always)
#pragma unroll
        for (int i = 0; i < 8; i++) {
            int e = tid + (i << 8);
            int ck = e & 7, r = (e >> 3) & 127, dt = e >> 10;
            const T* src = (dt ? wl : wh) + (size_t)(m0 + r) * KTOT + k0 + ck * 8;
            cpa16(stg + dt * 16384 + SWZ(r * 128 + ck * 16), src, 16);
        }
        // B (activations; TERMS-1 buffers)
        const T *bhp, *blp;
        if (dx == 0)      { bhp = xh;  blp = xl;  }
        else if (dx > 0)  { bhp = xhL; blp = xlL; }
        else              { bhp = xhR; blp = xlR; }
        const int sz = rowok ? 16 : 0;
#pragma unroll
        for (int i = 0; i < 4 * (TERMS - 1); i++) {
            int e = tid + (i << 8);
            int nc = e & 15, k = (e >> 4) & 63, dt = e >> 10;
            int n = nc * 8;
            const T* src =
                (dt ? blp : bhp) + ((size_t)b * CDIM + ci0 + k) * HWSZ + ys * 128 + n;
            cpa16(stg + 32768 + dt * 16384 + (nc >> 3) * 8192 + SWZ(k * 128 + (n & 63) * 2),
                  src, sz);
        }
        CPA_COMMIT();
    };

    float acc[2][8][4];
#pragma unroll
    for (int i = 0; i < 2; i++)
#pragma unroll
        for (int j = 0; j < 8; j++)
#pragma unroll
            for (int q = 0; q < 4; q++) acc[i][j][q] = 0.f;

#pragma unroll
    for (int i = 0; i < STAGES - 1 && i < NCH; i++) load_chunk(i);

    for (int cc = 0; cc < NCH; cc++) {
        if (cc + STAGES - 1 < NCH) load_chunk(cc + STAGES - 1);
        int pend = ((cc + STAGES - 1 < NCH) ? (STAGES - 1) : (NCH - 1 - cc));
        if (pend >= 2)      CPA_WAIT(2);
        else if (pend == 1) CPA_WAIT(1);
        else                CPA_WAIT(0);
        __syncthreads();
        const uint32_t stg = sb + (uint32_t)(cc % STAGES) * SSZ;

#pragma unroll
        for (int ks = 0; ks < 4; ks++) {
            uint32_t ah[2][4], alo[2][4];
#pragma unroll
            for (int mf = 0; mf < 2; mf++) {
                uint32_t ao = SWZ((wm * 32 + mf * 16 + lr) * 128 + ks * 32 + lc * 16);
                ldsm4(ah[mf],  stg + ao);
                ldsm4(alo[mf], stg + 16384 + ao);
            }
#pragma unroll
            for (int g = 0; g < 4; g++) {
                uint32_t bh[4], bl[4];
                uint32_t bo = 32768 + wn * 8192 + SWZ((ks * 16 + lr) * 128 + g * 32 + lc * 16);
                ldsm4t(bh, stg + bo);
                if (TERMS == 3) ldsm4t(bl, stg + 16384 + bo);
#pragma unroll
                for (int mf = 0; mf < 2; mf++) {
                    mma16816<T>(acc[mf][2 * g],     ah[mf],  bh);
                    mma16816<T>(acc[mf][2 * g],     alo[mf], bh);
                    mma16816<T>(acc[mf][2 * g + 1], ah[mf],  bh + 2);
                    mma16816<T>(acc[mf][2 * g + 1], alo[mf], bh + 2);
                    if (TERMS == 3) {
                        mma16816<T>(acc[mf][2 * g],     ah[mf], bl);
                        mma16816<T>(acc[mf][2 * g + 1], ah[mf], bl + 2);
                    }
                }
            }
        }
        __syncthreads();
    }

    // ---- epilogue
    const float osc = (TERMS == 2) ? IWSC : 1.f;
#pragma unroll
    for (int mf = 0; mf < 2; mf++) {
        int mb = m0 + wm * 32 + mf * 16 + (lane >> 2);
#pragma unroll
        for (int nb = 0; nb < 8; nb++) {
            int nn = n0 + wn * 64 + nb * 8 + (lane & 3) * 2;
            if (mb < Cout)
                *(float2*)(out + ((size_t)b * Cout + mb) * HWSZ + nn) =
                    make_float2(acc[mf][nb][0] * osc, acc[mf][nb][1] * osc);
            if (mb + 8 < Cout)
                *(float2*)(out + ((size_t)b * Cout + mb + 8) * HWSZ + nn) =
                    make_float2(acc[mf][nb][2] * osc, acc[mf][nb][3] * osc);
        }
    }
}

// ---------------------------------------------------------------------------
// depthwise 3x3, float4 vectorized
// ---------------------------------------------------------------------------
__global__ __launch_bounds__(256) void dwconv3_kernel(
    const float* __restrict__ in, const float* __restrict__ wdw,
    float* __restrict__ out) {
    int c = blockIdx.y, b = blockIdx.z;
    int p4 = (blockIdx.x * 256 + threadIdx.x) * 4;
    int y = p4 >> 7, x = p4 & 127;
    const float* src = in + ((size_t)b * (3 * CDIM) + c) * HWSZ;
    float w[9];
#pragma unroll
    for (int i = 0; i < 9; i++) w[i] = wdw[c * 9 + i];
    float4 a = make_float4(0.f, 0.f, 0.f, 0.f);
#pragma unroll
    for (int r = -1; r <= 1; r++) {
        int yy = y + r;
        if ((unsigned)yy >= 128u) continue;
        const float* rp = src + (yy << 7);
        float4 m = *(const float4*)(rp + x);
        float L = (x > 0) ? rp[x - 1] : 0.f;
        float R = (x + 4 < 128) ? rp[x + 4] : 0.f;
        int wb = (r + 1) * 3;
        a.x = fmaf(w[wb], L,   fmaf(w[wb + 1], m.x, fmaf(w[wb + 2], m.y, a.x)));
        a.y = fmaf(w[wb], m.x, fmaf(w[wb + 1], m.y, fmaf(w[wb + 2], m.z, a.y)));
        a.z = fmaf(w[wb], m.y, fmaf(w[wb + 1], m.z, fmaf(w[wb + 2], m.w, a.z)));
        a.w = fmaf(w[wb], m.z, fmaf(w[wb + 1], m.w, fmaf(w[wb + 2], R,   a.w)));
    }
    *(float4*)(out + ((size_t)b * (3 * CDIM) + c) * HWSZ + p4) = a;
}

// ---------------------------------------------------------------------------
// per-row norms -> normalization coefficients
// ---------------------------------------------------------------------------
__global__ __launch_bounds__(256) void stats_kernel(
    const float* __restrict__ qkv, const float* __restrict__ cnf,
    float* __restrict__ coef) {
    int rowi = blockIdx.x;
    int b = rowi / CDIM, c = rowi % CDIM;
    const float* q  = qkv + ((size_t)b * (3 * CDIM) + c) * HWSZ;
    const float* kk = qkv + ((size_t)b * (3 * CDIM) + CDIM + c) * HWSZ;
    const float* cn = cnf + (size_t)rowi * HWSZ;
    float sq = 0.f, sk = 0.f, sc = 0.f, sqc = 0.f;
    for (int i = threadIdx.x; i < HWSZ; i += 256) {
        float qv = q[i], kv = kk[i], cv = cn[i];
        sq = fmaf(qv, qv, sq); sk = fmaf(kv, kv, sk);
        sc = fmaf(cv, cv, sc); sqc = fmaf(qv, cv, sqc);
    }
#pragma unroll
    for (int o = 16; o; o >>= 1) {
        sq += __shfl_xor_sync(~0u, sq, o); sk += __shfl_xor_sync(~0u, sk, o);
        sc += __shfl_xor_sync(~0u, sc, o); sqc += __shfl_xor_sync(~0u, sqc, o);
    }
    __shared__ float r4[4][8];
    int wid = threadIdx.x >> 5, lane = threadIdx.x & 31;
    if (lane == 0) { r4[0][wid] = sq; r4[1][wid] = sk; r4[2][wid] = sc; r4[3][wid] = sqc; }
    __syncthreads();
    if (threadIdx.x == 0) {
        float SQ = 0, SK = 0, SC = 0, SQC = 0;
        for (int i = 0; i < 8; i++) { SQ += r4[0][i]; SK += r4[1][i]; SC += r4[2][i]; SQC += r4[3][i]; }
        float a  = fmaxf(sqrtf(SQ), EPSN);
        float bb = fmaxf(sqrtf(SC), EPSN);
        float s2 = SQ / (a * a) + 2.f * SQC / (a * bb) + SC / (bb * bb);
        float s  = fmaxf(sqrtf(s2), EPSN);
        float kn = fmaxf(sqrtf(SK), EPSN);
        coef[rowi * 3 + 0] = 1.f / (a * s);
        coef[rowi * 3 + 1] = 1.f / (bb * s);
        coef[rowi * 3 + 2] = 1.f / kn;
    }
}

// ---------------------------------------------------------------------------
// gram / softmax / apply
// ---------------------------------------------------------------------------
__global__ __launch_bounds__(256) void gram_kernel(
    const float* __restrict__ qkv, const float* __restrict__ cnf,
    const float* __restrict__ coef, float* __restrict__ gpart) {
    __shared__ float SQ[48][33];
    __shared__ float SK[48][33];
    __shared__ float al[48], be[48], ga[48];
    int bh = blockIdx.x, sp = blockIdx.y;
    int b = bh >> 2, h = bh & 3;
    int tid = threadIdx.x, tx = tid & 15, ty = tid >> 4;
    if (tid < 48) {
        int rw = b * CDIM + h * CHD + tid;
        al[tid] = coef[rw * 3 + 0]; be[tid] = coef[rw * 3 + 1]; ga[tid] = coef[rw * 3 + 2];
    }
    __syncthreads();
    const float* qb = qkv + ((size_t)b * (3 * CDIM) + h * CHD) * HWSZ;
    const float* kb = qkv + ((size_t)b * (3 * CDIM) + CDIM + h * CHD) * HWSZ;
    const float* cb = cnf + ((size_t)b * CDIM + h * CHD) * HWSZ;
    float acc[3][3] = {};
    int send = sp * 2048 + 2048;
    for (int s0 = sp * 2048; s0 < send; s0 += 32) {
        for (int e = tid; e < 1536; e += 256) {
            int r = e >> 5, s = e & 31;
            int off = r * HWSZ + s0 + s;
            SQ[r][s] = al[r] * qb[off] + be[r] * cb[off];
            SK[r][s] = ga[r] * kb[off];
        }
        __syncthreads();
#pragma unroll 4
        for (int s = 0; s < 32; s++) {
            float qa[3], kv[3];
#pragma unroll
            for (int i = 0; i < 3; i++) qa[i] = SQ[tx + 16 * i][s];
#pragma unroll
            for (int j = 0; j < 3; j++) kv[j] = SK[ty + 16 * j][s];
#pragma unroll
            for (int i = 0; i < 3; i++)
#pragma unroll
                for (int j = 0; j < 3; j++)
                    acc[i][j] = fmaf(qa[i], kv[j], acc[i][j]);
        }
        __syncthreads();
    }
#pragma unroll
    for (int i = 0; i < 3; i++)
#pragma unroll
        for (int j = 0; j < 3; j++)
            gpart[((bh * SPLIT + sp) * CHD + tx + 16 * i) * CHD + ty + 16 * j] = acc[i][j];
}

__global__ __launch_bounds__(256) void softmax_kernel(
    const float* __restrict__ gpart, const float* __restrict__ temp,
    float* __restrict__ attn) {
    __shared__ float S[48][49];
    int bh = blockIdx.x;
    float T = temp[bh & 3];
    int tid = threadIdx.x;
    for (int e = tid; e < CHD * CHD; e += 256) {
        int c = e / CHD, d = e - c * CHD;
        float g = 0.f;
#pragma unroll
        for (int sp = 0; sp < SPLIT; sp++)
            g += gpart[((bh * SPLIT + sp) * CHD + c) * CHD + d];
        S[c][d] = g * T;
    }
    __syncthreads();
    int wid = tid >> 5, lane = tid & 31;
    for (int r = wid; r < 48; r += 8) {
        float v1 = S[r][lane];
        float v2 = (lane < 16) ? S[r][32 + lane] : -1e30f;
        float m = fmaxf(v1, v2);
#pragma unroll
        for (int o = 16; o; o >>= 1) m = fmaxf(m, __shfl_xor_sync(~0u, m, o));
        float e1 = expf(v1 - m);
        float e2 = (lane < 16) ? expf(v2 - m) : 0.f;
        float s = e1 + e2;
#pragma unroll
        for (int o = 16; o; o >>= 1) s += __shfl_xor_sync(~0u, s, o);
        float inv = 1.f / s;
        attn[bh * (CHD * CHD) + r * CHD + lane] = e1 * inv;
        if (lane < 16) attn[bh * (CHD * CHD) + r * CHD + 32 + lane] = e2 * inv;
    }
}

// attn @ v, fused with bf16 hi/lo split (feeds proj GEMM directly)
__global__ __launch_bounds__(256) void apply_kernel(
    const float* __restrict__ qkv, const float* __restrict__ attn,
    __nv_bfloat16* __restrict__ oh, __nv_bfloat16* __restrict__ ol) {
    __shared__ float A[48][48];
    int b = blockIdx.z, h = blockIdx.y;
    int tid = threadIdx.x;
    for (int e = tid; e < CHD * CHD; e += 256)
        A[e / CHD][e % CHD] = attn[(b * NHEAD + h) * (CHD * CHD) + e];
    __syncthreads();
    int p = blockIdx.x * 512 + tid;
    const float* vb = qkv + ((size_t)b * (3 * CDIM) + 2 * CDIM + h * CHD) * HWSZ;
    float a0[48], a1[48];
#pragma unroll
    for (int c = 0; c < 48; c++) { a0[c] = 0.f; a1[c] = 0.f; }
#pragma unroll 2
    for (int d = 0; d < 48; d++) {
        float v0 = vb[d * HWSZ + p];
        float v1 = vb[d * HWSZ + p + 256];
#pragma unroll
        for (int c = 0; c < 48; c++) {
            float a = A[c][d];
            a0[c] = fmaf(a, v0, a0[c]);
            a1[c] = fmaf(a, v1, a1[c]);
        }
    }
    size_t ob = ((size_t)b * CDIM + h * CHD) * HWSZ;
#pragma unroll
    for (int c = 0; c < 48; c++) {
        __nv_bfloat16 hh, ll;
        splitbf(a0[c], hh, ll);
        oh[ob + c * HWSZ + p] = hh; ol[ob + c * HWSZ + p] = ll;
        splitbf(a1[c], hh, ll);
        oh[ob + c * HWSZ + p + 256] = hh; ol[ob + c * HWSZ + p + 256] = ll;
    }
}

// ---------------------------------------------------------------------------
// launch
// ---------------------------------------------------------------------------
constexpr int SMEM_CONV = 2 * 49152 + 128;   // 2-stage fp16, 2 CTAs/SM
constexpr int SMEM_PW   = 3 * 65536 + 128;   // 3-stage bf16, 1 CTA/SM

extern "C" void kernel_launch(void* const* d_in, const int* in_sizes, int n_in,
                              void* d_out, int out_size) {
    const float* x     = (const float*)d_in[0];
    const float* cn    = (const float*)d_in[1];
    const float* w1    = (const float*)d_in[2];
    const float* w3    = (const float*)d_in[3];
    const float* qkvw  = (const float*)d_in[4];
    const float* dww   = (const float*)d_in[5];
    const float* projw = (const float*)d_in[6];
    const float* temp  = (const float*)d_in[7];

    __half *wch, *wcl, *ch, *chL, *chR;
    __nv_bfloat16 *wqh, *wql, *wph, *wpl, *xh, *xl;
    float *cnf, *qkv1, *qkv2, *coef, *gpart, *attn;
    cudaGetSymbolAddress((void**)&wch, g_wc_h);  cudaGetSymbolAddress((void**)&wcl, g_wc_l);
    cudaGetSymbolAddress((void**)&wqh, g_wq_h);  cudaGetSymbolAddress((void**)&wql, g_wq_l);
    cudaGetSymbolAddress((void**)&wph, g_wp_h);  cudaGetSymbolAddress((void**)&wpl, g_wp_l);
    cudaGetSymbolAddress((void**)&ch,  g_ch);
    cudaGetSymbolAddress((void**)&chL, g_chL);
    cudaGetSymbolAddress((void**)&chR, g_chR);
    cudaGetSymbolAddress((void**)&xh,  g_xh);    cudaGetSymbolAddress((void**)&xl,  g_xl);
    cudaGetSymbolAddress((void**)&cnf,  g_cnf);
    cudaGetSymbolAddress((void**)&qkv1, g_qkv1);
    cudaGetSymbolAddress((void**)&qkv2, g_qkv);
    cudaGetSymbolAddress((void**)&coef, g_coef);
    cudaGetSymbolAddress((void**)&gpart, g_gpart);
    cudaGetSymbolAddress((void**)&attn, g_attn);

    cudaFuncSetAttribute(mm_kernel<1728, 9, 2, 2, __half>,
                         cudaFuncAttributeMaxDynamicSharedMemorySize, SMEM_CONV);
    cudaFuncSetAttribute(mm_kernel<192, 1, 3, 1, __nv_bfloat16>,
                         cudaFuncAttributeMaxDynamicSharedMemorySize, SMEM_PW);

    const int NACT4 = BATCH * CDIM * HWSZ / 4;

    // weight prep
    foldw_kernel<<<256 * 1728 / 256, 256>>>(w3, w1, wch, wcl);
    splitw_kernel<<<640 * 192 / 256, 256>>>(qkvw, wqh, wql, 3 * CDIM);
    splitw_kernel<<<256 * 192 / 256, 256>>>(projw, wph, wpl, CDIM);

    // cn branch: fp16 + shifted copies, folded 3x3 conv (fp16 2-term HMMA)
    asplit_shift_h_kernel<<<(NACT4 + 255) / 256, 256>>>(cn, ch, chL, chR, NACT4);
    mm_kernel<1728, 9, 2, 2, __half><<<dim3(128, 2, BATCH), 256, SMEM_CONV>>>(
        ch, ch, chL, chL, chR, chR, wch, wcl, cnf, CDIM);

    // qkv 1x1 (bf16 3-term HMMA)
    asplit_kernel<<<(NACT4 + 255) / 256, 256>>>(x, xh, xl, NACT4);
    mm_kernel<192, 1, 3, 1, __nv_bfloat16><<<dim3(128, 5, BATCH), 256, SMEM_PW>>>(
        xh, xl, xh, xl, xh, xl, wqh, wql, qkv1, 3 * CDIM);

    // depthwise 3x3
    dwconv3_kernel<<<dim3(HWSZ / 1024, 3 * CDIM, BATCH), 256>>>(qkv1, dww, qkv2);

    // attention chain
    stats_kernel<<<BATCH * CDIM, 256>>>(qkv2, cnf, coef);
    gram_kernel<<<dim3(BATCH * NHEAD, SPLIT), 256>>>(qkv2, cnf, coef, gpart);
    softmax_kernel<<<BATCH * NHEAD, 256>>>(gpart, temp, attn);
    apply_kernel<<<dim3(32, NHEAD, BATCH), 256>>>(qkv2, attn, xh, xl);

    // projection 1x1 (bf16 3-term HMMA; reads bf16 hi/lo written by apply)
    mm_kernel<192, 1, 3, 1, __nv_bfloat16><<<dim3(128, 2, BATCH), 256, SMEM_PW>>>(
        xh, xl, xh, xl, xh, xl, wph, wpl, (float*)d_out, CDIM);
}

// round 7
// speedup vs baseline: 6.2311x; 1.2831x over previous
#include <cuda_runtime.h>
#include <cuda_bf16.h>
#include <cuda_fp16.h>
#include <cstdint>

#define EPSN 1e-12f

constexpr int BATCH = 8;
constexpr int CDIM  = 192;
constexpr int HWSZ  = 16384;   // 128*128
constexpr int NHEAD = 4;
constexpr int CHD   = 48;
constexpr int SPLIT = 8;
constexpr float WSC  = 64.f;        // weight pre-scale (keeps fp16 lo-part normal)
constexpr float IWSC = 1.f / 64.f;

// ---------------------------------------------------------------------------
// helpers
// ---------------------------------------------------------------------------
__device__ __forceinline__ uint32_t s2u(const void* p) {
    uint32_t a;
    asm("{ .reg .u64 t; cvta.to.shared.u64 t, %1; cvt.u32.u64 %0, t; }" : "=r"(a) : "l"(p));
    return a;
}
#define SWZ(x) ((x) ^ (((x) >> 3) & 0x70))

__device__ __forceinline__ void cpa16(uint32_t dst, const void* src, int srcsize) {
    asm volatile("cp.async.cg.shared.global [%0], [%1], 16, %2;"
                 :: "r"(dst), "l"(src), "r"(srcsize));
}
#define CPA_COMMIT() asm volatile("cp.async.commit_group;" ::: "memory")
#define CPA_WAIT(n)  asm volatile("cp.async.wait_group %0;" :: "n"(n) : "memory")

__device__ __forceinline__ void ldsm4(uint32_t* r, uint32_t addr) {
    asm volatile("ldmatrix.sync.aligned.m8n8.x4.shared.b16 {%0,%1,%2,%3}, [%4];"
        : "=r"(r[0]), "=r"(r[1]), "=r"(r[2]), "=r"(r[3]) : "r"(addr));
}
__device__ __forceinline__ void ldsm4t(uint32_t* r, uint32_t addr) {
    asm volatile("ldmatrix.sync.aligned.m8n8.x4.trans.shared.b16 {%0,%1,%2,%3}, [%4];"
        : "=r"(r[0]), "=r"(r[1]), "=r"(r[2]), "=r"(r[3]) : "r"(addr));
}
__device__ __forceinline__ void mma16816h(float* d, const uint32_t* a, const uint32_t* b) {
    asm volatile("mma.sync.aligned.m16n8k16.row.col.f32.f16.f16.f32 "
        "{%0,%1,%2,%3}, {%4,%5,%6,%7}, {%8,%9}, {%0,%1,%2,%3};"
        : "+f"(d[0]), "+f"(d[1]), "+f"(d[2]), "+f"(d[3])
        : "r"(a[0]), "r"(a[1]), "r"(a[2]), "r"(a[3]), "r"(b[0]), "r"(b[1]));
}

__device__ __forceinline__ uint32_t pack2h(__half a, __half b) {
    return (uint32_t)__half_as_ushort(a) | ((uint32_t)__half_as_ushort(b) << 16);
}

// ---------------------------------------------------------------------------
// scratch buffers
// ---------------------------------------------------------------------------
__device__ __half g_wc[256 * 1728];                     // folded 3x3, fp16, x64 (1-term)
__device__ __half g_wq_h[640 * 192], g_wq_l[640 * 192]; // qkv 1x1 fp16 hi/lo, x64
__device__ __half g_wp_h[256 * 192], g_wp_l[256 * 192]; // proj 1x1 fp16 hi/lo, x64
__device__ __half g_ch [(size_t)BATCH * CDIM * HWSZ];   // cn fp16 (center)
__device__ __half g_chL[(size_t)BATCH * CDIM * HWSZ];   // cn fp16 [p]=x[p+1]
__device__ __half g_chR[(size_t)BATCH * CDIM * HWSZ];   // cn fp16 [p]=x[p-1]
__device__ __half g_x16[(size_t)BATCH * CDIM * HWSZ];   // x fp16, later reused for av
__device__ float g_cnf[(size_t)BATCH * CDIM * HWSZ];
__device__ float g_qkv1[(size_t)BATCH * 3 * CDIM * HWSZ];
__device__ float g_qkv[(size_t)BATCH * 3 * CDIM * HWSZ];
__device__ float g_coef[BATCH * CDIM * 3];
__device__ float g_gpart[BATCH * NHEAD * SPLIT * CHD * CHD];
__device__ float g_attn[BATCH * NHEAD * CHD * CHD];

// ---------------------------------------------------------------------------
// weight prep
// ---------------------------------------------------------------------------
// fold 1x1 into 3x3 (k = t*192+cj), scale x64, single fp16
__global__ void foldw_kernel(const float* __restrict__ w3, const float* __restrict__ w1,
                             __half* __restrict__ w) {
    int idx = blockIdx.x * 256 + threadIdx.x;          // 256*1728
    int co = idx / 1728, r = idx % 1728;
    int t = r / 192, cj = r % 192;
    float s = 0.f;
    if (co < CDIM)
        for (int ci = 0; ci < CDIM; ci++)
            s = fmaf(w3[(co * CDIM + ci) * 9 + t], w1[ci * CDIM + cj], s);
    w[idx] = __float2half(s * WSC);
}

// 1x1 weights: scale x64, fp16 hi/lo split
__global__ void splitw_kernel(const float* __restrict__ w, __half* __restrict__ wh,
                              __half* __restrict__ wl, int validRows) {
    int idx = blockIdx.x * 256 + threadIdx.x;
    int row = idx / CDIM;
    float v = (row < validRows) ? w[(size_t)row * CDIM + (idx % CDIM)] * WSC : 0.f;
    __half h = __float2half(v);
    wh[idx] = h;
    wl[idx] = __float2half(v - __half2float(h));
}

// elementwise fp32 -> fp16
__global__ __launch_bounds__(256) void ahalf_kernel(
    const float* __restrict__ in, __half* __restrict__ o, int n4) {
    int i = blockIdx.x * 256 + threadIdx.x;
    if (i >= n4) return;
    float4 v = ((const float4*)in)[i];
    ((uint2*)o)[i] = make_uint2(pack2h(__float2half(v.x), __float2half(v.y)),
                                pack2h(__float2half(v.z), __float2half(v.w)));
}

// fp32 -> fp16, center + left/right shifted copies (row-edge zeroed)
__global__ __launch_bounds__(256) void asplit_shift_h_kernel(
    const float* __restrict__ in,
    __half* __restrict__ oh, __half* __restrict__ ohL, __half* __restrict__ ohR, int n4) {
    int i = blockIdx.x * 256 + threadIdx.x;
    if (i >= n4) return;
    int p = i * 4;
    int col = p & 127;
    float4 v = ((const float4*)in)[i];
    float vnext = (col == 124) ? 0.f : in[p + 4];
    float vprev = (col == 0)   ? 0.f : in[p - 1];
    __half h0 = __float2half(v.x), h1 = __float2half(v.y);
    __half h2 = __float2half(v.z), h3 = __float2half(v.w);
    __half hn = __float2half(vnext), hp = __float2half(vprev);
    ((uint2*)oh)[i]  = make_uint2(pack2h(h0, h1), pack2h(h2, h3));
    ((uint2*)ohL)[i] = make_uint2(pack2h(h1, h2), pack2h(h3, hn));
    ((uint2*)ohR)[i] = make_uint2(pack2h(hp, h0), pack2h(h1, h2));
}

// ---------------------------------------------------------------------------
// fp16 HMMA GEMM, multi-stage cp.async pipeline. CTA 128m x 128n, K-chunk 64.
//   TERMS==1: C = A B              (stage 32KB: A 0 | B 16K),        3 stages
//   TERMS==2: C = Ah B + Al B      (stage 48KB: Ah 0 | Al 16K | B 32K), 2 stages
//   Weights pre-scaled x64; epilogue multiplies 1/64. fp32 accum.
//   TAPS=9: implicit im2col (k = t*192+ci); x-shift via pre-shifted arrays.
// ---------------------------------------------------------------------------
template <int KTOT, int TAPS, int TERMS, int MINB>
__global__ __launch_bounds__(256, MINB) void mm_kernel(
    const __half* __restrict__ xc, const __half* __restrict__ xL,
    const __half* __restrict__ xR,
    const __half* __restrict__ wh, const __half* __restrict__ wl,
    float* __restrict__ out, int Cout) {
    constexpr int SSZ    = (TERMS == 2) ? 49152 : 32768;
    constexpr int STAGES = (TERMS == 2) ? 2 : 3;
    constexpr int BOFF   = (TERMS == 2) ? 32768 : 16384;
    extern __shared__ char sraw[];
    char* sal = (char*)((((uintptr_t)sraw) + 127) & ~(uintptr_t)127);
    const uint32_t sb = s2u(sal);
    const int tid = threadIdx.x, lane = tid & 31, wid = tid >> 5;
    const int n0 = blockIdx.x * 128, m0 = blockIdx.y * 128, b = blockIdx.z;
    const int wm = wid >> 1, wn = wid & 1;
    const int y = n0 >> 7;
    const int lr = lane & 15, lc = lane >> 4;
    constexpr int NCH = KTOT / 64;

    auto load_chunk = [&](int cc) {
        const int k0 = cc * 64;
        const int t = (TAPS == 9) ? (k0 / 192) : 0;
        const int ci0 = k0 - t * 192;
        const int dy = (TAPS == 9) ? (t / 3 - 1) : 0;
        const int dx = (TAPS == 9) ? (t % 3 - 1) : 0;
        const int yy = y + dy;
        const bool rowok = (TAPS == 1) || ((unsigned)yy < 128u);
        const int ys = rowok ? yy : y;
        const uint32_t stg = sb + (uint32_t)(cc % STAGES) * SSZ;
        // A (weights): TERMS buffers of 16KB
#pragma unroll
        for (int i = 0; i < 4 * TERMS; i++) {
            int e = tid + (i << 8);
            int ck = e & 7, r = (e >> 3) & 127, dt = e >> 10;
            const __half* src = (dt ? wl : wh) + (size_t)(m0 + r) * KTOT + k0 + ck * 8;
            cpa16(stg + dt * 16384 + SWZ(r * 128 + ck * 16), src, 16);
        }
        // B (activations): single fp16 buffer
        const __half* bp = (dx == 0) ? xc : (dx > 0 ? xL : xR);
        const int sz = rowok ? 16 : 0;
#pragma unroll
        for (int i = 0; i < 4; i++) {
            int e = tid + (i << 8);
            int nc = e & 15, k = (e >> 4) & 63;
            int n = nc * 8;
            const __half* src = bp + ((size_t)b * CDIM + ci0 + k) * HWSZ + ys * 128 + n;
            cpa16(stg + BOFF + (nc >> 3) * 8192 + SWZ(k * 128 + (n & 63) * 2), src, sz);
        }
        CPA_COMMIT();
    };

    float acc[2][8][4];
#pragma unroll
    for (int i = 0; i < 2; i++)
#pragma unroll
        for (int j = 0; j < 8; j++)
#pragma unroll
            for (int q = 0; q < 4; q++) acc[i][j][q] = 0.f;

#pragma unroll
    for (int i = 0; i < STAGES - 1 && i < NCH; i++) load_chunk(i);

    for (int cc = 0; cc < NCH; cc++) {
        if (cc + STAGES - 1 < NCH) load_chunk(cc + STAGES - 1);
        int pend = ((cc + STAGES - 1 < NCH) ? (STAGES - 1) : (NCH - 1 - cc));
        if (pend >= 2)      CPA_WAIT(2);
        else if (pend == 1) CPA_WAIT(1);
        else                CPA_WAIT(0);
        __syncthreads();
        const uint32_t stg = sb + (uint32_t)(cc % STAGES) * SSZ;

#pragma unroll
        for (int ks = 0; ks < 4; ks++) {
            uint32_t ah[2][4], alo[2][4];
#pragma unroll
            for (int mf = 0; mf < 2; mf++) {
                uint32_t ao = SWZ((wm * 32 + mf * 16 + lr) * 128 + ks * 32 + lc * 16);
                ldsm4(ah[mf], stg + ao);
                if (TERMS == 2) ldsm4(alo[mf], stg + 16384 + ao);
            }
#pragma unroll
            for (int g = 0; g < 4; g++) {
                uint32_t bh[4];
                uint32_t bo = BOFF + wn * 8192 + SWZ((ks * 16 + lr) * 128 + g * 32 + lc * 16);
                ldsm4t(bh, stg + bo);
#pragma unroll
                for (int mf = 0; mf < 2; mf++) {
                    mma16816h(acc[mf][2 * g],     ah[mf], bh);
                    mma16816h(acc[mf][2 * g + 1], ah[mf], bh + 2);
                    if (TERMS == 2) {
                        mma16816h(acc[mf][2 * g],     alo[mf], bh);
                        mma16816h(acc[mf][2 * g + 1], alo[mf], bh + 2);
                    }
                }
            }
        }
        __syncthreads();
    }

    // ---- epilogue (undo weight pre-scale)
#pragma unroll
    for (int mf = 0; mf < 2; mf++) {
        int mb = m0 + wm * 32 + mf * 16 + (lane >> 2);
#pragma unroll
        for (int nb = 0; nb < 8; nb++) {
            int nn = n0 + wn * 64 + nb * 8 + (lane & 3) * 2;
            if (mb < Cout)
                *(float2*)(out + ((size_t)b * Cout + mb) * HWSZ + nn) =
                    make_float2(acc[mf][nb][0] * IWSC, acc[mf][nb][1] * IWSC);
            if (mb + 8 < Cout)
                *(float2*)(out + ((size_t)b * Cout + mb + 8) * HWSZ + nn) =
                    make_float2(acc[mf][nb][2] * IWSC, acc[mf][nb][3] * IWSC);
        }
    }
}

// ---------------------------------------------------------------------------
// depthwise 3x3, float4 vectorized
// ---------------------------------------------------------------------------
__global__ __launch_bounds__(256) void dwconv3_kernel(
    const float* __restrict__ in, const float* __restrict__ wdw,
    float* __restrict__ out) {
    int c = blockIdx.y, b = blockIdx.z;
    int p4 = (blockIdx.x * 256 + threadIdx.x) * 4;
    int y = p4 >> 7, x = p4 & 127;
    const float* src = in + ((size_t)b * (3 * CDIM) + c) * HWSZ;
    float w[9];
#pragma unroll
    for (int i = 0; i < 9; i++) w[i] = wdw[c * 9 + i];
    float4 a = make_float4(0.f, 0.f, 0.f, 0.f);
#pragma unroll
    for (int r = -1; r <= 1; r++) {
        int yy = y + r;
        if ((unsigned)yy >= 128u) continue;
        const float* rp = src + (yy << 7);
        float4 m = *(const float4*)(rp + x);
        float L = (x > 0) ? rp[x - 1] : 0.f;
        float R = (x + 4 < 128) ? rp[x + 4] : 0.f;
        int wb = (r + 1) * 3;
        a.x = fmaf(w[wb], L,   fmaf(w[wb + 1], m.x, fmaf(w[wb + 2], m.y, a.x)));
        a.y = fmaf(w[wb], m.x, fmaf(w[wb + 1], m.y, fmaf(w[wb + 2], m.z, a.y)));
        a.z = fmaf(w[wb], m.y, fmaf(w[wb + 1], m.z, fmaf(w[wb + 2], m.w, a.z)));
        a.w = fmaf(w[wb], m.z, fmaf(w[wb + 1], m.w, fmaf(w[wb + 2], R,   a.w)));
    }
    *(float4*)(out + ((size_t)b * (3 * CDIM) + c) * HWSZ + p4) = a;
}

// ---------------------------------------------------------------------------
// per-row norms -> normalization coefficients
// ---------------------------------------------------------------------------
__global__ __launch_bounds__(256) void stats_kernel(
    const float* __restrict__ qkv, const float* __restrict__ cnf,
    float* __restrict__ coef) {
    int rowi = blockIdx.x;
    int b = rowi / CDIM, c = rowi % CDIM;
    const float* q  = qkv + ((size_t)b * (3 * CDIM) + c) * HWSZ;
    const float* kk = qkv + ((size_t)b * (3 * CDIM) + CDIM + c) * HWSZ;
    const float* cn = cnf + (size_t)rowi * HWSZ;
    float sq = 0.f, sk = 0.f, sc = 0.f, sqc = 0.f;
    for (int i = threadIdx.x; i < HWSZ; i += 256) {
        float qv = q[i], kv = kk[i], cv = cn[i];
        sq = fmaf(qv, qv, sq); sk = fmaf(kv, kv, sk);
        sc = fmaf(cv, cv, sc); sqc = fmaf(qv, cv, sqc);
    }
#pragma unroll
    for (int o = 16; o; o >>= 1) {
        sq += __shfl_xor_sync(~0u, sq, o); sk += __shfl_xor_sync(~0u, sk, o);
        sc += __shfl_xor_sync(~0u, sc, o); sqc += __shfl_xor_sync(~0u, sqc, o);
    }
    __shared__ float r4[4][8];
    int wid = threadIdx.x >> 5, lane = threadIdx.x & 31;
    if (lane == 0) { r4[0][wid] = sq; r4[1][wid] = sk; r4[2][wid] = sc; r4[3][wid] = sqc; }
    __syncthreads();
    if (threadIdx.x == 0) {
        float SQ = 0, SK = 0, SC = 0, SQC = 0;
        for (int i = 0; i < 8; i++) { SQ += r4[0][i]; SK += r4[1][i]; SC += r4[2][i]; SQC += r4[3][i]; }
        float a  = fmaxf(sqrtf(SQ), EPSN);
        float bb = fmaxf(sqrtf(SC), EPSN);
        float s2 = SQ / (a * a) + 2.f * SQC / (a * bb) + SC / (bb * bb);
        float s  = fmaxf(sqrtf(s2), EPSN);
        float kn = fmaxf(sqrtf(SK), EPSN);
        coef[rowi * 3 + 0] = 1.f / (a * s);
        coef[rowi * 3 + 1] = 1.f / (bb * s);
        coef[rowi * 3 + 2] = 1.f / kn;
    }
}

// ---------------------------------------------------------------------------
// gram / softmax / apply
// ---------------------------------------------------------------------------
__global__ __launch_bounds__(256) void gram_kernel(
    const float* __restrict__ qkv, const float* __restrict__ cnf,
    const float* __restrict__ coef, float* __restrict__ gpart) {
    __shared__ float SQ[48][33];
    __shared__ float SK[48][33];
    __shared__ float al[48], be[48], ga[48];
    int bh = blockIdx.x, sp = blockIdx.y;
    int b = bh >> 2, h = bh & 3;
    int tid = threadIdx.x, tx = tid & 15, ty = tid >> 4;
    if (tid < 48) {
        int rw = b * CDIM + h * CHD + tid;
        al[tid] = coef[rw * 3 + 0]; be[tid] = coef[rw * 3 + 1]; ga[tid] = coef[rw * 3 + 2];
    }
    __syncthreads();
    const float* qb = qkv + ((size_t)b * (3 * CDIM) + h * CHD) * HWSZ;
    const float* kb = qkv + ((size_t)b * (3 * CDIM) + CDIM + h * CHD) * HWSZ;
    const float* cb = cnf + ((size_t)b * CDIM + h * CHD) * HWSZ;
    float acc[3][3] = {};
    int send = sp * 2048 + 2048;
    for (int s0 = sp * 2048; s0 < send; s0 += 32) {
        for (int e = tid; e < 1536; e += 256) {
            int r = e >> 5, s = e & 31;
            int off = r * HWSZ + s0 + s;
            SQ[r][s] = al[r] * qb[off] + be[r] * cb[off];
            SK[r][s] = ga[r] * kb[off];
        }
        __syncthreads();
#pragma unroll 4
        for (int s = 0; s < 32; s++) {
            float qa[3], kv[3];
#pragma unroll
            for (int i = 0; i < 3; i++) qa[i] = SQ[tx + 16 * i][s];
#pragma unroll
            for (int j = 0; j < 3; j++) kv[j] = SK[ty + 16 * j][s];
#pragma unroll
            for (int i = 0; i < 3; i++)
#pragma unroll
                for (int j = 0; j < 3; j++)
                    acc[i][j] = fmaf(qa[i], kv[j], acc[i][j]);
        }
        __syncthreads();
    }
#pragma unroll
    for (int i = 0; i < 3; i++)
#pragma unroll
        for (int j = 0; j < 3; j++)
            gpart[((bh * SPLIT + sp) * CHD + tx + 16 * i) * CHD + ty + 16 * j] = acc[i][j];
}

__global__ __launch_bounds__(256) void softmax_kernel(
    const float* __restrict__ gpart, const float* __restrict__ temp,
    float* __restrict__ attn) {
    __shared__ float S[48][49];
    int bh = blockIdx.x;
    float T = temp[bh & 3];
    int tid = threadIdx.x;
    for (int e = tid; e < CHD * CHD; e += 256) {
        int c = e / CHD, d = e - c * CHD;
        float g = 0.f;
#pragma unroll
        for (int sp = 0; sp < SPLIT; sp++)
            g += gpart[((bh * SPLIT + sp) * CHD + c) * CHD + d];
        S[c][d] = g * T;
    }
    __syncthreads();
    int wid = tid >> 5, lane = tid & 31;
    for (int r = wid; r < 48; r += 8) {
        float v1 = S[r][lane];
        float v2 = (lane < 16) ? S[r][32 + lane] : -1e30f;
        float m = fmaxf(v1, v2);
#pragma unroll
        for (int o = 16; o; o >>= 1) m = fmaxf(m, __shfl_xor_sync(~0u, m, o));
        float e1 = expf(v1 - m);
        float e2 = (lane < 16) ? expf(v2 - m) : 0.f;
        float s = e1 + e2;
#pragma unroll
        for (int o = 16; o; o >>= 1) s += __shfl_xor_sync(~0u, s, o);
        float inv = 1.f / s;
        attn[bh * (CHD * CHD) + r * CHD + lane] = e1 * inv;
        if (lane < 16) attn[bh * (CHD * CHD) + r * CHD + 32 + lane] = e2 * inv;
    }
}

// attn @ v, writes single fp16 (feeds proj GEMM)
__global__ __launch_bounds__(256) void apply_kernel(
    const float* __restrict__ qkv, const float* __restrict__ attn,
    __half* __restrict__ o16) {
    __shared__ float A[48][48];
    int b = blockIdx.z, h = blockIdx.y;
    int tid = threadIdx.x;
    for (int e = tid; e < CHD * CHD; e += 256)
        A[e / CHD][e % CHD] = attn[(b * NHEAD + h) * (CHD * CHD) + e];
    __syncthreads();
    int p = blockIdx.x * 512 + tid;
    const float* vb = qkv + ((size_t)b * (3 * CDIM) + 2 * CDIM + h * CHD) * HWSZ;
    float a0[48], a1[48];
#pragma unroll
    for (int c = 0; c < 48; c++) { a0[c] = 0.f; a1[c] = 0.f; }
#pragma unroll 2
    for (int d = 0; d < 48; d++) {
        float v0 = vb[d * HWSZ + p];
        float v1 = vb[d * HWSZ + p + 256];
#pragma unroll
        for (int c = 0; c < 48; c++) {
            float a = A[c][d];
            a0[c] = fmaf(a, v0, a0[c]);
            a1[c] = fmaf(a, v1, a1[c]);
        }
    }
    size_t ob = ((size_t)b * CDIM + h * CHD) * HWSZ;
#pragma unroll
    for (int c = 0; c < 48; c++) {
        o16[ob + c * HWSZ + p]       = __float2half(a0[c]);
        o16[ob + c * HWSZ + p + 256] = __float2half(a1[c]);
    }
}

// ---------------------------------------------------------------------------
// launch
// ---------------------------------------------------------------------------
constexpr int SMEM_CONV = 3 * 32768 + 128;   // 1-term, 3 stages, 2 CTAs/SM
constexpr int SMEM_PW   = 2 * 49152 + 128;   // 2-term, 2 stages, 2 CTAs/SM

extern "C" void kernel_launch(void* const* d_in, const int* in_sizes, int n_in,
                              void* d_out, int out_size) {
    const float* x     = (const float*)d_in[0];
    const float* cn    = (const float*)d_in[1];
    const float* w1    = (const float*)d_in[2];
    const float* w3    = (const float*)d_in[3];
    const float* qkvw  = (const float*)d_in[4];
    const float* dww   = (const float*)d_in[5];
    const float* projw = (const float*)d_in[6];
    const float* temp  = (const float*)d_in[7];

    __half *wc, *wqh, *wql, *wph, *wpl, *ch, *chL, *chR, *x16;
    float *cnf, *qkv1, *qkv2, *coef, *gpart, *attn;
    cudaGetSymbolAddress((void**)&wc,  g_wc);
    cudaGetSymbolAddress((void**)&wqh, g_wq_h);  cudaGetSymbolAddress((void**)&wql, g_wq_l);
    cudaGetSymbolAddress((void**)&wph, g_wp_h);  cudaGetSymbolAddress((void**)&wpl, g_wp_l);
    cudaGetSymbolAddress((void**)&ch,  g_ch);
    cudaGetSymbolAddress((void**)&chL, g_chL);
    cudaGetSymbolAddress((void**)&chR, g_chR);
    cudaGetSymbolAddress((void**)&x16, g_x16);
    cudaGetSymbolAddress((void**)&cnf,  g_cnf);
    cudaGetSymbolAddress((void**)&qkv1, g_qkv1);
    cudaGetSymbolAddress((void**)&qkv2, g_qkv);
    cudaGetSymbolAddress((void**)&coef, g_coef);
    cudaGetSymbolAddress((void**)&gpart, g_gpart);
    cudaGetSymbolAddress((void**)&attn, g_attn);

    cudaFuncSetAttribute(mm_kernel<1728, 9, 1, 2>,
                         cudaFuncAttributeMaxDynamicSharedMemorySize, SMEM_CONV);
    cudaFuncSetAttribute(mm_kernel<192, 1, 2, 2>,
                         cudaFuncAttributeMaxDynamicSharedMemorySize, SMEM_PW);

    const int NACT4 = BATCH * CDIM * HWSZ / 4;

    // weight prep
    foldw_kernel<<<256 * 1728 / 256, 256>>>(w3, w1, wc);
    splitw_kernel<<<640 * 192 / 256, 256>>>(qkvw, wqh, wql, 3 * CDIM);
    splitw_kernel<<<256 * 192 / 256, 256>>>(projw, wph, wpl, CDIM);

    // cn branch: fp16 + shifted copies, folded 3x3 conv (1-term fp16 HMMA)
    asplit_shift_h_kernel<<<(NACT4 + 255) / 256, 256>>>(cn, ch, chL, chR, NACT4);
    mm_kernel<1728, 9, 1, 2><<<dim3(128, 2, BATCH), 256, SMEM_CONV>>>(
        ch, chL, chR, wc, wc, cnf, CDIM);

    // qkv 1x1 (2-term fp16 HMMA)
    ahalf_kernel<<<(NACT4 + 255) / 256, 256>>>(x, x16, NACT4);
    mm_kernel<192, 1, 2, 2><<<dim3(128, 5, BATCH), 256, SMEM_PW>>>(
        x16, x16, x16, wqh, wql, qkv1, 3 * CDIM);

    // depthwise 3x3
    dwconv3_kernel<<<dim3(HWSZ / 1024, 3 * CDIM, BATCH), 256>>>(qkv1, dww, qkv2);

    // attention chain
    stats_kernel<<<BATCH * CDIM, 256>>>(qkv2, cnf, coef);
    gram_kernel<<<dim3(BATCH * NHEAD, SPLIT), 256>>>(qkv2, cnf, coef, gpart);
    softmax_kernel<<<BATCH * NHEAD, 256>>>(gpart, temp, attn);
    apply_kernel<<<dim3(32, NHEAD, BATCH), 256>>>(qkv2, attn, x16);   // reuse x16 for av

    // projection 1x1 (2-term fp16 HMMA; reads fp16 av written by apply)
    mm_kernel<192, 1, 2, 2><<<dim3(128, 2, BATCH), 256, SMEM_PW>>>(
        x16, x16, x16, wph, wpl, (float*)d_out, CDIM);
}

// round 9
// speedup vs baseline: 7.3791x; 1.1842x over previous
#include <cuda_runtime.h>
#include <cuda_fp16.h>
#include <cstdint>

#define EPSN 1e-12f

constexpr int BATCH = 8;
constexpr int CDIM  = 192;
constexpr int HWSZ  = 16384;   // 128*128
constexpr int NHEAD = 4;
constexpr int CHD   = 48;
constexpr int SPLIT = 8;
constexpr float WSC  = 64.f;
constexpr float IWSC = 1.f / 64.f;

// ---------------------------------------------------------------------------
// helpers
// ---------------------------------------------------------------------------
__device__ __forceinline__ uint32_t s2u(const void* p) {
    uint32_t a;
    asm("{ .reg .u64 t; cvta.to.shared.u64 t, %1; cvt.u32.u64 %0, t; }" : "=r"(a) : "l"(p));
    return a;
}
#define SWZ(x) ((x) ^ (((x) >> 3) & 0x70))

__device__ __forceinline__ void cpa16(uint32_t dst, const void* src, int srcsize) {
    asm volatile("cp.async.cg.shared.global [%0], [%1], 16, %2;"
                 :: "r"(dst), "l"(src), "r"(srcsize));
}
#define CPA_COMMIT() asm volatile("cp.async.commit_group;" ::: "memory")
#define CPA_WAIT(n)  asm volatile("cp.async.wait_group %0;" :: "n"(n) : "memory")

__device__ __forceinline__ void ldsm4(uint32_t* r, uint32_t addr) {
    asm volatile("ldmatrix.sync.aligned.m8n8.x4.shared.b16 {%0,%1,%2,%3}, [%4];"
        : "=r"(r[0]), "=r"(r[1]), "=r"(r[2]), "=r"(r[3]) : "r"(addr));
}
__device__ __forceinline__ void ldsm4t(uint32_t* r, uint32_t addr) {
    asm volatile("ldmatrix.sync.aligned.m8n8.x4.trans.shared.b16 {%0,%1,%2,%3}, [%4];"
        : "=r"(r[0]), "=r"(r[1]), "=r"(r[2]), "=r"(r[3]) : "r"(addr));
}
__device__ __forceinline__ void mma16816h(float* d, const uint32_t* a, const uint32_t* b) {
    asm volatile("mma.sync.aligned.m16n8k16.row.col.f32.f16.f16.f32 "
        "{%0,%1,%2,%3}, {%4,%5,%6,%7}, {%8,%9}, {%0,%1,%2,%3};"
        : "+f"(d[0]), "+f"(d[1]), "+f"(d[2]), "+f"(d[3])
        : "r"(a[0]), "r"(a[1]), "r"(a[2]), "r"(a[3]), "r"(b[0]), "r"(b[1]));
}
__device__ __forceinline__ uint32_t pack2h(__half a, __half b) {
    return (uint32_t)__half_as_ushort(a) | ((uint32_t)__half_as_ushort(b) << 16);
}

// ---------------------------------------------------------------------------
// scratch buffers (all intermediate streams fp16)
// ---------------------------------------------------------------------------
__device__ __half g_wc[256 * 1728];                     // folded 3x3, fp16, x64
__device__ __half g_wq_h[640 * 192], g_wq_l[640 * 192]; // qkv 1x1 fp16 hi/lo, x64
__device__ __half g_wp_h[256 * 192], g_wp_l[256 * 192]; // proj 1x1 fp16 hi/lo, x64
__device__ __half g_ch [(size_t)BATCH * CDIM * HWSZ];   // cn fp16 (center)
__device__ __half g_chL[(size_t)BATCH * CDIM * HWSZ];
__device__ __half g_chR[(size_t)BATCH * CDIM * HWSZ];
__device__ __half g_x16[(size_t)BATCH * CDIM * HWSZ];   // x fp16 / later av fp16
__device__ __half g_cnf[(size_t)BATCH * CDIM * HWSZ];       // conv out fp16
__device__ __half g_q1h[(size_t)BATCH * 3 * CDIM * HWSZ];   // qkv after 1x1, fp16
__device__ __half g_q2h[(size_t)BATCH * 3 * CDIM * HWSZ];   // qkv after dw, fp16
__device__ float g_coef[BATCH * CDIM * 3];
__device__ float g_gpart[BATCH * NHEAD * SPLIT * CHD * CHD];
__device__ float g_attn[BATCH * NHEAD * CHD * CHD];

// ---------------------------------------------------------------------------
// weight prep
// ---------------------------------------------------------------------------
__global__ void foldw_kernel(const float* __restrict__ w3, const float* __restrict__ w1,
                             __half* __restrict__ w) {
    int idx = blockIdx.x * 256 + threadIdx.x;          // 256*1728
    int co = idx / 1728, r = idx % 1728;
    int t = r / 192, cj = r % 192;
    float s = 0.f;
    if (co < CDIM)
        for (int ci = 0; ci < CDIM; ci++)
            s = fmaf(w3[(co * CDIM + ci) * 9 + t], w1[ci * CDIM + cj], s);
    w[idx] = __float2half(s * WSC);
}

__global__ void splitw_kernel(const float* __restrict__ w, __half* __restrict__ wh,
                              __half* __restrict__ wl, int validRows) {
    int idx = blockIdx.x * 256 + threadIdx.x;
    int row = idx / CDIM;
    float v = (row < validRows) ? w[(size_t)row * CDIM + (idx % CDIM)] * WSC : 0.f;
    __half h = __float2half(v);
    wh[idx] = h;
    wl[idx] = __float2half(v - __half2float(h));
}

__global__ __launch_bounds__(256) void ahalf_kernel(
    const float* __restrict__ in, __half* __restrict__ o, int n4) {
    int i = blockIdx.x * 256 + threadIdx.x;
    if (i >= n4) return;
    float4 v = ((const float4*)in)[i];
    ((uint2*)o)[i] = make_uint2(pack2h(__float2half(v.x), __float2half(v.y)),
                                pack2h(__float2half(v.z), __float2half(v.w)));
}

__global__ __launch_bounds__(256) void asplit_shift_h_kernel(
    const float* __restrict__ in,
    __half* __restrict__ oh, __half* __restrict__ ohL, __half* __restrict__ ohR, int n4) {
    int i = blockIdx.x * 256 + threadIdx.x;
    if (i >= n4) return;
    int p = i * 4;
    int col = p & 127;
    float4 v = ((const float4*)in)[i];
    float vnext = (col == 124) ? 0.f : in[p + 4];
    float vprev = (col == 0)   ? 0.f : in[p - 1];
    __half h0 = __float2half(v.x), h1 = __float2half(v.y);
    __half h2 = __float2half(v.z), h3 = __float2half(v.w);
    __half hn = __float2half(vnext), hp = __float2half(vprev);
    ((uint2*)oh)[i]  = make_uint2(pack2h(h0, h1), pack2h(h2, h3));
    ((uint2*)ohL)[i] = make_uint2(pack2h(h1, h2), pack2h(h3, hn));
    ((uint2*)ohR)[i] = make_uint2(pack2h(hp, h0), pack2h(h1, h2));
}

// ---------------------------------------------------------------------------
// fp16 HMMA GEMM, multi-stage cp.async pipeline. CTA 128m x 128n, K-chunk 64.
//   TERMS==1: C = A B ; 32KB stage, 3 stages.   TERMS==2: hi/lo weights; 48KB, 2 st.
//   HOUT: write fp16 (x 1/64), else fp32 (x 1/64).
// ---------------------------------------------------------------------------
template <int KTOT, int TAPS, int TERMS, int MINB, bool HOUT>
__global__ __launch_bounds__(256, MINB) void mm_kernel(
    const __half* __restrict__ xc, const __half* __restrict__ xL,
    const __half* __restrict__ xR,
    const __half* __restrict__ wh, const __half* __restrict__ wl,
    void* __restrict__ outv, int Cout) {
    constexpr int SSZ    = (TERMS == 2) ? 49152 : 32768;
    constexpr int STAGES = (TERMS == 2) ? 2 : 3;
    constexpr int BOFF   = (TERMS == 2) ? 32768 : 16384;
    extern __shared__ char sraw[];
    char* sal = (char*)((((uintptr_t)sraw) + 127) & ~(uintptr_t)127);
    const uint32_t sb = s2u(sal);
    const int tid = threadIdx.x, lane = tid & 31, wid = tid >> 5;
    const int n0 = blockIdx.x * 128, m0 = blockIdx.y * 128, b = blockIdx.z;
    const int wm = wid >> 1, wn = wid & 1;
    const int y = n0 >> 7;
    const int lr = lane & 15, lc = lane >> 4;
    constexpr int NCH = KTOT / 64;

    auto load_chunk = [&](int cc) {
        const int k0 = cc * 64;
        const int t = (TAPS == 9) ? (k0 / 192) : 0;
        const int ci0 = k0 - t * 192;
        const int dy = (TAPS == 9) ? (t / 3 - 1) : 0;
        const int dx = (TAPS == 9) ? (t % 3 - 1) : 0;
        const int yy = y + dy;
        const bool rowok = (TAPS == 1) || ((unsigned)yy < 128u);
        const int ys = rowok ? yy : y;
        const uint32_t stg = sb + (uint32_t)(cc % STAGES) * SSZ;
#pragma unroll
        for (int i = 0; i < 4 * TERMS; i++) {
            int e = tid + (i << 8);
            int ck = e & 7, r = (e >> 3) & 127, dt = e >> 10;
            const __half* src = (dt ? wl : wh) + (size_t)(m0 + r) * KTOT + k0 + ck * 8;
            cpa16(stg + dt * 16384 + SWZ(r * 128 + ck * 16), src, 16);
        }
        const __half* bp = (dx == 0) ? xc : (dx > 0 ? xL : xR);
        const int sz = rowok ? 16 : 0;
#pragma unroll
        for (int i = 0; i < 4; i++) {
            int e = tid + (i << 8);
            int nc = e & 15, k = (e >> 4) & 63;
            int n = nc * 8;
            const __half* src = bp + ((size_t)b * CDIM + ci0 + k) * HWSZ + ys * 128 + n;
            cpa16(stg + BOFF + (nc >> 3) * 8192 + SWZ(k * 128 + (n & 63) * 2), src, sz);
        }
        CPA_COMMIT();
    };

    float acc[2][8][4];
#pragma unroll
    for (int i = 0; i < 2; i++)
#pragma unroll
        for (int j = 0; j < 8; j++)
#pragma unroll
            for (int q = 0; q < 4; q++) acc[i][j][q] = 0.f;

#pragma unroll
    for (int i = 0; i < STAGES - 1 && i < NCH; i++) load_chunk(i);

    for (int cc = 0; cc < NCH; cc++) {
        if (cc + STAGES - 1 < NCH) load_chunk(cc + STAGES - 1);
        int pend = ((cc + STAGES - 1 < NCH) ? (STAGES - 1) : (NCH - 1 - cc));
        if (pend >= 2)      CPA_WAIT(2);
        else if (pend == 1) CPA_WAIT(1);
        else                CPA_WAIT(0);
        __syncthreads();
        const uint32_t stg = sb + (uint32_t)(cc % STAGES) * SSZ;

#pragma unroll
        for (int ks = 0; ks < 4; ks++) {
            uint32_t ah[2][4], alo[2][4];
#pragma unroll
            for (int mf = 0; mf < 2; mf++) {
                uint32_t ao = SWZ((wm * 32 + mf * 16 + lr) * 128 + ks * 32 + lc * 16);
                ldsm4(ah[mf], stg + ao);
                if (TERMS == 2) ldsm4(alo[mf], stg + 16384 + ao);
            }
#pragma unroll
            for (int g = 0; g < 4; g++) {
                uint32_t bh[4];
                uint32_t bo = BOFF + wn * 8192 + SWZ((ks * 16 + lr) * 128 + g * 32 + lc * 16);
                ldsm4t(bh, stg + bo);
#pragma unroll
                for (int mf = 0; mf < 2; mf++) {
                    mma16816h(acc[mf][2 * g],     ah[mf], bh);
                    mma16816h(acc[mf][2 * g + 1], ah[mf], bh + 2);
                    if (TERMS == 2) {
                        mma16816h(acc[mf][2 * g],     alo[mf], bh);
                        mma16816h(acc[mf][2 * g + 1], alo[mf], bh + 2);
                    }
                }
            }
        }
        __syncthreads();
    }

    // ---- epilogue (undo weight pre-scale)
#pragma unroll
    for (int mf = 0; mf < 2; mf++) {
        int mb = m0 + wm * 32 + mf * 16 + (lane >> 2);
#pragma unroll
        for (int nb = 0; nb < 8; nb++) {
            int nn = n0 + wn * 64 + nb * 8 + (lane & 3) * 2;
            if (HOUT) {
                __half* out = (__half*)outv;
                if (mb < Cout)
                    *(uint32_t*)(out + ((size_t)b * Cout + mb) * HWSZ + nn) =
                        pack2h(__float2half(acc[mf][nb][0] * IWSC),
                               __float2half(acc[mf][nb][1] * IWSC));
                if (mb + 8 < Cout)
                    *(uint32_t*)(out + ((size_t)b * Cout + mb + 8) * HWSZ + nn) =
                        pack2h(__float2half(acc[mf][nb][2] * IWSC),
                               __float2half(acc[mf][nb][3] * IWSC));
            } else {
                float* out = (float*)outv;
                if (mb < Cout)
                    *(float2*)(out + ((size_t)b * Cout + mb) * HWSZ + nn) =
                        make_float2(acc[mf][nb][0] * IWSC, acc[mf][nb][1] * IWSC);
                if (mb + 8 < Cout)
                    *(float2*)(out + ((size_t)b * Cout + mb + 8) * HWSZ + nn) =
                        make_float2(acc[mf][nb][2] * IWSC, acc[mf][nb][3] * IWSC);
            }
        }
    }
}

// ---------------------------------------------------------------------------
// depthwise 3x3 on fp16, 8 px/thread (uint4 = 8 halves), fp32 math
// ---------------------------------------------------------------------------
__global__ __launch_bounds__(256) void dwconv3h_kernel(
    const __half* __restrict__ in, const float* __restrict__ wdw,
    __half* __restrict__ out) {
    int c = blockIdx.y, b = blockIdx.z;
    int p8 = (blockIdx.x * 256 + threadIdx.x) * 8;
    int y = p8 >> 7, x = p8 & 127;
    const __half* src = in + ((size_t)b * (3 * CDIM) + c) * HWSZ;
    float w[9];
#pragma unroll
    for (int i = 0; i < 9; i++) w[i] = wdw[c * 9 + i];
    float a[8];
#pragma unroll
    for (int j = 0; j < 8; j++) a[j] = 0.f;
#pragma unroll
    for (int r = -1; r <= 1; r++) {
        int yy = y + r;
        if ((unsigned)yy >= 128u) continue;
        const __half* rp = src + (yy << 7);
        uint4 m4 = *(const uint4*)(rp + x);
        const __half* mh = (const __half*)&m4;
        float v[10];
        v[0] = (x > 0) ? __half2float(rp[x - 1]) : 0.f;
#pragma unroll
        for (int j = 0; j < 8; j++) v[j + 1] = __half2float(mh[j]);
        v[9] = (x + 8 < 128) ? __half2float(rp[x + 8]) : 0.f;
        int wb = (r + 1) * 3;
#pragma unroll
        for (int j = 0; j < 8; j++)
            a[j] = fmaf(w[wb], v[j], fmaf(w[wb + 1], v[j + 1], fmaf(w[wb + 2], v[j + 2], a[j])));
    }
    uint4 o4;
    __half* oh = (__half*)&o4;
#pragma unroll
    for (int j = 0; j < 8; j++) oh[j] = __float2half(a[j]);
    *(uint4*)(out + ((size_t)b * (3 * CDIM) + c) * HWSZ + p8) = o4;
}

// ---------------------------------------------------------------------------
// per-row norms (fp16 in, fp32 sums) -> normalization coefficients
// ---------------------------------------------------------------------------
__global__ __launch_bounds__(256) void stats_kernel(
    const __half* __restrict__ qkv, const __half* __restrict__ cnf,
    float* __restrict__ coef) {
    int rowi = blockIdx.x;
    int b = rowi / CDIM, c = rowi % CDIM;
    const __half2* q  = (const __half2*)(qkv + ((size_t)b * (3 * CDIM) + c) * HWSZ);
    const __half2* kk = (const __half2*)(qkv + ((size_t)b * (3 * CDIM) + CDIM + c) * HWSZ);
    const __half2* cn = (const __half2*)(cnf + (size_t)rowi * HWSZ);
    float sq = 0.f, sk = 0.f, sc = 0.f, sqc = 0.f;
    for (int i = threadIdx.x; i < HWSZ / 2; i += 256) {
        float2 qv = __half22float2(q[i]);
        float2 kv = __half22float2(kk[i]);
        float2 cv = __half22float2(cn[i]);
        sq  = fmaf(qv.x, qv.x, fmaf(qv.y, qv.y, sq));
        sk  = fmaf(kv.x, kv.x, fmaf(kv.y, kv.y, sk));
        sc  = fmaf(cv.x, cv.x, fmaf(cv.y, cv.y, sc));
        sqc = fmaf(qv.x, cv.x, fmaf(qv.y, cv.y, sqc));
    }
#pragma unroll
    for (int o = 16; o; o >>= 1) {
        sq += __shfl_xor_sync(~0u, sq, o); sk += __shfl_xor_sync(~0u, sk, o);
        sc += __shfl_xor_sync(~0u, sc, o); sqc += __shfl_xor_sync(~0u, sqc, o);
    }
    __shared__ float r4[4][8];
    int wid = threadIdx.x >> 5, lane = threadIdx.x & 31;
    if (lane == 0) { r4[0][wid] = sq; r4[1][wid] = sk; r4[2][wid] = sc; r4[3][wid] = sqc; }
    __syncthreads();
    if (threadIdx.x == 0) {
        float SQ = 0, SK = 0, SC = 0, SQC = 0;
        for (int i = 0; i < 8; i++) { SQ += r4[0][i]; SK += r4[1][i]; SC += r4[2][i]; SQC += r4[3][i]; }
        float a  = fmaxf(sqrtf(SQ), EPSN);
        float bb = fmaxf(sqrtf(SC), EPSN);
        float s2 = SQ / (a * a) + 2.f * SQC / (a * bb) + SC / (bb * bb);
        float s  = fmaxf(sqrtf(s2), EPSN);
        float kn = fmaxf(sqrtf(SK), EPSN);
        coef[rowi * 3 + 0] = 1.f / (a * s);
        coef[rowi * 3 + 1] = 1.f / (bb * s);
        coef[rowi * 3 + 2] = 1.f / kn;
    }
}

// ---------------------------------------------------------------------------
// gram (fp16 in) / softmax / apply (fp16 in/out)
// ---------------------------------------------------------------------------
__global__ __launch_bounds__(256) void gram_kernel(
    const __half* __restrict__ qkv, const __half* __restrict__ cnf,
    const float* __restrict__ coef, float* __restrict__ gpart) {
    __shared__ float SQ[48][33];
    __shared__ float SK[48][33];
    __shared__ float al[48], be[48], ga[48];
    int bh = blockIdx.x, sp = blockIdx.y;
    int b = bh >> 2, h = bh & 3;
    int tid = threadIdx.x, tx = tid & 15, ty = tid >> 4;
    if (tid < 48) {
        int rw = b * CDIM + h * CHD + tid;
        al[tid] = coef[rw * 3 + 0]; be[tid] = coef[rw * 3 + 1]; ga[tid] = coef[rw * 3 + 2];
    }
    __syncthreads();
    const __half* qb = qkv + ((size_t)b * (3 * CDIM) + h * CHD) * HWSZ;
    const __half* kb = qkv + ((size_t)b * (3 * CDIM) + CDIM + h * CHD) * HWSZ;
    const __half* cb = cnf + ((size_t)b * CDIM + h * CHD) * HWSZ;
    float acc[3][3] = {};
    int send = sp * 2048 + 2048;
    for (int s0 = sp * 2048; s0 < send; s0 += 32) {
        for (int e = tid; e < 768; e += 256) {      // 48 rows x 16 half2
            int r = e >> 4, s2 = (e & 15) * 2;
            size_t off = (size_t)r * HWSZ + s0 + s2;
            float2 q2 = __half22float2(*(const __half2*)(qb + off));
            float2 c2 = __half22float2(*(const __half2*)(cb + off));
            float2 k2 = __half22float2(*(const __half2*)(kb + off));
            SQ[r][s2]     = al[r] * q2.x + be[r] * c2.x;
            SQ[r][s2 + 1] = al[r] * q2.y + be[r] * c2.y;
            SK[r][s2]     = ga[r] * k2.x;
            SK[r][s2 + 1] = ga[r] * k2.y;
        }
        __syncthreads();
#pragma unroll 4
        for (int s = 0; s < 32; s++) {
            float qa[3], kv[3];
#pragma unroll
            for (int i = 0; i < 3; i++) qa[i] = SQ[tx + 16 * i][s];
#pragma unroll
            for (int j = 0; j < 3; j++) kv[j] = SK[ty + 16 * j][s];
#pragma unroll
            for (int i = 0; i < 3; i++)
#pragma unroll
                for (int j = 0; j < 3; j++)
                    acc[i][j] = fmaf(qa[i], kv[j], acc[i][j]);
        }
        __syncthreads();
    }
#pragma unroll
    for (int i = 0; i < 3; i++)
#pragma unroll
        for (int j = 0; j < 3; j++)
            gpart[((bh * SPLIT + sp) * CHD + tx + 16 * i) * CHD + ty + 16 * j] = acc[i][j];
}

__global__ __launch_bounds__(256) void softmax_kernel(
    const float* __restrict__ gpart, const float* __restrict__ temp,
    float* __restrict__ attn) {
    __shared__ float S[48][49];
    int bh = blockIdx.x;
    float T = temp[bh & 3];
    int tid = threadIdx.x;
    for (int e = tid; e < CHD * CHD; e += 256) {
        int c = e / CHD, d = e - c * CHD;
        float g = 0.f;
#pragma unroll
        for (int sp = 0; sp < SPLIT; sp++)
            g += gpart[((bh * SPLIT + sp) * CHD + c) * CHD + d];
        S[c][d] = g * T;
    }
    __syncthreads();
    int wid = tid >> 5, lane = tid & 31;
    for (int r = wid; r < 48; r += 8) {
        float v1 = S[r][lane];
        float v2 = (lane < 16) ? S[r][32 + lane] : -1e30f;
        float m = fmaxf(v1, v2);
#pragma unroll
        for (int o = 16; o; o >>= 1) m = fmaxf(m, __shfl_xor_sync(~0u, m, o));
        float e1 = expf(v1 - m);
        float e2 = (lane < 16) ? expf(v2 - m) : 0.f;
        float s = e1 + e2;
#pragma unroll
        for (int o = 16; o; o >>= 1) s += __shfl_xor_sync(~0u, s, o);
        float inv = 1.f / s;
        attn[bh * (CHD * CHD) + r * CHD + lane] = e1 * inv;
        if (lane < 16) attn[bh * (CHD * CHD) + r * CHD + 32 + lane] = e2 * inv;
    }
}

// attn @ v (fp16 v), writes fp16 av
__global__ __launch_bounds__(256) void apply_kernel(
    const __half* __restrict__ qkv, const float* __restrict__ attn,
    __half* __restrict__ o16) {
    __shared__ float A[48][48];
    int b = blockIdx.z, h = blockIdx.y;
    int tid = threadIdx.x;
    for (int e = tid; e < CHD * CHD; e += 256)
        A[e / CHD][e % CHD] = attn[(b * NHEAD + h) * (CHD * CHD) + e];
    __syncthreads();
    int p2 = (blockIdx.x * 256 + tid) * 2;
    const __half* vb = qkv + ((size_t)b * (3 * CDIM) + 2 * CDIM + h * CHD) * HWSZ;
    float a0[48], a1[48];
#pragma unroll
    for (int c = 0; c < 48; c++) { a0[c] = 0.f; a1[c] = 0.f; }
#pragma unroll 2
    for (int d = 0; d < 48; d++) {
        float2 vf = __half22float2(*(const __half2*)(vb + (size_t)d * HWSZ + p2));
#pragma unroll
        for (int c = 0; c < 48; c++) {
            float a = A[c][d];
            a0[c] = fmaf(a, vf.x, a0[c]);
            a1[c] = fmaf(a, vf.y, a1[c]);
        }
    }
    size_t ob = ((size_t)b * CDIM + h * CHD) * HWSZ + p2;
#pragma unroll
    for (int c = 0; c < 48; c++)
        *(uint32_t*)(o16 + ob + (size_t)c * HWSZ) =
            pack2h(__float2half(a0[c]), __float2half(a1[c]));
}

// ---------------------------------------------------------------------------
// launch
// ---------------------------------------------------------------------------
constexpr int SMEM_CONV = 3 * 32768 + 128;   // 1-term, 3 stages
constexpr int SMEM_PW   = 2 * 49152 + 128;   // 2-term, 2 stages

extern "C" void kernel_launch(void* const* d_in, const int* in_sizes, int n_in,
                              void* d_out, int out_size) {
    const float* x     = (const float*)d_in[0];
    const float* cn    = (const float*)d_in[1];
    const float* w1    = (const float*)d_in[2];
    const float* w3    = (const float*)d_in[3];
    const float* qkvw  = (const float*)d_in[4];
    const float* dww   = (const float*)d_in[5];
    const float* projw = (const float*)d_in[6];
    const float* temp  = (const float*)d_in[7];

    __half *wc, *wqh, *wql, *wph, *wpl, *ch, *chL, *chR, *x16, *cnf, *q1h, *q2h;
    float *coef, *gpart, *attn;
    cudaGetSymbolAddress((void**)&wc,  g_wc);
    cudaGetSymbolAddress((void**)&wqh, g_wq_h);  cudaGetSymbolAddress((void**)&wql, g_wq_l);
    cudaGetSymbolAddress((void**)&wph, g_wp_h);  cudaGetSymbolAddress((void**)&wpl, g_wp_l);
    cudaGetSymbolAddress((void**)&ch,  g_ch);
    cudaGetSymbolAddress((void**)&chL, g_chL);
    cudaGetSymbolAddress((void**)&chR, g_chR);
    cudaGetSymbolAddress((void**)&x16, g_x16);
    cudaGetSymbolAddress((void**)&cnf, g_cnf);
    cudaGetSymbolAddress((void**)&q1h, g_q1h);
    cudaGetSymbolAddress((void**)&q2h, g_q2h);
    cudaGetSymbolAddress((void**)&coef, g_coef);
    cudaGetSymbolAddress((void**)&gpart, g_gpart);
    cudaGetSymbolAddress((void**)&attn, g_attn);

    cudaFuncSetAttribute(mm_kernel<1728, 9, 1, 2, true>,
                         cudaFuncAttributeMaxDynamicSharedMemorySize, SMEM_CONV);
    cudaFuncSetAttribute(mm_kernel<192, 1, 2, 2, true>,
                         cudaFuncAttributeMaxDynamicSharedMemorySize, SMEM_PW);
    cudaFuncSetAttribute(mm_kernel<192, 1, 2, 2, false>,
                         cudaFuncAttributeMaxDynamicSharedMemorySize, SMEM_PW);

    const int NACT4 = BATCH * CDIM * HWSZ / 4;

    // weight prep
    foldw_kernel<<<256 * 1728 / 256, 256>>>(w3, w1, wc);
    splitw_kernel<<<640 * 192 / 256, 256>>>(qkvw, wqh, wql, 3 * CDIM);
    splitw_kernel<<<256 * 192 / 256, 256>>>(projw, wph, wpl, CDIM);

    // cn branch: fp16 + shifted copies, folded 3x3 conv -> fp16 cnf
    asplit_shift_h_kernel<<<(NACT4 + 255) / 256, 256>>>(cn, ch, chL, chR, NACT4);
    mm_kernel<1728, 9, 1, 2, true><<<dim3(128, 2, BATCH), 256, SMEM_CONV>>>(
        ch, chL, chR, wc, wc, cnf, CDIM);

    // qkv 1x1 -> fp16
    ahalf_kernel<<<(NACT4 + 255) / 256, 256>>>(x, x16, NACT4);
    mm_kernel<192, 1, 2, 2, true><<<dim3(128, 5, BATCH), 256, SMEM_PW>>>(
        x16, x16, x16, wqh, wql, q1h, 3 * CDIM);

    // depthwise 3x3 (fp16 in/out, 8 px/thread)
    dwconv3h_kernel<<<dim3(HWSZ / 2048, 3 * CDIM, BATCH), 256>>>(q1h, dww, q2h);

    // attention chain (fp16 streams)
    stats_kernel<<<BATCH * CDIM, 256>>>(q2h, cnf, coef);
    gram_kernel<<<dim3(BATCH * NHEAD, SPLIT), 256>>>(q2h, cnf, coef, gpart);
    softmax_kernel<<<BATCH * NHEAD, 256>>>(gpart, temp, attn);
    apply_kernel<<<dim3(32, NHEAD, BATCH), 256>>>(q2h, attn, x16);   // av -> x16

    // projection 1x1 -> fp32 output
    mm_kernel<192, 1, 2, 2, false><<<dim3(128, 2, BATCH), 256, SMEM_PW>>>(
        x16, x16, x16, wph, wpl, (float*)d_out, CDIM);
}

// round 10
// speedup vs baseline: 8.2581x; 1.1191x over previous
#include <cuda_runtime.h>
#include <cuda_fp16.h>
#include <cstdint>

#define EPSN 1e-12f

constexpr int BATCH = 8;
constexpr int CDIM  = 192;
constexpr int HWSZ  = 16384;   // 128*128
constexpr int NHEAD = 4;
constexpr int CHD   = 48;
constexpr int SPLIT = 8;
constexpr float WSC  = 64.f;
constexpr float IWSC = 1.f / 64.f;

// ---------------------------------------------------------------------------
// helpers
// ---------------------------------------------------------------------------
__device__ __forceinline__ uint32_t s2u(const void* p) {
    uint32_t a;
    asm("{ .reg .u64 t; cvta.to.shared.u64 t, %1; cvt.u32.u64 %0, t; }" : "=r"(a) : "l"(p));
    return a;
}
#define SWZ(x) ((x) ^ (((x) >> 3) & 0x70))

__device__ __forceinline__ void cpa16(uint32_t dst, const void* src, int srcsize) {
    asm volatile("cp.async.cg.shared.global [%0], [%1], 16, %2;"
                 :: "r"(dst), "l"(src), "r"(srcsize));
}
#define CPA_COMMIT() asm volatile("cp.async.commit_group;" ::: "memory")
#define CPA_WAIT(n)  asm volatile("cp.async.wait_group %0;" :: "n"(n) : "memory")

__device__ __forceinline__ void ldsm4(uint32_t* r, uint32_t addr) {
    asm volatile("ldmatrix.sync.aligned.m8n8.x4.shared.b16 {%0,%1,%2,%3}, [%4];"
        : "=r"(r[0]), "=r"(r[1]), "=r"(r[2]), "=r"(r[3]) : "r"(addr));
}
__device__ __forceinline__ void ldsm4t(uint32_t* r, uint32_t addr) {
    asm volatile("ldmatrix.sync.aligned.m8n8.x4.trans.shared.b16 {%0,%1,%2,%3}, [%4];"
        : "=r"(r[0]), "=r"(r[1]), "=r"(r[2]), "=r"(r[3]) : "r"(addr));
}
__device__ __forceinline__ void mma16816h(float* d, const uint32_t* a, const uint32_t* b) {
    asm volatile("mma.sync.aligned.m16n8k16.row.col.f32.f16.f16.f32 "
        "{%0,%1,%2,%3}, {%4,%5,%6,%7}, {%8,%9}, {%0,%1,%2,%3};"
        : "+f"(d[0]), "+f"(d[1]), "+f"(d[2]), "+f"(d[3])
        : "r"(a[0]), "r"(a[1]), "r"(a[2]), "r"(a[3]), "r"(b[0]), "r"(b[1]));
}
__device__ __forceinline__ uint32_t pack2h(__half a, __half b) {
    return (uint32_t)__half_as_ushort(a) | ((uint32_t)__half_as_ushort(b) << 16);
}

// ---------------------------------------------------------------------------
// scratch buffers (all intermediate streams fp16)
// ---------------------------------------------------------------------------
__device__ __half g_wc[256 * 1728];                     // folded 3x3, fp16, x64
__device__ __half g_wq_h[640 * 192], g_wq_l[640 * 192]; // qkv 1x1 fp16 hi/lo, x64
__device__ __half g_wp_h[256 * 192], g_wp_l[256 * 192]; // proj 1x1 fp16 hi/lo, x64
__device__ __half g_ch [(size_t)BATCH * CDIM * HWSZ];   // cn fp16 (center)
__device__ __half g_chL[(size_t)BATCH * CDIM * HWSZ];
__device__ __half g_chR[(size_t)BATCH * CDIM * HWSZ];
__device__ __half g_x16[(size_t)BATCH * CDIM * HWSZ];   // x fp16 / later av fp16
__device__ __half g_cnf[(size_t)BATCH * CDIM * HWSZ];       // conv out fp16
__device__ __half g_q1h[(size_t)BATCH * 3 * CDIM * HWSZ];   // qkv after 1x1, fp16
__device__ __half g_q2h[(size_t)BATCH * 3 * CDIM * HWSZ];   // qkv after dw, fp16
__device__ float g_coef[BATCH * CDIM * 3];
__device__ float g_gpart[BATCH * NHEAD * SPLIT * CHD * CHD];
__device__ float g_attn[BATCH * NHEAD * CHD * CHD];

// ---------------------------------------------------------------------------
// weight prep
// ---------------------------------------------------------------------------
__global__ void foldw_kernel(const float* __restrict__ w3, const float* __restrict__ w1,
                             __half* __restrict__ w) {
    int idx = blockIdx.x * 256 + threadIdx.x;          // 256*1728
    int co = idx / 1728, r = idx % 1728;
    int t = r / 192, cj = r % 192;
    float s = 0.f;
    if (co < CDIM)
        for (int ci = 0; ci < CDIM; ci++)
            s = fmaf(w3[(co * CDIM + ci) * 9 + t], w1[ci * CDIM + cj], s);
    w[idx] = __float2half(s * WSC);
}

__global__ void splitw_kernel(const float* __restrict__ w, __half* __restrict__ wh,
                              __half* __restrict__ wl, int validRows) {
    int idx = blockIdx.x * 256 + threadIdx.x;
    int row = idx / CDIM;
    float v = (row < validRows) ? w[(size_t)row * CDIM + (idx % CDIM)] * WSC : 0.f;
    __half h = __float2half(v);
    wh[idx] = h;
    wl[idx] = __float2half(v - __half2float(h));
}

__global__ __launch_bounds__(256) void ahalf_kernel(
    const float* __restrict__ in, __half* __restrict__ o, int n4) {
    int i = blockIdx.x * 256 + threadIdx.x;
    if (i >= n4) return;
    float4 v = ((const float4*)in)[i];
    ((uint2*)o)[i] = make_uint2(pack2h(__float2half(v.x), __float2half(v.y)),
                                pack2h(__float2half(v.z), __float2half(v.w)));
}

__global__ __launch_bounds__(256) void asplit_shift_h_kernel(
    const float* __restrict__ in,
    __half* __restrict__ oh, __half* __restrict__ ohL, __half* __restrict__ ohR, int n4) {
    int i = blockIdx.x * 256 + threadIdx.x;
    if (i >= n4) return;
    int p = i * 4;
    int col = p & 127;
    float4 v = ((const float4*)in)[i];
    float vnext = (col == 124) ? 0.f : in[p + 4];
    float vprev = (col == 0)   ? 0.f : in[p - 1];
    __half h0 = __float2half(v.x), h1 = __float2half(v.y);
    __half h2 = __float2half(v.z), h3 = __float2half(v.w);
    __half hn = __float2half(vnext), hp = __float2half(vprev);
    ((uint2*)oh)[i]  = make_uint2(pack2h(h0, h1), pack2h(h2, h3));
    ((uint2*)ohL)[i] = make_uint2(pack2h(h1, h2), pack2h(h3, hn));
    ((uint2*)ohR)[i] = make_uint2(pack2h(hp, h0), pack2h(h1, h2));
}

// ---------------------------------------------------------------------------
// fp16 HMMA GEMM, multi-stage cp.async pipeline.
//   CTA tile M=96 x N=128 (8 warps = 2m x 4n; warp tile 48x32), K-chunk 64.
//   M=96 divides 192/576 exactly -> no padded-row MMA waste.
//   TERMS==1: C = A B          (stage 28KB: A 12K | B 16K), 3 stages
//   TERMS==2: C = Ah B + Al B  (stage 40KB: Ah 12K | Al 12K | B 16K), 2 stages
//   Weights pre-scaled x64; epilogue multiplies 1/64. fp32 accum.
//   HOUT: write fp16, else fp32.
// ---------------------------------------------------------------------------
template <int KTOT, int TAPS, int TERMS, bool HOUT>
__global__ __launch_bounds__(256, 2) void mm_kernel(
    const __half* __restrict__ xc, const __half* __restrict__ xL,
    const __half* __restrict__ xR,
    const __half* __restrict__ wh, const __half* __restrict__ wl,
    void* __restrict__ outv, int Cout) {
    constexpr int ATSZ   = 12288;                 // one A term: 96 rows x 128B
    constexpr int BOFF   = TERMS * ATSZ;
    constexpr int SSZ    = BOFF + 16384;
    constexpr int STAGES = (TERMS == 2) ? 2 : 3;
    extern __shared__ char sraw[];
    char* sal = (char*)((((uintptr_t)sraw) + 127) & ~(uintptr_t)127);
    const uint32_t sb = s2u(sal);
    const int tid = threadIdx.x, lane = tid & 31, wid = tid >> 5;
    const int n0 = blockIdx.x * 128, m0 = blockIdx.y * 96, b = blockIdx.z;
    const int wm = wid >> 2, wn = wid & 3;        // 2m x 4n warp grid
    const int y = n0 >> 7;
    const int lr = lane & 15, lc = lane >> 4;
    constexpr int NCH = KTOT / 64;

    auto load_chunk = [&](int cc) {
        const int k0 = cc * 64;
        const int t = (TAPS == 9) ? (k0 / 192) : 0;
        const int ci0 = k0 - t * 192;
        const int dy = (TAPS == 9) ? (t / 3 - 1) : 0;
        const int dx = (TAPS == 9) ? (t % 3 - 1) : 0;
        const int yy = y + dy;
        const bool rowok = (TAPS == 1) || ((unsigned)yy < 128u);
        const int ys = rowok ? yy : y;
        const uint32_t stg = sb + (uint32_t)(cc % STAGES) * SSZ;
        // A: TERMS buffers of 96 rows x 8 x 16B = 768 transfers each
#pragma unroll
        for (int i = 0; i < 3 * TERMS; i++) {
            int e = tid + (i << 8);
            int dt = e / 768, rr = e - dt * 768;
            int ck = rr & 7, r = rr >> 3;
            const __half* src = (dt ? wl : wh) + (size_t)(m0 + r) * KTOT + k0 + ck * 8;
            cpa16(stg + dt * ATSZ + SWZ(r * 128 + ck * 16), src, 16);
        }
        // B: single fp16 buffer, 64 rows x 128B (two 64-col halves of 8KB)
        const __half* bp = (dx == 0) ? xc : (dx > 0 ? xL : xR);
        const int sz = rowok ? 16 : 0;
#pragma unroll
        for (int i = 0; i < 4; i++) {
            int e = tid + (i << 8);
            int nc = e & 15, k = (e >> 4) & 63;
            int n = nc * 8;
            const __half* src = bp + ((size_t)b * CDIM + ci0 + k) * HWSZ + ys * 128 + n;
            cpa16(stg + BOFF + (nc >> 3) * 8192 + SWZ(k * 128 + (n & 63) * 2), src, sz);
        }
        CPA_COMMIT();
    };

    float acc[3][4][4];
#pragma unroll
    for (int i = 0; i < 3; i++)
#pragma unroll
        for (int j = 0; j < 4; j++)
#pragma unroll
            for (int q = 0; q < 4; q++) acc[i][j][q] = 0.f;

#pragma unroll
    for (int i = 0; i < STAGES - 1 && i < NCH; i++) load_chunk(i);

    for (int cc = 0; cc < NCH; cc++) {
        if (cc + STAGES - 1 < NCH) load_chunk(cc + STAGES - 1);
        int pend = ((cc + STAGES - 1 < NCH) ? (STAGES - 1) : (NCH - 1 - cc));
        if (pend >= 2)      CPA_WAIT(2);
        else if (pend == 1) CPA_WAIT(1);
        else                CPA_WAIT(0);
        __syncthreads();
        const uint32_t stg = sb + (uint32_t)(cc % STAGES) * SSZ;

#pragma unroll
        for (int ks = 0; ks < 4; ks++) {
            uint32_t ah[3][4], alo[3][4];
#pragma unroll
            for (int mf = 0; mf < 3; mf++) {
                uint32_t ao = SWZ((wm * 48 + mf * 16 + lr) * 128 + ks * 32 + lc * 16);
                ldsm4(ah[mf], stg + ao);
                if (TERMS == 2) ldsm4(alo[mf], stg + ATSZ + ao);
            }
#pragma unroll
            for (int gg = 0; gg < 2; gg++) {
                int cb = wn * 32 + gg * 16;       // n-column (halves)
                uint32_t bh[4];
                uint32_t bo = BOFF + (cb >> 6) * 8192 +
                              SWZ((ks * 16 + lr) * 128 + (cb & 63) * 2 + lc * 16);
                ldsm4t(bh, stg + bo);
#pragma unroll
                for (int mf = 0; mf < 3; mf++) {
                    mma16816h(acc[mf][2 * gg],     ah[mf], bh);
                    mma16816h(acc[mf][2 * gg + 1], ah[mf], bh + 2);
                    if (TERMS == 2) {
                        mma16816h(acc[mf][2 * gg],     alo[mf], bh);
                        mma16816h(acc[mf][2 * gg + 1], alo[mf], bh + 2);
                    }
                }
            }
        }
        __syncthreads();
    }

    // ---- epilogue (undo weight pre-scale)
#pragma unroll
    for (int mf = 0; mf < 3; mf++) {
        int mb = m0 + wm * 48 + mf * 16 + (lane >> 2);
#pragma unroll
        for (int nb = 0; nb < 4; nb++) {
            int nn = n0 + wn * 32 + nb * 8 + (lane & 3) * 2;
            if (HOUT) {
                __half* out = (__half*)outv;
                *(uint32_t*)(out + ((size_t)b * Cout + mb) * HWSZ + nn) =
                    pack2h(__float2half(acc[mf][nb][0] * IWSC),
                           __float2half(acc[mf][nb][1] * IWSC));
                *(uint32_t*)(out + ((size_t)b * Cout + mb + 8) * HWSZ + nn) =
                    pack2h(__float2half(acc[mf][nb][2] * IWSC),
                           __float2half(acc[mf][nb][3] * IWSC));
            } else {
                float* out = (float*)outv;
                *(float2*)(out + ((size_t)b * Cout + mb) * HWSZ + nn) =
                    make_float2(acc[mf][nb][0] * IWSC, acc[mf][nb][1] * IWSC);
                *(float2*)(out + ((size_t)b * Cout + mb + 8) * HWSZ + nn) =
                    make_float2(acc[mf][nb][2] * IWSC, acc[mf][nb][3] * IWSC);
            }
        }
    }
}

// ---------------------------------------------------------------------------
// depthwise 3x3 on fp16, 8 px/thread (uint4 = 8 halves), fp32 math
// ---------------------------------------------------------------------------
__global__ __launch_bounds__(256) void dwconv3h_kernel(
    const __half* __restrict__ in, const float* __restrict__ wdw,
    __half* __restrict__ out) {
    int c = blockIdx.y, b = blockIdx.z;
    int p8 = (blockIdx.x * 256 + threadIdx.x) * 8;
    int y = p8 >> 7, x = p8 & 127;
    const __half* src = in + ((size_t)b * (3 * CDIM) + c) * HWSZ;
    float w[9];
#pragma unroll
    for (int i = 0; i < 9; i++) w[i] = wdw[c * 9 + i];
    float a[8];
#pragma unroll
    for (int j = 0; j < 8; j++) a[j] = 0.f;
#pragma unroll
    for (int r = -1; r <= 1; r++) {
        int yy = y + r;
        if ((unsigned)yy >= 128u) continue;
        const __half* rp = src + (yy << 7);
        uint4 m4 = *(const uint4*)(rp + x);
        const __half* mh = (const __half*)&m4;
        float v[10];
        v[0] = (x > 0) ? __half2float(rp[x - 1]) : 0.f;
#pragma unroll
        for (int j = 0; j < 8; j++) v[j + 1] = __half2float(mh[j]);
        v[9] = (x + 8 < 128) ? __half2float(rp[x + 8]) : 0.f;
        int wb = (r + 1) * 3;
#pragma unroll
        for (int j = 0; j < 8; j++)
            a[j] = fmaf(w[wb], v[j], fmaf(w[wb + 1], v[j + 1], fmaf(w[wb + 2], v[j + 2], a[j])));
    }
    uint4 o4;
    __half* oh = (__half*)&o4;
#pragma unroll
    for (int j = 0; j < 8; j++) oh[j] = __float2half(a[j]);
    *(uint4*)(out + ((size_t)b * (3 * CDIM) + c) * HWSZ + p8) = o4;
}

// ---------------------------------------------------------------------------
// per-row norms (fp16 in, fp32 sums) -> normalization coefficients
// ---------------------------------------------------------------------------
__global__ __launch_bounds__(256) void stats_kernel(
    const __half* __restrict__ qkv, const __half* __restrict__ cnf,
    float* __restrict__ coef) {
    int rowi = blockIdx.x;
    int b = rowi / CDIM, c = rowi % CDIM;
    const __half2* q  = (const __half2*)(qkv + ((size_t)b * (3 * CDIM) + c) * HWSZ);
    const __half2* kk = (const __half2*)(qkv + ((size_t)b * (3 * CDIM) + CDIM + c) * HWSZ);
    const __half2* cn = (const __half2*)(cnf + (size_t)rowi * HWSZ);
    float sq = 0.f, sk = 0.f, sc = 0.f, sqc = 0.f;
    for (int i = threadIdx.x; i < HWSZ / 2; i += 256) {
        float2 qv = __half22float2(q[i]);
        float2 kv = __half22float2(kk[i]);
        float2 cv = __half22float2(cn[i]);
        sq  = fmaf(qv.x, qv.x, fmaf(qv.y, qv.y, sq));
        sk  = fmaf(kv.x, kv.x, fmaf(kv.y, kv.y, sk));
        sc  = fmaf(cv.x, cv.x, fmaf(cv.y, cv.y, sc));
        sqc = fmaf(qv.x, cv.x, fmaf(qv.y, cv.y, sqc));
    }
#pragma unroll
    for (int o = 16; o; o >>= 1) {
        sq += __shfl_xor_sync(~0u, sq, o); sk += __shfl_xor_sync(~0u, sk, o);
        sc += __shfl_xor_sync(~0u, sc, o); sqc += __shfl_xor_sync(~0u, sqc, o);
    }
    __shared__ float r4[4][8];
    int wid = threadIdx.x >> 5, lane = threadIdx.x & 31;
    if (lane == 0) { r4[0][wid] = sq; r4[1][wid] = sk; r4[2][wid] = sc; r4[3][wid] = sqc; }
    __syncthreads();
    if (threadIdx.x == 0) {
        float SQ = 0, SK = 0, SC = 0, SQC = 0;
        for (int i = 0; i < 8; i++) { SQ += r4[0][i]; SK += r4[1][i]; SC += r4[2][i]; SQC += r4[3][i]; }
        float a  = fmaxf(sqrtf(SQ), EPSN);
        float bb = fmaxf(sqrtf(SC), EPSN);
        float s2 = SQ / (a * a) + 2.f * SQC / (a * bb) + SC / (bb * bb);
        float s  = fmaxf(sqrtf(s2), EPSN);
        float kn = fmaxf(sqrtf(SK), EPSN);
        coef[rowi * 3 + 0] = 1.f / (a * s);
        coef[rowi * 3 + 1] = 1.f / (bb * s);
        coef[rowi * 3 + 2] = 1.f / kn;
    }
}

// ---------------------------------------------------------------------------
// gram (fp16 in) / softmax / apply (fp16 in/out)
// ---------------------------------------------------------------------------
__global__ __launch_bounds__(256) void gram_kernel(
    const __half* __restrict__ qkv, const __half* __restrict__ cnf,
    const float* __restrict__ coef, float* __restrict__ gpart) {
    __shared__ float SQ[48][33];
    __shared__ float SK[48][33];
    __shared__ float al[48], be[48], ga[48];
    int bh = blockIdx.x, sp = blockIdx.y;
    int b = bh >> 2, h = bh & 3;
    int tid = threadIdx.x, tx = tid & 15, ty = tid >> 4;
    if (tid < 48) {
        int rw = b * CDIM + h * CHD + tid;
        al[tid] = coef[rw * 3 + 0]; be[tid] = coef[rw * 3 + 1]; ga[tid] = coef[rw * 3 + 2];
    }
    __syncthreads();
    const __half* qb = qkv + ((size_t)b * (3 * CDIM) + h * CHD) * HWSZ;
    const __half* kb = qkv + ((size_t)b * (3 * CDIM) + CDIM + h * CHD) * HWSZ;
    const __half* cb = cnf + ((size_t)b * CDIM + h * CHD) * HWSZ;
    float acc[3][3] = {};
    int send = sp * 2048 + 2048;
    for (int s0 = sp * 2048; s0 < send; s0 += 32) {
        for (int e = tid; e < 768; e += 256) {      // 48 rows x 16 half2
            int r = e >> 4, s2 = (e & 15) * 2;
            size_t off = (size_t)r * HWSZ + s0 + s2;
            float2 q2 = __half22float2(*(const __half2*)(qb + off));
            float2 c2 = __half22float2(*(const __half2*)(cb + off));
            float2 k2 = __half22float2(*(const __half2*)(kb + off));
            SQ[r][s2]     = al[r] * q2.x + be[r] * c2.x;
            SQ[r][s2 + 1] = al[r] * q2.y + be[r] * c2.y;
            SK[r][s2]     = ga[r] * k2.x;
            SK[r][s2 + 1] = ga[r] * k2.y;
        }
        __syncthreads();
#pragma unroll 4
        for (int s = 0; s < 32; s++) {
            float qa[3], kv[3];
#pragma unroll
            for (int i = 0; i < 3; i++) qa[i] = SQ[tx + 16 * i][s];
#pragma unroll
            for (int j = 0; j < 3; j++) kv[j] = SK[ty + 16 * j][s];
#pragma unroll
            for (int i = 0; i < 3; i++)
#pragma unroll
                for (int j = 0; j < 3; j++)
                    acc[i][j] = fmaf(qa[i], kv[j], acc[i][j]);
        }
        __syncthreads();
    }
#pragma unroll
    for (int i = 0; i < 3; i++)
#pragma unroll
        for (int j = 0; j < 3; j++)
            gpart[((bh * SPLIT + sp) * CHD + tx + 16 * i) * CHD + ty + 16 * j] = acc[i][j];
}

__global__ __launch_bounds__(256) void softmax_kernel(
    const float* __restrict__ gpart, const float* __restrict__ temp,
    float* __restrict__ attn) {
    __shared__ float S[48][49];
    int bh = blockIdx.x;
    float T = temp[bh & 3];
    int tid = threadIdx.x;
    for (int e = tid; e < CHD * CHD; e += 256) {
        int c = e / CHD, d = e - c * CHD;
        float g = 0.f;
#pragma unroll
        for (int sp = 0; sp < SPLIT; sp++)
            g += gpart[((bh * SPLIT + sp) * CHD + c) * CHD + d];
        S[c][d] = g * T;
    }
    __syncthreads();
    int wid = tid >> 5, lane = tid & 31;
    for (int r = wid; r < 48; r += 8) {
        float v1 = S[r][lane];
        float v2 = (lane < 16) ? S[r][32 + lane] : -1e30f;
        float m = fmaxf(v1, v2);
#pragma unroll
        for (int o = 16; o; o >>= 1) m = fmaxf(m, __shfl_xor_sync(~0u, m, o));
        float e1 = expf(v1 - m);
        float e2 = (lane < 16) ? expf(v2 - m) : 0.f;
        float s = e1 + e2;
#pragma unroll
        for (int o = 16; o; o >>= 1) s += __shfl_xor_sync(~0u, s, o);
        float inv = 1.f / s;
        attn[bh * (CHD * CHD) + r * CHD + lane] = e1 * inv;
        if (lane < 16) attn[bh * (CHD * CHD) + r * CHD + 32 + lane] = e2 * inv;
    }
}

// attn @ v (fp16 v), writes fp16 av
__global__ __launch_bounds__(256) void apply_kernel(
    const __half* __restrict__ qkv, const float* __restrict__ attn,
    __half* __restrict__ o16) {
    __shared__ float A[48][48];
    int b = blockIdx.z, h = blockIdx.y;
    int tid = threadIdx.x;
    for (int e = tid; e < CHD * CHD; e += 256)
        A[e / CHD][e % CHD] = attn[(b * NHEAD + h) * (CHD * CHD) + e];
    __syncthreads();
    int p2 = (blockIdx.x * 256 + tid) * 2;
    const __half* vb = qkv + ((size_t)b * (3 * CDIM) + 2 * CDIM + h * CHD) * HWSZ;
    float a0[48], a1[48];
#pragma unroll
    for (int c = 0; c < 48; c++) { a0[c] = 0.f; a1[c] = 0.f; }
#pragma unroll 2
    for (int d = 0; d < 48; d++) {
        float2 vf = __half22float2(*(const __half2*)(vb + (size_t)d * HWSZ + p2));
#pragma unroll
        for (int c = 0; c < 48; c++) {
            float a = A[c][d];
            a0[c] = fmaf(a, vf.x, a0[c]);
            a1[c] = fmaf(a, vf.y, a1[c]);
        }
    }
    size_t ob = ((size_t)b * CDIM + h * CHD) * HWSZ + p2;
#pragma unroll
    for (int c = 0; c < 48; c++)
        *(uint32_t*)(o16 + ob + (size_t)c * HWSZ) =
            pack2h(__float2half(a0[c]), __float2half(a1[c]));
}

// ---------------------------------------------------------------------------
// launch
// ---------------------------------------------------------------------------
constexpr int SMEM_CONV = 3 * 28672 + 128;   // TERMS=1: 3 stages x 28KB, 2 CTAs/SM
constexpr int SMEM_PW   = 2 * 40960 + 128;   // TERMS=2: 2 stages x 40KB, 2 CTAs/SM

extern "C" void kernel_launch(void* const* d_in, const int* in_sizes, int n_in,
                              void* d_out, int out_size) {
    const float* x     = (const float*)d_in[0];
    const float* cn    = (const float*)d_in[1];
    const float* w1    = (const float*)d_in[2];
    const float* w3    = (const float*)d_in[3];
    const float* qkvw  = (const float*)d_in[4];
    const float* dww   = (const float*)d_in[5];
    const float* projw = (const float*)d_in[6];
    const float* temp  = (const float*)d_in[7];

    __half *wc, *wqh, *wql, *wph, *wpl, *ch, *chL, *chR, *x16, *cnf, *q1h, *q2h;
    float *coef, *gpart, *attn;
    cudaGetSymbolAddress((void**)&wc,  g_wc);
    cudaGetSymbolAddress((void**)&wqh, g_wq_h);  cudaGetSymbolAddress((void**)&wql, g_wq_l);
    cudaGetSymbolAddress((void**)&wph, g_wp_h);  cudaGetSymbolAddress((void**)&wpl, g_wp_l);
    cudaGetSymbolAddress((void**)&ch,  g_ch);
    cudaGetSymbolAddress((void**)&chL, g_chL);
    cudaGetSymbolAddress((void**)&chR, g_chR);
    cudaGetSymbolAddress((void**)&x16, g_x16);
    cudaGetSymbolAddress((void**)&cnf, g_cnf);
    cudaGetSymbolAddress((void**)&q1h, g_q1h);
    cudaGetSymbolAddress((void**)&q2h, g_q2h);
    cudaGetSymbolAddress((void**)&coef, g_coef);
    cudaGetSymbolAddress((void**)&gpart, g_gpart);
    cudaGetSymbolAddress((void**)&attn, g_attn);

    cudaFuncSetAttribute(mm_kernel<1728, 9, 1, true>,
                         cudaFuncAttributeMaxDynamicSharedMemorySize, SMEM_CONV);
    cudaFuncSetAttribute(mm_kernel<192, 1, 2, true>,
                         cudaFuncAttributeMaxDynamicSharedMemorySize, SMEM_PW);
    cudaFuncSetAttribute(mm_kernel<192, 1, 2, false>,
                         cudaFuncAttributeMaxDynamicSharedMemorySize, SMEM_PW);

    const int NACT4 = BATCH * CDIM * HWSZ / 4;

    // weight prep
    foldw_kernel<<<256 * 1728 / 256, 256>>>(w3, w1, wc);
    splitw_kernel<<<640 * 192 / 256, 256>>>(qkvw, wqh, wql, 3 * CDIM);
    splitw_kernel<<<256 * 192 / 256, 256>>>(projw, wph, wpl, CDIM);

    // cn branch: fp16 + shifted copies, folded 3x3 conv -> fp16 cnf (M=96 x2)
    asplit_shift_h_kernel<<<(NACT4 + 255) / 256, 256>>>(cn, ch, chL, chR, NACT4);
    mm_kernel<1728, 9, 1, true><<<dim3(128, 2, BATCH), 256, SMEM_CONV>>>(
        ch, chL, chR, wc, wc, cnf, CDIM);

    // qkv 1x1 -> fp16 (M=96 x6 = 576, exact)
    ahalf_kernel<<<(NACT4 + 255) / 256, 256>>>(x, x16, NACT4);
    mm_kernel<192, 1, 2, true><<<dim3(128, 6, BATCH), 256, SMEM_PW>>>(
        x16, x16, x16, wqh, wql, q1h, 3 * CDIM);

    // depthwise 3x3 (fp16 in/out, 8 px/thread)
    dwconv3h_kernel<<<dim3(HWSZ / 2048, 3 * CDIM, BATCH), 256>>>(q1h, dww, q2h);

    // attention chain (fp16 streams)
    stats_kernel<<<BATCH * CDIM, 256>>>(q2h, cnf, coef);
    gram_kernel<<<dim3(BATCH * NHEAD, SPLIT), 256>>>(q2h, cnf, coef, gpart);
    softmax_kernel<<<BATCH * NHEAD, 256>>>(gpart, temp, attn);
    apply_kernel<<<dim3(32, NHEAD, BATCH), 256>>>(q2h, attn, x16);   // av -> x16

    // projection 1x1 -> fp32 output (M=96 x2 = 192, exact)
    mm_kernel<192, 1, 2, false><<<dim3(128, 2, BATCH), 256, SMEM_PW>>>(
        x16, x16, x16, wph, wpl, (float*)d_out, CDIM);
}

// round 11
// speedup vs baseline: 10.0795x; 1.2206x over previous
#include <cuda_runtime.h>
#include <cuda_fp16.h>
#include <cstdint>

#define EPSN 1e-12f

constexpr int BATCH = 8;
constexpr int CDIM  = 192;
constexpr int HWSZ  = 16384;   // 128*128
constexpr int NHEAD = 4;
constexpr int CHD   = 48;
constexpr int SPLIT = 8;
constexpr float WSC  = 64.f;
constexpr float IWSC = 1.f / 64.f;

// ---------------------------------------------------------------------------
// helpers
// ---------------------------------------------------------------------------
__device__ __forceinline__ uint32_t s2u(const void* p) {
    uint32_t a;
    asm("{ .reg .u64 t; cvta.to.shared.u64 t, %1; cvt.u32.u64 %0, t; }" : "=r"(a) : "l"(p));
    return a;
}
#define SWZ(x) ((x) ^ (((x) >> 3) & 0x70))

__device__ __forceinline__ void cpa16(uint32_t dst, const void* src, int srcsize) {
    asm volatile("cp.async.cg.shared.global [%0], [%1], 16, %2;"
                 :: "r"(dst), "l"(src), "r"(srcsize));
}
#define CPA_COMMIT() asm volatile("cp.async.commit_group;" ::: "memory")
#define CPA_WAIT(n)  asm volatile("cp.async.wait_group %0;" :: "n"(n) : "memory")

__device__ __forceinline__ void ldsm4(uint32_t* r, uint32_t addr) {
    asm volatile("ldmatrix.sync.aligned.m8n8.x4.shared.b16 {%0,%1,%2,%3}, [%4];"
        : "=r"(r[0]), "=r"(r[1]), "=r"(r[2]), "=r"(r[3]) : "r"(addr));
}
__device__ __forceinline__ void ldsm4t(uint32_t* r, uint32_t addr) {
    asm volatile("ldmatrix.sync.aligned.m8n8.x4.trans.shared.b16 {%0,%1,%2,%3}, [%4];"
        : "=r"(r[0]), "=r"(r[1]), "=r"(r[2]), "=r"(r[3]) : "r"(addr));
}
__device__ __forceinline__ void mma16816h(float* d, const uint32_t* a, const uint32_t* b) {
    asm volatile("mma.sync.aligned.m16n8k16.row.col.f32.f16.f16.f32 "
        "{%0,%1,%2,%3}, {%4,%5,%6,%7}, {%8,%9}, {%0,%1,%2,%3};"
        : "+f"(d[0]), "+f"(d[1]), "+f"(d[2]), "+f"(d[3])
        : "r"(a[0]), "r"(a[1]), "r"(a[2]), "r"(a[3]), "r"(b[0]), "r"(b[1]));
}
__device__ __forceinline__ uint32_t pack2h(__half a, __half b) {
    return (uint32_t)__half_as_ushort(a) | ((uint32_t)__half_as_ushort(b) << 16);
}

// ---------------------------------------------------------------------------
// scratch buffers (all intermediate streams fp16)
// ---------------------------------------------------------------------------
__device__ __half g_wc[256 * 1728];                     // folded 3x3, fp16, x64
__device__ __half g_wq_h[640 * 192], g_wq_l[640 * 192]; // qkv 1x1 fp16 hi/lo, x64
__device__ __half g_wp_h[256 * 192], g_wp_l[256 * 192]; // proj 1x1 fp16 hi/lo, x64
__device__ __half g_ch [(size_t)BATCH * CDIM * HWSZ];   // cn fp16 (center)
__device__ __half g_chL[(size_t)BATCH * CDIM * HWSZ];
__device__ __half g_chR[(size_t)BATCH * CDIM * HWSZ];
__device__ __half g_x16[(size_t)BATCH * CDIM * HWSZ];   // x fp16 / later av fp16
__device__ __half g_cnf[(size_t)BATCH * CDIM * HWSZ];       // conv out fp16
__device__ __half g_q1h[(size_t)BATCH * 3 * CDIM * HWSZ];   // qkv after 1x1, fp16
__device__ __half g_q2h[(size_t)BATCH * 3 * CDIM * HWSZ];   // qkv after dw, fp16
__device__ float g_coef[BATCH * CDIM * 3];
__device__ float g_gpart[BATCH * NHEAD * SPLIT * CHD * CHD];
__device__ float g_attn[BATCH * NHEAD * CHD * CHD];

// ---------------------------------------------------------------------------
// weight prep
// ---------------------------------------------------------------------------
__global__ void foldw_kernel(const float* __restrict__ w3, const float* __restrict__ w1,
                             __half* __restrict__ w) {
    int idx = blockIdx.x * 256 + threadIdx.x;          // 256*1728
    int co = idx / 1728, r = idx % 1728;
    int t = r / 192, cj = r % 192;
    float s = 0.f;
    if (co < CDIM)
        for (int ci = 0; ci < CDIM; ci++)
            s = fmaf(w3[(co * CDIM + ci) * 9 + t], w1[ci * CDIM + cj], s);
    w[idx] = __float2half(s * WSC);
}

__global__ void splitw_kernel(const float* __restrict__ w, __half* __restrict__ wh,
                              __half* __restrict__ wl, int validRows) {
    int idx = blockIdx.x * 256 + threadIdx.x;
    int row = idx / CDIM;
    float v = (row < validRows) ? w[(size_t)row * CDIM + (idx % CDIM)] * WSC : 0.f;
    __half h = __float2half(v);
    wh[idx] = h;
    wl[idx] = __float2half(v - __half2float(h));
}

__global__ __launch_bounds__(256) void ahalf_kernel(
    const float* __restrict__ in, __half* __restrict__ o, int n4) {
    int i = blockIdx.x * 256 + threadIdx.x;
    if (i >= n4) return;
    float4 v = ((const float4*)in)[i];
    ((uint2*)o)[i] = make_uint2(pack2h(__float2half(v.x), __float2half(v.y)),
                                pack2h(__float2half(v.z), __float2half(v.w)));
}

__global__ __launch_bounds__(256) void asplit_shift_h_kernel(
    const float* __restrict__ in,
    __half* __restrict__ oh, __half* __restrict__ ohL, __half* __restrict__ ohR, int n4) {
    int i = blockIdx.x * 256 + threadIdx.x;
    if (i >= n4) return;
    int p = i * 4;
    int col = p & 127;
    float4 v = ((const float4*)in)[i];
    float vnext = (col == 124) ? 0.f : in[p + 4];
    float vprev = (col == 0)   ? 0.f : in[p - 1];
    __half h0 = __float2half(v.x), h1 = __float2half(v.y);
    __half h2 = __float2half(v.z), h3 = __float2half(v.w);
    __half hn = __float2half(vnext), hp = __float2half(vprev);
    ((uint2*)oh)[i]  = make_uint2(pack2h(h0, h1), pack2h(h2, h3));
    ((uint2*)ohL)[i] = make_uint2(pack2h(h1, h2), pack2h(h3, hn));
    ((uint2*)ohR)[i] = make_uint2(pack2h(hp, h0), pack2h(h1, h2));
}

// ---------------------------------------------------------------------------
// fp16 HMMA GEMM, multi-stage cp.async pipeline.
//   CTA tile M=96 x N=128 (8 warps = 2m x 4n; warp tile 48x32), K-chunk 64.
//   TERMS==1: C = A B          (stage 28KB), 3 stages
//   TERMS==2: C = Ah B + Al B  (stage 40KB), 2 stages
//   Weights pre-scaled x64; epilogue x 1/64. fp32 accum. HOUT: fp16 out.
// ---------------------------------------------------------------------------
template <int KTOT, int TAPS, int TERMS, bool HOUT>
__global__ __launch_bounds__(256, 2) void mm_kernel(
    const __half* __restrict__ xc, const __half* __restrict__ xL,
    const __half* __restrict__ xR,
    const __half* __restrict__ wh, const __half* __restrict__ wl,
    void* __restrict__ outv, int Cout) {
    constexpr int ATSZ   = 12288;                 // one A term: 96 rows x 128B
    constexpr int BOFF   = TERMS * ATSZ;
    constexpr int SSZ    = BOFF + 16384;
    constexpr int STAGES = (TERMS == 2) ? 2 : 3;
    extern __shared__ char sraw[];
    char* sal = (char*)((((uintptr_t)sraw) + 127) & ~(uintptr_t)127);
    const uint32_t sb = s2u(sal);
    const int tid = threadIdx.x, lane = tid & 31, wid = tid >> 5;
    const int n0 = blockIdx.x * 128, m0 = blockIdx.y * 96, b = blockIdx.z;
    const int wm = wid >> 2, wn = wid & 3;        // 2m x 4n warp grid
    const int y = n0 >> 7;
    const int lr = lane & 15, lc = lane >> 4;
    constexpr int NCH = KTOT / 64;

    auto load_chunk = [&](int cc) {
        const int k0 = cc * 64;
        const int t = (TAPS == 9) ? (k0 / 192) : 0;
        const int ci0 = k0 - t * 192;
        const int dy = (TAPS == 9) ? (t / 3 - 1) : 0;
        const int dx = (TAPS == 9) ? (t % 3 - 1) : 0;
        const int yy = y + dy;
        const bool rowok = (TAPS == 1) || ((unsigned)yy < 128u);
        const int ys = rowok ? yy : y;
        const uint32_t stg = sb + (uint32_t)(cc % STAGES) * SSZ;
#pragma unroll
        for (int i = 0; i < 3 * TERMS; i++) {
            int e = tid + (i << 8);
            int dt = e / 768, rr = e - dt * 768;
            int ck = rr & 7, r = rr >> 3;
            const __half* src = (dt ? wl : wh) + (size_t)(m0 + r) * KTOT + k0 + ck * 8;
            cpa16(stg + dt * ATSZ + SWZ(r * 128 + ck * 16), src, 16);
        }
        const __half* bp = (dx == 0) ? xc : (dx > 0 ? xL : xR);
        const int sz = rowok ? 16 : 0;
#pragma unroll
        for (int i = 0; i < 4; i++) {
            int e = tid + (i << 8);
            int nc = e & 15, k = (e >> 4) & 63;
            int n = nc * 8;
            const __half* src = bp + ((size_t)b * CDIM + ci0 + k) * HWSZ + ys * 128 + n;
            cpa16(stg + BOFF + (nc >> 3) * 8192 + SWZ(k * 128 + (n & 63) * 2), src, sz);
        }
        CPA_COMMIT();
    };

    float acc[3][4][4];
#pragma unroll
    for (int i = 0; i < 3; i++)
#pragma unroll
        for (int j = 0; j < 4; j++)
#pragma unroll
            for (int q = 0; q < 4; q++) acc[i][j][q] = 0.f;

#pragma unroll
    for (int i = 0; i < STAGES - 1 && i < NCH; i++) load_chunk(i);

    for (int cc = 0; cc < NCH; cc++) {
        if (cc + STAGES - 1 < NCH) load_chunk(cc + STAGES - 1);
        int pend = ((cc + STAGES - 1 < NCH) ? (STAGES - 1) : (NCH - 1 - cc));
        if (pend >= 2)      CPA_WAIT(2);
        else if (pend == 1) CPA_WAIT(1);
        else                CPA_WAIT(0);
        __syncthreads();
        const uint32_t stg = sb + (uint32_t)(cc % STAGES) * SSZ;

#pragma unroll
        for (int ks = 0; ks < 4; ks++) {
            uint32_t ah[3][4], alo[3][4];
#pragma unroll
            for (int mf = 0; mf < 3; mf++) {
                uint32_t ao = SWZ((wm * 48 + mf * 16 + lr) * 128 + ks * 32 + lc * 16);
                ldsm4(ah[mf], stg + ao);
                if (TERMS == 2) ldsm4(alo[mf], stg + ATSZ + ao);
            }
#pragma unroll
            for (int gg = 0; gg < 2; gg++) {
                int cb = wn * 32 + gg * 16;
                uint32_t bh[4];
                uint32_t bo = BOFF + (cb >> 6) * 8192 +
                              SWZ((ks * 16 + lr) * 128 + (cb & 63) * 2 + lc * 16);
                ldsm4t(bh, stg + bo);
#pragma unroll
                for (int mf = 0; mf < 3; mf++) {
                    mma16816h(acc[mf][2 * gg],     ah[mf], bh);
                    mma16816h(acc[mf][2 * gg + 1], ah[mf], bh + 2);
                    if (TERMS == 2) {
                        mma16816h(acc[mf][2 * gg],     alo[mf], bh);
                        mma16816h(acc[mf][2 * gg + 1], alo[mf], bh + 2);
                    }
                }
            }
        }
        __syncthreads();
    }

#pragma unroll
    for (int mf = 0; mf < 3; mf++) {
        int mb = m0 + wm * 48 + mf * 16 + (lane >> 2);
#pragma unroll
        for (int nb = 0; nb < 4; nb++) {
            int nn = n0 + wn * 32 + nb * 8 + (lane & 3) * 2;
            if (HOUT) {
                __half* out = (__half*)outv;
                *(uint32_t*)(out + ((size_t)b * Cout + mb) * HWSZ + nn) =
                    pack2h(__float2half(acc[mf][nb][0] * IWSC),
                           __float2half(acc[mf][nb][1] * IWSC));
                *(uint32_t*)(out + ((size_t)b * Cout + mb + 8) * HWSZ + nn) =
                    pack2h(__float2half(acc[mf][nb][2] * IWSC),
                           __float2half(acc[mf][nb][3] * IWSC));
            } else {
                float* out = (float*)outv;
                *(float2*)(out + ((size_t)b * Cout + mb) * HWSZ + nn) =
                    make_float2(acc[mf][nb][0] * IWSC, acc[mf][nb][1] * IWSC);
                *(float2*)(out + ((size_t)b * Cout + mb + 8) * HWSZ + nn) =
                    make_float2(acc[mf][nb][2] * IWSC, acc[mf][nb][3] * IWSC);
            }
        }
    }
}

// ---------------------------------------------------------------------------
// depthwise 3x3 on fp16, 8 px/thread, fp32 math
// ---------------------------------------------------------------------------
__global__ __launch_bounds__(256) void dwconv3h_kernel(
    const __half* __restrict__ in, const float* __restrict__ wdw,
    __half* __restrict__ out) {
    int c = blockIdx.y, b = blockIdx.z;
    int p8 = (blockIdx.x * 256 + threadIdx.x) * 8;
    int y = p8 >> 7, x = p8 & 127;
    const __half* src = in + ((size_t)b * (3 * CDIM) + c) * HWSZ;
    float w[9];
#pragma unroll
    for (int i = 0; i < 9; i++) w[i] = wdw[c * 9 + i];
    float a[8];
#pragma unroll
    for (int j = 0; j < 8; j++) a[j] = 0.f;
#pragma unroll
    for (int r = -1; r <= 1; r++) {
        int yy = y + r;
        if ((unsigned)yy >= 128u) continue;
        const __half* rp = src + (yy << 7);
        uint4 m4 = *(const uint4*)(rp + x);
        const __half* mh = (const __half*)&m4;
        float v[10];
        v[0] = (x > 0) ? __half2float(rp[x - 1]) : 0.f;
#pragma unroll
        for (int j = 0; j < 8; j++) v[j + 1] = __half2float(mh[j]);
        v[9] = (x + 8 < 128) ? __half2float(rp[x + 8]) : 0.f;
        int wb = (r + 1) * 3;
#pragma unroll
        for (int j = 0; j < 8; j++)
            a[j] = fmaf(w[wb], v[j], fmaf(w[wb + 1], v[j + 1], fmaf(w[wb + 2], v[j + 2], a[j])));
    }
    uint4 o4;
    __half* oh = (__half*)&o4;
#pragma unroll
    for (int j = 0; j < 8; j++) oh[j] = __float2half(a[j]);
    *(uint4*)(out + ((size_t)b * (3 * CDIM) + c) * HWSZ + p8) = o4;
}

// ---------------------------------------------------------------------------
// per-row norms (fp16 in, fp32 sums) -> normalization coefficients
// ---------------------------------------------------------------------------
__global__ __launch_bounds__(256) void stats_kernel(
    const __half* __restrict__ qkv, const __half* __restrict__ cnf,
    float* __restrict__ coef) {
    int rowi = blockIdx.x;
    int b = rowi / CDIM, c = rowi % CDIM;
    const __half2* q  = (const __half2*)(qkv + ((size_t)b * (3 * CDIM) + c) * HWSZ);
    const __half2* kk = (const __half2*)(qkv + ((size_t)b * (3 * CDIM) + CDIM + c) * HWSZ);
    const __half2* cn = (const __half2*)(cnf + (size_t)rowi * HWSZ);
    float sq = 0.f, sk = 0.f, sc = 0.f, sqc = 0.f;
    for (int i = threadIdx.x; i < HWSZ / 2; i += 256) {
        float2 qv = __half22float2(q[i]);
        float2 kv = __half22float2(kk[i]);
        float2 cv = __half22float2(cn[i]);
        sq  = fmaf(qv.x, qv.x, fmaf(qv.y, qv.y, sq));
        sk  = fmaf(kv.x, kv.x, fmaf(kv.y, kv.y, sk));
        sc  = fmaf(cv.x, cv.x, fmaf(cv.y, cv.y, sc));
        sqc = fmaf(qv.x, cv.x, fmaf(qv.y, cv.y, sqc));
    }
#pragma unroll
    for (int o = 16; o; o >>= 1) {
        sq += __shfl_xor_sync(~0u, sq, o); sk += __shfl_xor_sync(~0u, sk, o);
        sc += __shfl_xor_sync(~0u, sc, o); sqc += __shfl_xor_sync(~0u, sqc, o);
    }
    __shared__ float r4[4][8];
    int wid = threadIdx.x >> 5, lane = threadIdx.x & 31;
    if (lane == 0) { r4[0][wid] = sq; r4[1][wid] = sk; r4[2][wid] = sc; r4[3][wid] = sqc; }
    __syncthreads();
    if (threadIdx.x == 0) {
        float SQ = 0, SK = 0, SC = 0, SQC = 0;
        for (int i = 0; i < 8; i++) { SQ += r4[0][i]; SK += r4[1][i]; SC += r4[2][i]; SQC += r4[3][i]; }
        float a  = fmaxf(sqrtf(SQ), EPSN);
        float bb = fmaxf(sqrtf(SC), EPSN);
        float s2 = SQ / (a * a) + 2.f * SQC / (a * bb) + SC / (bb * bb);
        float s  = fmaxf(sqrtf(s2), EPSN);
        float kn = fmaxf(sqrtf(SK), EPSN);
        coef[rowi * 3 + 0] = 1.f / (a * s);
        coef[rowi * 3 + 1] = 1.f / (bb * s);
        coef[rowi * 3 + 2] = 1.f / kn;
    }
}

// ---------------------------------------------------------------------------
// gram via HMMA: gpart[bh,sp][c][d] = sum_s (a_c q + b_c cn)[s] * (g_d k)[s]
//   A = q-hat [c][s] tiles (ldsm), B = k-hat^T [s][d] tiles (ldsm.trans).
//   Padded to 64x64; 8 warps = 4m x 2(n32). fp16 operands, fp32 acc.
// ---------------------------------------------------------------------------
__global__ __launch_bounds__(256) void gram_mma_kernel(
    const __half* __restrict__ qkv, const __half* __restrict__ cnf,
    const float* __restrict__ coef, float* __restrict__ gpart) {
    __shared__ __align__(16) char QS[8192];   // [c 64][s 64] halves (rows 48.. unused)
    __shared__ __align__(16) char KS[8192];   // [s 64][d 64] halves (cols 48.. unused)
    __shared__ float al[48], be[48], ga[48];
    int bh = blockIdx.x, sp = blockIdx.y;
    int b = bh >> 2, h = bh & 3;
    int tid = threadIdx.x, lane = tid & 31, wid = tid >> 5;
    int wm = wid >> 1, wn = wid & 1;
    int lr = lane & 15, lc = lane >> 4;
    uint32_t qs = s2u(QS), ksm = s2u(KS);
    if (tid < 48) {
        int rw = b * CDIM + h * CHD + tid;
        al[tid] = coef[rw * 3 + 0]; be[tid] = coef[rw * 3 + 1]; ga[tid] = coef[rw * 3 + 2];
    }
    const __half* qb = qkv + ((size_t)b * (3 * CDIM) + h * CHD) * HWSZ;
    const __half* kb = qkv + ((size_t)b * (3 * CDIM) + CDIM + h * CHD) * HWSZ;
    const __half* cb = cnf + ((size_t)b * CDIM + h * CHD) * HWSZ;
    float acc[4][4] = {};
    __syncthreads();
    int send = sp * 2048 + 2048;
    for (int s0 = sp * 2048; s0 < send; s0 += 64) {
        // fill: 48 rows x 32 half2 (q-hat into QS rows; k-hat transposed into KS)
        for (int e = tid; e < 1536; e += 256) {
            int r = e >> 5, sc = (e & 31) * 2;
            size_t off = (size_t)r * HWSZ + s0 + sc;
            float2 q2 = __half22float2(*(const __half2*)(qb + off));
            float2 c2 = __half22float2(*(const __half2*)(cb + off));
            *(uint32_t*)(QS + SWZ(r * 128 + sc * 2)) =
                pack2h(__float2half(al[r] * q2.x + be[r] * c2.x),
                       __float2half(al[r] * q2.y + be[r] * c2.y));
            float2 k2 = __half22float2(*(const __half2*)(kb + off));
            *(__half*)(KS + SWZ(sc * 128 + r * 2))       = __float2half(ga[r] * k2.x);
            *(__half*)(KS + SWZ((sc + 1) * 128 + r * 2)) = __float2half(ga[r] * k2.y);
        }
        __syncthreads();
#pragma unroll
        for (int ks = 0; ks < 4; ks++) {
            uint32_t af[4];
            ldsm4(af, qs + SWZ((wm * 16 + lr) * 128 + ks * 32 + lc * 16));
#pragma unroll
            for (int g = 0; g < 2; g++) {
                uint32_t bf[4];
                ldsm4t(bf, ksm + SWZ((ks * 16 + lr) * 128 + (wn * 32 + g * 16) * 2 + lc * 16));
                mma16816h(acc[2 * g],     af, bf);
                mma16816h(acc[2 * g + 1], af, bf + 2);
            }
        }
        __syncthreads();
    }
    if (wm < 3) {
        int c = wm * 16 + (lane >> 2);
#pragma unroll
        for (int nb = 0; nb < 4; nb++) {
            int d0 = wn * 32 + nb * 8;
            if (d0 < 48) {
                int dd = d0 + (lane & 3) * 2;
                float* g0 = gpart + ((size_t)(bh * SPLIT + sp) * CHD + c) * CHD + dd;
                g0[0] = acc[nb][0]; g0[1] = acc[nb][1];
                float* g1 = gpart + ((size_t)(bh * SPLIT + sp) * CHD + c + 8) * CHD + dd;
                g1[0] = acc[nb][2]; g1[1] = acc[nb][3];
            }
        }
    }
}

__global__ __launch_bounds__(256) void softmax_kernel(
    const float* __restrict__ gpart, const float* __restrict__ temp,
    float* __restrict__ attn) {
    __shared__ float S[48][49];
    int bh = blockIdx.x;
    float T = temp[bh & 3];
    int tid = threadIdx.x;
    for (int e = tid; e < CHD * CHD; e += 256) {
        int c = e / CHD, d = e - c * CHD;
        float g = 0.f;
#pragma unroll
        for (int sp = 0; sp < SPLIT; sp++)
            g += gpart[((bh * SPLIT + sp) * CHD + c) * CHD + d];
        S[c][d] = g * T;
    }
    __syncthreads();
    int wid = tid >> 5, lane = tid & 31;
    for (int r = wid; r < 48; r += 8) {
        float v1 = S[r][lane];
        float v2 = (lane < 16) ? S[r][32 + lane] : -1e30f;
        float m = fmaxf(v1, v2);
#pragma unroll
        for (int o = 16; o; o >>= 1) m = fmaxf(m, __shfl_xor_sync(~0u, m, o));
        float e1 = expf(v1 - m);
        float e2 = (lane < 16) ? expf(v2 - m) : 0.f;
        float s = e1 + e2;
#pragma unroll
        for (int o = 16; o; o >>= 1) s += __shfl_xor_sync(~0u, s, o);
        float inv = 1.f / s;
        attn[bh * (CHD * CHD) + r * CHD + lane] = e1 * inv;
        if (lane < 16) attn[bh * (CHD * CHD) + r * CHD + 32 + lane] = e2 * inv;
    }
}

// ---------------------------------------------------------------------------
// apply via HMMA: out[c][s] = sum_d attn[c][d] v[d][s], per (b,h), n-tile 128.
//   A = attn x64 split hi/lo [c][d] (exact); B = v tile [d][s] via cp.async.
//   K=48 = 3 exact k-steps, one-shot. 8 warps n16 each. fp16 out.
// ---------------------------------------------------------------------------
__global__ __launch_bounds__(256) void apply_mma_kernel(
    const __half* __restrict__ qkv, const float* __restrict__ attn,
    __half* __restrict__ o16) {
    __shared__ __align__(16) char ASH[6144];   // attn hi [48][64 halves]
    __shared__ __align__(16) char ASL[6144];   // attn lo
    __shared__ __align__(16) char BS[12288];   // v [48][128] as two 64-col halves
    int n0 = blockIdx.x * 128, h = blockIdx.y, b = blockIdx.z;
    int tid = threadIdx.x, lane = tid & 31, wid = tid >> 5;
    int lr = lane & 15, lc = lane >> 4;
    uint32_t ash = s2u(ASH), asl = s2u(ASL), bsm = s2u(BS);

    const float* ab = attn + (size_t)(b * NHEAD + h) * (CHD * CHD);
    for (int e = tid; e < CHD * CHD; e += 256) {
        int r = e / CHD, d = e - r * CHD;
        float a = ab[e] * WSC;
        __half hh = __float2half(a);
        uint32_t off = SWZ(r * 128 + d * 2);
        *(__half*)(ASH + off) = hh;
        *(__half*)(ASL + off) = __float2half(a - __half2float(hh));
    }
    const __half* vb = qkv + ((size_t)b * (3 * CDIM) + 2 * CDIM + h * CHD) * HWSZ;
#pragma unroll
    for (int i = 0; i < 3; i++) {
        int e = tid + (i << 8);
        int nc = e & 15, d = e >> 4;
        cpa16(bsm + (nc >> 3) * 6144 + SWZ(d * 128 + (nc & 7) * 16),
              vb + (size_t)d * HWSZ + n0 + nc * 8, 16);
    }
    CPA_COMMIT(); CPA_WAIT(0);
    __syncthreads();

    int wn = wid;                // n16 per warp
    float acc[3][2][4];
#pragma unroll
    for (int i = 0; i < 3; i++)
#pragma unroll
        for (int j = 0; j < 2; j++)
#pragma unroll
            for (int q = 0; q < 4; q++) acc[i][j][q] = 0.f;

#pragma unroll
    for (int ks = 0; ks < 3; ks++) {
        int col = wn * 16;
        uint32_t bf[4];
        ldsm4t(bf, bsm + (col >> 6) * 6144 + SWZ((ks * 16 + lr) * 128 + (col & 63) * 2 + lc * 16));
#pragma unroll
        for (int mf = 0; mf < 3; mf++) {
            uint32_t ah4[4], al4[4];
            uint32_t ao = SWZ((mf * 16 + lr) * 128 + ks * 32 + lc * 16);
            ldsm4(ah4, ash + ao);
            ldsm4(al4, asl + ao);
            mma16816h(acc[mf][0], ah4, bf);
            mma16816h(acc[mf][0], al4, bf);
            mma16816h(acc[mf][1], ah4, bf + 2);
            mma16816h(acc[mf][1], al4, bf + 2);
        }
    }

#pragma unroll
    for (int mf = 0; mf < 3; mf++) {
        int c = mf * 16 + (lane >> 2);
        size_t rb = ((size_t)b * CDIM + h * CHD + c) * HWSZ;
#pragma unroll
        for (int nb = 0; nb < 2; nb++) {
            int s = n0 + wn * 16 + nb * 8 + (lane & 3) * 2;
            *(uint32_t*)(o16 + rb + s) =
                pack2h(__float2half(acc[mf][nb][0] * IWSC),
                       __float2half(acc[mf][nb][1] * IWSC));
            *(uint32_t*)(o16 + rb + 8 * HWSZ + s) =
                pack2h(__float2half(acc[mf][nb][2] * IWSC),
                       __float2half(acc[mf][nb][3] * IWSC));
        }
    }
}

// ---------------------------------------------------------------------------
// launch
// ---------------------------------------------------------------------------
constexpr int SMEM_1T = 3 * 28672 + 128;   // TERMS=1: 3 stages x 28KB
constexpr int SMEM_2T = 2 * 40960 + 128;   // TERMS=2: 2 stages x 40KB

extern "C" void kernel_launch(void* const* d_in, const int* in_sizes, int n_in,
                              void* d_out, int out_size) {
    const float* x     = (const float*)d_in[0];
    const float* cn    = (const float*)d_in[1];
    const float* w1    = (const float*)d_in[2];
    const float* w3    = (const float*)d_in[3];
    const float* qkvw  = (const float*)d_in[4];
    const float* dww   = (const float*)d_in[5];
    const float* projw = (const float*)d_in[6];
    const float* temp  = (const float*)d_in[7];

    __half *wc, *wqh, *wql, *wph, *wpl, *ch, *chL, *chR, *x16, *cnf, *q1h, *q2h;
    float *coef, *gpart, *attn;
    cudaGetSymbolAddress((void**)&wc,  g_wc);
    cudaGetSymbolAddress((void**)&wqh, g_wq_h);  cudaGetSymbolAddress((void**)&wql, g_wq_l);
    cudaGetSymbolAddress((void**)&wph, g_wp_h);  cudaGetSymbolAddress((void**)&wpl, g_wp_l);
    cudaGetSymbolAddress((void**)&ch,  g_ch);
    cudaGetSymbolAddress((void**)&chL, g_chL);
    cudaGetSymbolAddress((void**)&chR, g_chR);
    cudaGetSymbolAddress((void**)&x16, g_x16);
    cudaGetSymbolAddress((void**)&cnf, g_cnf);
    cudaGetSymbolAddress((void**)&q1h, g_q1h);
    cudaGetSymbolAddress((void**)&q2h, g_q2h);
    cudaGetSymbolAddress((void**)&coef, g_coef);
    cudaGetSymbolAddress((void**)&gpart, g_gpart);
    cudaGetSymbolAddress((void**)&attn, g_attn);

    cudaFuncSetAttribute(mm_kernel<1728, 9, 1, true>,
                         cudaFuncAttributeMaxDynamicSharedMemorySize, SMEM_1T);
    cudaFuncSetAttribute(mm_kernel<192, 1, 1, true>,
                         cudaFuncAttributeMaxDynamicSharedMemorySize, SMEM_1T);
    cudaFuncSetAttribute(mm_kernel<192, 1, 2, true>,
                         cudaFuncAttributeMaxDynamicSharedMemorySize, SMEM_2T);
    cudaFuncSetAttribute(mm_kernel<192, 1, 2, false>,
                         cudaFuncAttributeMaxDynamicSharedMemorySize, SMEM_2T);

    const int NACT4 = BATCH * CDIM * HWSZ / 4;

    // weight prep
    foldw_kernel<<<256 * 1728 / 256, 256>>>(w3, w1, wc);
    splitw_kernel<<<640 * 192 / 256, 256>>>(qkvw, wqh, wql, 3 * CDIM);
    splitw_kernel<<<256 * 192 / 256, 256>>>(projw, wph, wpl, CDIM);

    // cn branch: fp16 + shifted copies, folded 3x3 conv -> fp16 cnf
    asplit_shift_h_kernel<<<(NACT4 + 255) / 256, 256>>>(cn, ch, chL, chR, NACT4);
    mm_kernel<1728, 9, 1, true><<<dim3(128, 2, BATCH), 256, SMEM_1T>>>(
        ch, chL, chR, wc, wc, cnf, CDIM);

    // qkv 1x1: q,k 1-term (rows 0..383, damped path), v 2-term (rows 384..575)
    ahalf_kernel<<<(NACT4 + 255) / 256, 256>>>(x, x16, NACT4);
    mm_kernel<192, 1, 1, true><<<dim3(128, 4, BATCH), 256, SMEM_1T>>>(
        x16, x16, x16, wqh, wqh, q1h, 3 * CDIM);
    mm_kernel<192, 1, 2, true><<<dim3(128, 2, BATCH), 256, SMEM_2T>>>(
        x16, x16, x16, wqh + (size_t)384 * CDIM, wql + (size_t)384 * CDIM,
        q1h + (size_t)384 * HWSZ, 3 * CDIM);

    // depthwise 3x3 (fp16 in/out)
    dwconv3h_kernel<<<dim3(HWSZ / 2048, 3 * CDIM, BATCH), 256>>>(q1h, dww, q2h);

    // attention chain
    stats_kernel<<<BATCH * CDIM, 256>>>(q2h, cnf, coef);
    gram_mma_kernel<<<dim3(BATCH * NHEAD, SPLIT), 256>>>(q2h, cnf, coef, gpart);
    softmax_kernel<<<BATCH * NHEAD, 256>>>(gpart, temp, attn);
    apply_mma_kernel<<<dim3(128, NHEAD, BATCH), 256>>>(q2h, attn, x16);  // av -> x16

    // projection 1x1 -> fp32 output (2-term, first-order path)
    mm_kernel<192, 1, 2, false><<<dim3(128, 2, BATCH), 256, SMEM_2T>>>(
        x16, x16, x16, wph, wpl, (float*)d_out, CDIM);
}

// round 12
// speedup vs baseline: 10.6267x; 1.0543x over previous
#include <cuda_runtime.h>
#include <cuda_fp16.h>
#include <cstdint>

#define EPSN 1e-12f

constexpr int BATCH = 8;
constexpr int CDIM  = 192;
constexpr int HWSZ  = 16384;   // 128*128
constexpr int NHEAD = 4;
constexpr int CHD   = 48;
constexpr int SPLIT = 8;
constexpr float WSC  = 64.f;
constexpr float IWSC = 1.f / 64.f;

// ---------------------------------------------------------------------------
// helpers
// ---------------------------------------------------------------------------
__device__ __forceinline__ uint32_t s2u(const void* p) {
    uint32_t a;
    asm("{ .reg .u64 t; cvta.to.shared.u64 t, %1; cvt.u32.u64 %0, t; }" : "=r"(a) : "l"(p));
    return a;
}
#define SWZ(x) ((x) ^ (((x) >> 3) & 0x70))

__device__ __forceinline__ void cpa16(uint32_t dst, const void* src, int srcsize) {
    asm volatile("cp.async.cg.shared.global [%0], [%1], 16, %2;"
                 :: "r"(dst), "l"(src), "r"(srcsize));
}
#define CPA_COMMIT() asm volatile("cp.async.commit_group;" ::: "memory")
#define CPA_WAIT(n)  asm volatile("cp.async.wait_group %0;" :: "n"(n) : "memory")

__device__ __forceinline__ void ldsm4(uint32_t* r, uint32_t addr) {
    asm volatile("ldmatrix.sync.aligned.m8n8.x4.shared.b16 {%0,%1,%2,%3}, [%4];"
        : "=r"(r[0]), "=r"(r[1]), "=r"(r[2]), "=r"(r[3]) : "r"(addr));
}
__device__ __forceinline__ void ldsm4t(uint32_t* r, uint32_t addr) {
    asm volatile("ldmatrix.sync.aligned.m8n8.x4.trans.shared.b16 {%0,%1,%2,%3}, [%4];"
        : "=r"(r[0]), "=r"(r[1]), "=r"(r[2]), "=r"(r[3]) : "r"(addr));
}
__device__ __forceinline__ void mma16816h(float* d, const uint32_t* a, const uint32_t* b) {
    asm volatile("mma.sync.aligned.m16n8k16.row.col.f32.f16.f16.f32 "
        "{%0,%1,%2,%3}, {%4,%5,%6,%7}, {%8,%9}, {%0,%1,%2,%3};"
        : "+f"(d[0]), "+f"(d[1]), "+f"(d[2]), "+f"(d[3])
        : "r"(a[0]), "r"(a[1]), "r"(a[2]), "r"(a[3]), "r"(b[0]), "r"(b[1]));
}
__device__ __forceinline__ uint32_t pack2h(__half a, __half b) {
    return (uint32_t)__half_as_ushort(a) | ((uint32_t)__half_as_ushort(b) << 16);
}

// ---------------------------------------------------------------------------
// scratch buffers
// ---------------------------------------------------------------------------
__device__ __half g_wc[256 * 1728];                   // folded 3x3, fp16, x64
__device__ __half g_wq[640 * 192];                    // qkv 1x1 fp16, x64 (1-term)
__device__ __half g_wp[256 * 192];                    // proj 1x1 fp16, x64 (1-term)
__device__ __half g_ch [(size_t)BATCH * CDIM * HWSZ]; // cn fp16 (center)
__device__ __half g_chL[(size_t)BATCH * CDIM * HWSZ];
__device__ __half g_chR[(size_t)BATCH * CDIM * HWSZ];
__device__ __half g_x16[(size_t)BATCH * CDIM * HWSZ]; // x fp16 / later av fp16
__device__ __half g_cnf[(size_t)BATCH * CDIM * HWSZ];     // conv out fp16
__device__ __half g_q1h[(size_t)BATCH * 3 * CDIM * HWSZ]; // qkv after 1x1
__device__ __half g_q2h[(size_t)BATCH * 3 * CDIM * HWSZ]; // qkv after dw
__device__ float g_part[(size_t)BATCH * 384 * 8 * 4];     // fused stats partials
__device__ float g_coef[BATCH * CDIM * 3];
__device__ float g_gpart[BATCH * NHEAD * SPLIT * CHD * CHD];
__device__ float g_attn[BATCH * NHEAD * CHD * CHD];

// ---------------------------------------------------------------------------
// weight prep
// ---------------------------------------------------------------------------
__global__ void foldw_kernel(const float* __restrict__ w3, const float* __restrict__ w1,
                             __half* __restrict__ w) {
    int idx = blockIdx.x * 256 + threadIdx.x;          // 256*1728
    int co = idx / 1728, r = idx % 1728;
    int t = r / 192, cj = r % 192;
    float s = 0.f;
    if (co < CDIM)
        for (int ci = 0; ci < CDIM; ci++)
            s = fmaf(w3[(co * CDIM + ci) * 9 + t], w1[ci * CDIM + cj], s);
    w[idx] = __float2half(s * WSC);
}

__global__ void whalf_kernel(const float* __restrict__ w, __half* __restrict__ wo,
                             int validRows) {
    int idx = blockIdx.x * 256 + threadIdx.x;
    int row = idx / CDIM;
    float v = (row < validRows) ? w[(size_t)row * CDIM + (idx % CDIM)] * WSC : 0.f;
    wo[idx] = __float2half(v);
}

__global__ __launch_bounds__(256) void ahalf_kernel(
    const float* __restrict__ in, __half* __restrict__ o, int n4) {
    int i = blockIdx.x * 256 + threadIdx.x;
    if (i >= n4) return;
    float4 v = ((const float4*)in)[i];
    ((uint2*)o)[i] = make_uint2(pack2h(__float2half(v.x), __float2half(v.y)),
                                pack2h(__float2half(v.z), __float2half(v.w)));
}

__global__ __launch_bounds__(256) void asplit_shift_h_kernel(
    const float* __restrict__ in,
    __half* __restrict__ oh, __half* __restrict__ ohL, __half* __restrict__ ohR, int n4) {
    int i = blockIdx.x * 256 + threadIdx.x;
    if (i >= n4) return;
    int p = i * 4;
    int col = p & 127;
    float4 v = ((const float4*)in)[i];
    float vnext = (col == 124) ? 0.f : in[p + 4];
    float vprev = (col == 0)   ? 0.f : in[p - 1];
    __half h0 = __float2half(v.x), h1 = __float2half(v.y);
    __half h2 = __float2half(v.z), h3 = __float2half(v.w);
    __half hn = __float2half(vnext), hp = __float2half(vprev);
    ((uint2*)oh)[i]  = make_uint2(pack2h(h0, h1), pack2h(h2, h3));
    ((uint2*)ohL)[i] = make_uint2(pack2h(h1, h2), pack2h(h3, hn));
    ((uint2*)ohR)[i] = make_uint2(pack2h(hp, h0), pack2h(h1, h2));
}

// ---------------------------------------------------------------------------
// fp16 HMMA GEMM, 1-term, 3-stage cp.async pipeline.
//   CTA tile M=96 x N=128 (8 warps = 2m x 4n; warp tile 48x32), K-chunk 64.
//   Weights pre-scaled x64; epilogue x 1/64. fp32 accum. HOUT: fp16 out.
// ---------------------------------------------------------------------------
template <int KTOT, int TAPS, bool HOUT>
__global__ __launch_bounds__(256, 2) void mm_kernel(
    const __half* __restrict__ xc, const __half* __restrict__ xL,
    const __half* __restrict__ xR,
    const __half* __restrict__ wh,
    void* __restrict__ outv, int Cout) {
    constexpr int ATSZ   = 12288;                 // A: 96 rows x 128B
    constexpr int BOFF   = ATSZ;
    constexpr int SSZ    = BOFF + 16384;
    constexpr int STAGES = 3;
    extern __shared__ char sraw[];
    char* sal = (char*)((((uintptr_t)sraw) + 127) & ~(uintptr_t)127);
    const uint32_t sb = s2u(sal);
    const int tid = threadIdx.x, lane = tid & 31, wid = tid >> 5;
    const int n0 = blockIdx.x * 128, m0 = blockIdx.y * 96, b = blockIdx.z;
    const int wm = wid >> 2, wn = wid & 3;        // 2m x 4n warp grid
    const int y = n0 >> 7;
    const int lr = lane & 15, lc = lane >> 4;
    constexpr int NCH = KTOT / 64;

    auto load_chunk = [&](int cc) {
        const int k0 = cc * 64;
        const int t = (TAPS == 9) ? (k0 / 192) : 0;
        const int ci0 = k0 - t * 192;
        const int dy = (TAPS == 9) ? (t / 3 - 1) : 0;
        const int dx = (TAPS == 9) ? (t % 3 - 1) : 0;
        const int yy = y + dy;
        const bool rowok = (TAPS == 1) || ((unsigned)yy < 128u);
        const int ys = rowok ? yy : y;
        const uint32_t stg = sb + (uint32_t)(cc % STAGES) * SSZ;
#pragma unroll
        for (int i = 0; i < 3; i++) {
            int e = tid + (i << 8);
            int ck = e & 7, r = e >> 3;
            const __half* src = wh + (size_t)(m0 + r) * KTOT + k0 + ck * 8;
            cpa16(stg + SWZ(r * 128 + ck * 16), src, 16);
        }
        const __half* bp = (dx == 0) ? xc : (dx > 0 ? xL : xR);
        const int sz = rowok ? 16 : 0;
#pragma unroll
        for (int i = 0; i < 4; i++) {
            int e = tid + (i << 8);
            int nc = e & 15, k = (e >> 4) & 63;
            int n = nc * 8;
            const __half* src = bp + ((size_t)b * CDIM + ci0 + k) * HWSZ + ys * 128 + n;
            cpa16(stg + BOFF + (nc >> 3) * 8192 + SWZ(k * 128 + (n & 63) * 2), src, sz);
        }
        CPA_COMMIT();
    };

    float acc[3][4][4];
#pragma unroll
    for (int i = 0; i < 3; i++)
#pragma unroll
        for (int j = 0; j < 4; j++)
#pragma unroll
            for (int q = 0; q < 4; q++) acc[i][j][q] = 0.f;

#pragma unroll
    for (int i = 0; i < STAGES - 1 && i < NCH; i++) load_chunk(i);

    for (int cc = 0; cc < NCH; cc++) {
        if (cc + STAGES - 1 < NCH) load_chunk(cc + STAGES - 1);
        int pend = ((cc + STAGES - 1 < NCH) ? (STAGES - 1) : (NCH - 1 - cc));
        if (pend >= 2)      CPA_WAIT(2);
        else if (pend == 1) CPA_WAIT(1);
        else                CPA_WAIT(0);
        __syncthreads();
        const uint32_t stg = sb + (uint32_t)(cc % STAGES) * SSZ;

#pragma unroll
        for (int ks = 0; ks < 4; ks++) {
            uint32_t ah[3][4];
#pragma unroll
            for (int mf = 0; mf < 3; mf++)
                ldsm4(ah[mf], stg + SWZ((wm * 48 + mf * 16 + lr) * 128 + ks * 32 + lc * 16));
#pragma unroll
            for (int gg = 0; gg < 2; gg++) {
                int cb = wn * 32 + gg * 16;
                uint32_t bh[4];
                uint32_t bo = BOFF + (cb >> 6) * 8192 +
                              SWZ((ks * 16 + lr) * 128 + (cb & 63) * 2 + lc * 16);
                ldsm4t(bh, stg + bo);
#pragma unroll
                for (int mf = 0; mf < 3; mf++) {
                    mma16816h(acc[mf][2 * gg],     ah[mf], bh);
                    mma16816h(acc[mf][2 * gg + 1], ah[mf], bh + 2);
                }
            }
        }
        __syncthreads();
    }

#pragma unroll
    for (int mf = 0; mf < 3; mf++) {
        int mb = m0 + wm * 48 + mf * 16 + (lane >> 2);
#pragma unroll
        for (int nb = 0; nb < 4; nb++) {
            int nn = n0 + wn * 32 + nb * 8 + (lane & 3) * 2;
            if (HOUT) {
                __half* out = (__half*)outv;
                *(uint32_t*)(out + ((size_t)b * Cout + mb) * HWSZ + nn) =
                    pack2h(__float2half(acc[mf][nb][0] * IWSC),
                           __float2half(acc[mf][nb][1] * IWSC));
                *(uint32_t*)(out + ((size_t)b * Cout + mb + 8) * HWSZ + nn) =
                    pack2h(__float2half(acc[mf][nb][2] * IWSC),
                           __float2half(acc[mf][nb][3] * IWSC));
            } else {
                float* out = (float*)outv;
                *(float2*)(out + ((size_t)b * Cout + mb) * HWSZ + nn) =
                    make_float2(acc[mf][nb][0] * IWSC, acc[mf][nb][1] * IWSC);
                *(float2*)(out + ((size_t)b * Cout + mb + 8) * HWSZ + nn) =
                    make_float2(acc[mf][nb][2] * IWSC, acc[mf][nb][3] * IWSC);
            }
        }
    }
}

// ---------------------------------------------------------------------------
// depthwise 3x3 on fp16 + FUSED norm partials (deterministic, no atomics).
//   q channels (c<192): partial (sum q^2, sum cn^2, sum q*cn) using fp32 pre-
//   rounding values + cnf tile; k channels (192<=c<384): partial sum k^2.
//   One float4 per (b, c, xblock) -> g_part; coef_kernel reduces 8 partials.
// ---------------------------------------------------------------------------
__global__ __launch_bounds__(256) void dwconv3h_stats_kernel(
    const __half* __restrict__ in, const float* __restrict__ wdw,
    const __half* __restrict__ cnf,
    __half* __restrict__ out, float* __restrict__ part) {
    int c = blockIdx.y, b = blockIdx.z, xb = blockIdx.x;
    int p8 = (xb * 256 + threadIdx.x) * 8;
    int y = p8 >> 7, x = p8 & 127;
    const __half* src = in + ((size_t)b * (3 * CDIM) + c) * HWSZ;
    float w[9];
#pragma unroll
    for (int i = 0; i < 9; i++) w[i] = wdw[c * 9 + i];
    float a[8];
#pragma unroll
    for (int j = 0; j < 8; j++) a[j] = 0.f;
#pragma unroll
    for (int r = -1; r <= 1; r++) {
        int yy = y + r;
        if ((unsigned)yy >= 128u) continue;
        const __half* rp = src + (yy << 7);
        uint4 m4 = *(const uint4*)(rp + x);
        const __half* mh = (const __half*)&m4;
        float v[10];
        v[0] = (x > 0) ? __half2float(rp[x - 1]) : 0.f;
#pragma unroll
        for (int j = 0; j < 8; j++) v[j + 1] = __half2float(mh[j]);
        v[9] = (x + 8 < 128) ? __half2float(rp[x + 8]) : 0.f;
        int wb = (r + 1) * 3;
#pragma unroll
        for (int j = 0; j < 8; j++)
            a[j] = fmaf(w[wb], v[j], fmaf(w[wb + 1], v[j + 1], fmaf(w[wb + 2], v[j + 2], a[j])));
    }
    uint4 o4;
    __half* oh = (__half*)&o4;
#pragma unroll
    for (int j = 0; j < 8; j++) oh[j] = __float2half(a[j]);
    *(uint4*)(out + ((size_t)b * (3 * CDIM) + c) * HWSZ + p8) = o4;

    if (c >= 384) return;      // v channels: no stats
    float s0 = 0.f, s1 = 0.f, s2 = 0.f;
    if (c < CDIM) {            // q channel: needs cn too
        uint4 c4 = *(const uint4*)(cnf + ((size_t)b * CDIM + c) * HWSZ + p8);
        const __half* chh = (const __half*)&c4;
#pragma unroll
        for (int j = 0; j < 8; j++) {
            float cv = __half2float(chh[j]);
            s0 = fmaf(a[j], a[j], s0);
            s1 = fmaf(cv, cv, s1);
            s2 = fmaf(a[j], cv, s2);
        }
    } else {                   // k channel
#pragma unroll
        for (int j = 0; j < 8; j++) s0 = fmaf(a[j], a[j], s0);
    }
#pragma unroll
    for (int o = 16; o; o >>= 1) {
        s0 += __shfl_xor_sync(~0u, s0, o);
        s1 += __shfl_xor_sync(~0u, s1, o);
        s2 += __shfl_xor_sync(~0u, s2, o);
    }
    __shared__ float rs[3][8];
    int wid = threadIdx.x >> 5, lane = threadIdx.x & 31;
    if (lane == 0) { rs[0][wid] = s0; rs[1][wid] = s1; rs[2][wid] = s2; }
    __syncthreads();
    if (threadIdx.x == 0) {
        float t0 = 0.f, t1 = 0.f, t2 = 0.f;
#pragma unroll
        for (int i = 0; i < 8; i++) { t0 += rs[0][i]; t1 += rs[1][i]; t2 += rs[2][i]; }
        ((float4*)part)[((size_t)b * 384 + c) * 8 + xb] = make_float4(t0, t1, t2, 0.f);
    }
}

// reduce 8 x-block partials -> alpha/beta/gamma per row
__global__ __launch_bounds__(256) void coef_kernel(
    const float* __restrict__ part, float* __restrict__ coef) {
    int row = blockIdx.x * 256 + threadIdx.x;
    if (row >= BATCH * CDIM) return;
    int b = row / CDIM, c = row % CDIM;
    const float4* pq = (const float4*)part + ((size_t)b * 384 + c) * 8;
    const float4* pk = (const float4*)part + ((size_t)b * 384 + CDIM + c) * 8;
    float SQ = 0.f, SC = 0.f, SQC = 0.f, SK = 0.f;
#pragma unroll
    for (int i = 0; i < 8; i++) {
        float4 q = pq[i];
        SQ += q.x; SC += q.y; SQC += q.z;
        SK += pk[i].x;
    }
    float a  = fmaxf(sqrtf(SQ), EPSN);
    float bb = fmaxf(sqrtf(SC), EPSN);
    float s2 = SQ / (a * a) + 2.f * SQC / (a * bb) + SC / (bb * bb);
    float s  = fmaxf(sqrtf(s2), EPSN);
    float kn = fmaxf(sqrtf(SK), EPSN);
    coef[row * 3 + 0] = 1.f / (a * s);
    coef[row * 3 + 1] = 1.f / (bb * s);
    coef[row * 3 + 2] = 1.f / kn;
}

// ---------------------------------------------------------------------------
// gram via HMMA (unchanged from R10)
// ---------------------------------------------------------------------------
__global__ __launch_bounds__(256) void gram_mma_kernel(
    const __half* __restrict__ qkv, const __half* __restrict__ cnf,
    const float* __restrict__ coef, float* __restrict__ gpart) {
    __shared__ __align__(16) char QS[8192];
    __shared__ __align__(16) char KS[8192];
    __shared__ float al[48], be[48], ga[48];
    int bh = blockIdx.x, sp = blockIdx.y;
    int b = bh >> 2, h = bh & 3;
    int tid = threadIdx.x, lane = tid & 31, wid = tid >> 5;
    int wm = wid >> 1, wn = wid & 1;
    int lr = lane & 15, lc = lane >> 4;
    uint32_t qs = s2u(QS), ksm = s2u(KS);
    if (tid < 48) {
        int rw = b * CDIM + h * CHD + tid;
        al[tid] = coef[rw * 3 + 0]; be[tid] = coef[rw * 3 + 1]; ga[tid] = coef[rw * 3 + 2];
    }
    const __half* qb = qkv + ((size_t)b * (3 * CDIM) + h * CHD) * HWSZ;
    const __half* kb = qkv + ((size_t)b * (3 * CDIM) + CDIM + h * CHD) * HWSZ;
    const __half* cb = cnf + ((size_t)b * CDIM + h * CHD) * HWSZ;
    float acc[4][4] = {};
    __syncthreads();
    int send = sp * 2048 + 2048;
    for (int s0 = sp * 2048; s0 < send; s0 += 64) {
        for (int e = tid; e < 1536; e += 256) {
            int r = e >> 5, sc = (e & 31) * 2;
            size_t off = (size_t)r * HWSZ + s0 + sc;
            float2 q2 = __half22float2(*(const __half2*)(qb + off));
            float2 c2 = __half22float2(*(const __half2*)(cb + off));
            *(uint32_t*)(QS + SWZ(r * 128 + sc * 2)) =
                pack2h(__float2half(al[r] * q2.x + be[r] * c2.x),
                       __float2half(al[r] * q2.y + be[r] * c2.y));
            float2 k2 = __half22float2(*(const __half2*)(kb + off));
            *(__half*)(KS + SWZ(sc * 128 + r * 2))       = __float2half(ga[r] * k2.x);
            *(__half*)(KS + SWZ((sc + 1) * 128 + r * 2)) = __float2half(ga[r] * k2.y);
        }
        __syncthreads();
#pragma unroll
        for (int ks = 0; ks < 4; ks++) {
            uint32_t af[4];
            ldsm4(af, qs + SWZ((wm * 16 + lr) * 128 + ks * 32 + lc * 16));
#pragma unroll
            for (int g = 0; g < 2; g++) {
                uint32_t bf[4];
                ldsm4t(bf, ksm + SWZ((ks * 16 + lr) * 128 + (wn * 32 + g * 16) * 2 + lc * 16));
                mma16816h(acc[2 * g],     af, bf);
                mma16816h(acc[2 * g + 1], af, bf + 2);
            }
        }
        __syncthreads();
    }
    if (wm < 3) {
        int c = wm * 16 + (lane >> 2);
#pragma unroll
        for (int nb = 0; nb < 4; nb++) {
            int d0 = wn * 32 + nb * 8;
            if (d0 < 48) {
                int dd = d0 + (lane & 3) * 2;
                float* g0 = gpart + ((size_t)(bh * SPLIT + sp) * CHD + c) * CHD + dd;
                g0[0] = acc[nb][0]; g0[1] = acc[nb][1];
                float* g1 = gpart + ((size_t)(bh * SPLIT + sp) * CHD + c + 8) * CHD + dd;
                g1[0] = acc[nb][2]; g1[1] = acc[nb][3];
            }
        }
    }
}

__global__ __launch_bounds__(256) void softmax_kernel(
    const float* __restrict__ gpart, const float* __restrict__ temp,
    float* __restrict__ attn) {
    __shared__ float S[48][49];
    int bh = blockIdx.x;
    float T = temp[bh & 3];
    int tid = threadIdx.x;
    for (int e = tid; e < CHD * CHD; e += 256) {
        int c = e / CHD, d = e - c * CHD;
        float g = 0.f;
#pragma unroll
        for (int sp = 0; sp < SPLIT; sp++)
            g += gpart[((bh * SPLIT + sp) * CHD + c) * CHD + d];
        S[c][d] = g * T;
    }
    __syncthreads();
    int wid = tid >> 5, lane = tid & 31;
    for (int r = wid; r < 48; r += 8) {
        float v1 = S[r][lane];
        float v2 = (lane < 16) ? S[r][32 + lane] : -1e30f;
        float m = fmaxf(v1, v2);
#pragma unroll
        for (int o = 16; o; o >>= 1) m = fmaxf(m, __shfl_xor_sync(~0u, m, o));
        float e1 = expf(v1 - m);
        float e2 = (lane < 16) ? expf(v2 - m) : 0.f;
        float s = e1 + e2;
#pragma unroll
        for (int o = 16; o; o >>= 1) s += __shfl_xor_sync(~0u, s, o);
        float inv = 1.f / s;
        attn[bh * (CHD * CHD) + r * CHD + lane] = e1 * inv;
        if (lane < 16) attn[bh * (CHD * CHD) + r * CHD + 32 + lane] = e2 * inv;
    }
}

// ---------------------------------------------------------------------------
// apply via HMMA (unchanged from R10)
// ---------------------------------------------------------------------------
__global__ __launch_bounds__(256) void apply_mma_kernel(
    const __half* __restrict__ qkv, const float* __restrict__ attn,
    __half* __restrict__ o16) {
    __shared__ __align__(16) char ASH[6144];
    __shared__ __align__(16) char ASL[6144];
    __shared__ __align__(16) char BS[12288];
    int n0 = blockIdx.x * 128, h = blockIdx.y, b = blockIdx.z;
    int tid = threadIdx.x, lane = tid & 31, wid = tid >> 5;
    int lr = lane & 15, lc = lane >> 4;
    uint32_t ash = s2u(ASH), asl = s2u(ASL), bsm = s2u(BS);

    const float* ab = attn + (size_t)(b * NHEAD + h) * (CHD * CHD);
    for (int e = tid; e < CHD * CHD; e += 256) {
        int r = e / CHD, d = e - r * CHD;
        float a = ab[e] * WSC;
        __half hh = __float2half(a);
        uint32_t off = SWZ(r * 128 + d * 2);
        *(__half*)(ASH + off) = hh;
        *(__half*)(ASL + off) = __float2half(a - __half2float(hh));
    }
    const __half* vb = qkv + ((size_t)b * (3 * CDIM) + 2 * CDIM + h * CHD) * HWSZ;
#pragma unroll
    for (int i = 0; i < 3; i++) {
        int e = tid + (i << 8);
        int nc = e & 15, d = e >> 4;
        cpa16(bsm + (nc >> 3) * 6144 + SWZ(d * 128 + (nc & 7) * 16),
              vb + (size_t)d * HWSZ + n0 + nc * 8, 16);
    }
    CPA_COMMIT(); CPA_WAIT(0);
    __syncthreads();

    int wn = wid;
    float acc[3][2][4];
#pragma unroll
    for (int i = 0; i < 3; i++)
#pragma unroll
        for (int j = 0; j < 2; j++)
#pragma unroll
            for (int q = 0; q < 4; q++) acc[i][j][q] = 0.f;

#pragma unroll
    for (int ks = 0; ks < 3; ks++) {
        int col = wn * 16;
        uint32_t bf[4];
        ldsm4t(bf, bsm + (col >> 6) * 6144 + SWZ((ks * 16 + lr) * 128 + (col & 63) * 2 + lc * 16));
#pragma unroll
        for (int mf = 0; mf < 3; mf++) {
            uint32_t ah4[4], al4[4];
            uint32_t ao = SWZ((mf * 16 + lr) * 128 + ks * 32 + lc * 16);
            ldsm4(ah4, ash + ao);
            ldsm4(al4, asl + ao);
            mma16816h(acc[mf][0], ah4, bf);
            mma16816h(acc[mf][0], al4, bf);
            mma16816h(acc[mf][1], ah4, bf + 2);
            mma16816h(acc[mf][1], al4, bf + 2);
        }
    }

#pragma unroll
    for (int mf = 0; mf < 3; mf++) {
        int c = mf * 16 + (lane >> 2);
        size_t rb = ((size_t)b * CDIM + h * CHD + c) * HWSZ;
#pragma unroll
        for (int nb = 0; nb < 2; nb++) {
            int s = n0 + wn * 16 + nb * 8 + (lane & 3) * 2;
            *(uint32_t*)(o16 + rb + s) =
                pack2h(__float2half(acc[mf][nb][0] * IWSC),
                       __float2half(acc[mf][nb][1] * IWSC));
            *(uint32_t*)(o16 + rb + 8 * HWSZ + s) =
                pack2h(__float2half(acc[mf][nb][2] * IWSC),
                       __float2half(acc[mf][nb][3] * IWSC));
        }
    }
}

// ---------------------------------------------------------------------------
// launch
// ---------------------------------------------------------------------------
constexpr int SMEM_1T = 3 * 28672 + 128;   // 3 stages x 28KB, 2 CTAs/SM

extern "C" void kernel_launch(void* const* d_in, const int* in_sizes, int n_in,
                              void* d_out, int out_size) {
    const float* x     = (const float*)d_in[0];
    const float* cn    = (const float*)d_in[1];
    const float* w1    = (const float*)d_in[2];
    const float* w3    = (const float*)d_in[3];
    const float* qkvw  = (const float*)d_in[4];
    const float* dww   = (const float*)d_in[5];
    const float* projw = (const float*)d_in[6];
    const float* temp  = (const float*)d_in[7];

    __half *wc, *wq, *wp, *ch, *chL, *chR, *x16, *cnf, *q1h, *q2h;
    float *part, *coef, *gpart, *attn;
    cudaGetSymbolAddress((void**)&wc,  g_wc);
    cudaGetSymbolAddress((void**)&wq,  g_wq);
    cudaGetSymbolAddress((void**)&wp,  g_wp);
    cudaGetSymbolAddress((void**)&ch,  g_ch);
    cudaGetSymbolAddress((void**)&chL, g_chL);
    cudaGetSymbolAddress((void**)&chR, g_chR);
    cudaGetSymbolAddress((void**)&x16, g_x16);
    cudaGetSymbolAddress((void**)&cnf, g_cnf);
    cudaGetSymbolAddress((void**)&q1h, g_q1h);
    cudaGetSymbolAddress((void**)&q2h, g_q2h);
    cudaGetSymbolAddress((void**)&part, g_part);
    cudaGetSymbolAddress((void**)&coef, g_coef);
    cudaGetSymbolAddress((void**)&gpart, g_gpart);
    cudaGetSymbolAddress((void**)&attn, g_attn);

    cudaFuncSetAttribute(mm_kernel<1728, 9, true>,
                         cudaFuncAttributeMaxDynamicSharedMemorySize, SMEM_1T);
    cudaFuncSetAttribute(mm_kernel<192, 1, true>,
                         cudaFuncAttributeMaxDynamicSharedMemorySize, SMEM_1T);
    cudaFuncSetAttribute(mm_kernel<192, 1, false>,
                         cudaFuncAttributeMaxDynamicSharedMemorySize, SMEM_1T);

    const int NACT4 = BATCH * CDIM * HWSZ / 4;

    // weight prep (all 1-term fp16, x64)
    foldw_kernel<<<256 * 1728 / 256, 256>>>(w3, w1, wc);
    whalf_kernel<<<640 * 192 / 256, 256>>>(qkvw, wq, 3 * CDIM);
    whalf_kernel<<<256 * 192 / 256, 256>>>(projw, wp, CDIM);

    // cn branch: fp16 + shifted copies, folded 3x3 conv -> fp16 cnf
    asplit_shift_h_kernel<<<(NACT4 + 255) / 256, 256>>>(cn, ch, chL, chR, NACT4);
    mm_kernel<1728, 9, true><<<dim3(128, 2, BATCH), 256, SMEM_1T>>>(
        ch, chL, chR, wc, cnf, CDIM);

    // qkv 1x1: single 1-term launch (q,k,v)
    ahalf_kernel<<<(NACT4 + 255) / 256, 256>>>(x, x16, NACT4);
    mm_kernel<192, 1, true><<<dim3(128, 6, BATCH), 256, SMEM_1T>>>(
        x16, x16, x16, wq, q1h, 3 * CDIM);

    // depthwise 3x3 + fused norm partials
    dwconv3h_stats_kernel<<<dim3(HWSZ / 2048, 3 * CDIM, BATCH), 256>>>(
        q1h, dww, cnf, q2h, part);
    coef_kernel<<<(BATCH * CDIM + 255) / 256, 256>>>(part, coef);

    // attention chain
    gram_mma_kernel<<<dim3(BATCH * NHEAD, SPLIT), 256>>>(q2h, cnf, coef, gpart);
    softmax_kernel<<<BATCH * NHEAD, 256>>>(gpart, temp, attn);
    apply_mma_kernel<<<dim3(128, NHEAD, BATCH), 256>>>(q2h, attn, x16);  // av -> x16

    // projection 1x1 -> fp32 output (1-term)
    mm_kernel<192, 1, false><<<dim3(128, 2, BATCH), 256, SMEM_1T>>>(
        x16, x16, x16, wp, (float*)d_out, CDIM);
}